// round 4
// baseline (speedup 1.0000x reference)
#include <cuda_runtime.h>
#include <math.h>

#define NN 50000
#define NE 500000
#define NG 2000

typedef unsigned long long u64t;

// ---------------- scratch (device globals) ----------------
__device__ float f_x1  [NN * 128];
__device__ float f_p   [NN * 128];      // p / xp
__device__ float f_h   [NN * 128];
__device__ float f_xcur[NN * 128];
__device__ float f_gi  [NN * 3 * 128];  // also reused as tsum (first NN*128)
__device__ float f_as  [NN];
__device__ float f_ad  [NN];
__device__ float g_agg [NG * 128];
__device__ float g_out [NG * 128];
__device__ float g_hh  [NG * 128];
__device__ float g_tmp [NG * 128];
__device__ float g_gi  [NG * 4 * 128];
__device__ float g_gh  [NG * 4 * 128];
// CSR
__device__ int c_cnt[NN];
__device__ int c_off[NN + 1];
__device__ int c_pos[NN];
__device__ int c_eid[NE];

__device__ __forceinline__ float sigm(float x) { return 1.0f / (1.0f + expf(-x)); }

__device__ __forceinline__ void ffma2(u64t& d, u64t a, u64t b) {
    asm("fma.rn.f32x2 %0, %1, %2, %0;" : "+l"(d) : "l"(a), "l"(b));
}
__device__ __forceinline__ float hsum2(u64t v) {
    float lo, hi;
    asm("mov.b64 {%0, %1}, %2;" : "=f"(lo), "=f"(hi) : "l"(v));
    return lo + hi;
}

// ---------------- CSR build ----------------
__global__ void zero_i_kernel(int* p, int n) {
    int t = blockIdx.x * blockDim.x + threadIdx.x;
    if (t < n) p[t] = 0;
}
__global__ void hist_kernel(const int* __restrict__ dst, int* __restrict__ cnt) {
    int e = blockIdx.x * blockDim.x + threadIdx.x;
    if (e < NE) atomicAdd(&cnt[dst[e]], 1);
}
__global__ void __launch_bounds__(1024) scan_kernel(const int* __restrict__ cnt,
                                                    int* __restrict__ off, int* __restrict__ pos) {
    __shared__ int sm[1024];
    __shared__ int s_carry;
    const int tid = threadIdx.x;
    if (tid == 0) s_carry = 0;
    __syncthreads();
    const int CH = 1024 * 8;
    for (int base = 0; base < NN; base += CH) {
        int v[8]; int s = 0;
        int i0 = base + tid * 8;
#pragma unroll
        for (int j = 0; j < 8; ++j) {
            int i = i0 + j;
            v[j] = (i < NN) ? cnt[i] : 0;
            s += v[j];
        }
        sm[tid] = s;
        __syncthreads();
        for (int d = 1; d < 1024; d <<= 1) {
            int t = (tid >= d) ? sm[tid - d] : 0;
            __syncthreads();
            sm[tid] += t;
            __syncthreads();
        }
        int pref = sm[tid] - s + s_carry;
        int total = sm[1023];
#pragma unroll
        for (int j = 0; j < 8; ++j) {
            int i = i0 + j;
            if (i < NN) { off[i] = pref; pos[i] = pref; }
            pref += v[j];
        }
        __syncthreads();
        if (tid == 0) s_carry += total;
        __syncthreads();
    }
    if (tid == 0) off[NN] = NE;
}
__global__ void fill_kernel(const int* __restrict__ dst, int* __restrict__ pos,
                            int* __restrict__ eid) {
    int e = blockIdx.x * blockDim.x + threadIdx.x;
    if (e < NE) {
        int idx = atomicAdd(&pos[dst[e]], 1);
        eid[idx] = e;
    }
}

// ---------------- dense GEMM (persistent; FFMA2 packed-f32x2 inner loop) ----
// out[n, jbase + tid + c*128] = act(sum_k A[n,k]*W[j*wstride+k] + b)
// EPI==1 (JPT==3): fused GRU combine; gi precomputed, hprev = A row.
template <int K, int JPT, int ACT, int EPI>
__global__ void __launch_bounds__(128) dense_kernel(
    const float* __restrict__ A, const float* __restrict__ W,
    const float* __restrict__ bias, float* __restrict__ out,
    const float* __restrict__ gi, int n, int Jtotal, int wstride)
{
    constexpr int KP = K + 2;        // odd u64 row stride -> conflict-free LDS.64
    constexpr int NT = 16;
    constexpr int NPRE = NT * K / 512;
    extern __shared__ float sm[];
    float* Ws = sm;                     // JPT*128*KP
    float* ins = sm + JPT * 128 * KP;   // NT*K (row-major)
    const int tid = threadIdx.x;
    const int jbase = blockIdx.y * JPT * 128;

    for (int idx = tid; idx < JPT * 128 * K; idx += 128) {
        int r = idx / K, k = idx - r * K;
        Ws[r * KP + k] = W[(size_t)(jbase + r) * wstride + k];
    }
    float b[JPT];
#pragma unroll
    for (int c = 0; c < JPT; ++c)
        b[c] = bias ? bias[jbase + tid + c * 128] : 0.0f;

    const int stride = gridDim.x * NT;
    int t0 = blockIdx.x * NT;
    float4 pre[NPRE];
    if (t0 < n) {
        int lim = min(NT, n - t0) * (K / 4);
#pragma unroll
        for (int i = 0; i < NPRE; ++i) {
            int idx = tid + i * 128;
            pre[i] = (idx < lim) ? ((const float4*)(A + (size_t)t0 * K))[idx]
                                 : make_float4(0.f, 0.f, 0.f, 0.f);
        }
    }
    __syncthreads();

    const u64t* wrow8[JPT];
#pragma unroll
    for (int c = 0; c < JPT; ++c)
        wrow8[c] = (const u64t*)(Ws + (size_t)(c * 128 + tid) * KP);

    for (; t0 < n; t0 += stride) {
        int cnt = min(NT, n - t0);
#pragma unroll
        for (int i = 0; i < NPRE; ++i)
            ((float4*)ins)[tid + i * 128] = pre[i];
        __syncthreads();
        int tn = t0 + stride;
        if (tn < n) {
            int lim = min(NT, n - tn) * (K / 4);
#pragma unroll
            for (int i = 0; i < NPRE; ++i) {
                int idx = tid + i * 128;
                pre[i] = (idx < lim) ? ((const float4*)(A + (size_t)tn * K))[idx]
                                     : make_float4(0.f, 0.f, 0.f, 0.f);
            }
        }
        u64t acc2[JPT][NT];
#pragma unroll
        for (int c = 0; c < JPT; ++c)
#pragma unroll
            for (int q = 0; q < NT; ++q) acc2[c][q] = 0ULL;

        const u64t* ins8 = (const u64t*)ins;
#pragma unroll 4
        for (int k2 = 0; k2 < K / 2; ++k2) {
            u64t w2[JPT];
#pragma unroll
            for (int c = 0; c < JPT; ++c) w2[c] = wrow8[c][k2];
#pragma unroll
            for (int q = 0; q < NT; ++q) {
                u64t v2 = ins8[q * (K / 2) + k2];
#pragma unroll
                for (int c = 0; c < JPT; ++c)
                    ffma2(acc2[c][q], w2[c], v2);
            }
        }
        if (EPI == 0) {
            for (int q = 0; q < cnt; ++q) {
#pragma unroll
                for (int c = 0; c < JPT; ++c) {
                    float r = hsum2(acc2[c][q]) + b[c];
                    if (ACT == 1) r = (r >= 0.f) ? r : 0.01f * r;
                    else if (ACT == 2) r = fmaxf(r, 0.f);
                    else if (ACT == 3) r = (r > 0.f) ? r : expm1f(r);
                    out[(size_t)(t0 + q) * Jtotal + jbase + tid + c * 128] = r;
                }
            }
        } else {
            for (int q = 0; q < cnt; ++q) {
                size_t node = t0 + q;
                float hr = hsum2(acc2[0][q]) + b[0];
                float hz = hsum2(acc2[1][q]) + b[1];
                float hn = hsum2(acc2[2][q]) + b[2];
                size_t gbase = node * 384 + tid;
                float r = sigm(gi[gbase] + hr);
                float z = sigm(gi[gbase + 128] + hz);
                float nng = tanhf(gi[gbase + 256] + r * hn);
                float hv = ins[q * K + tid];
                out[node * 128 + tid] = fmaxf((1.f - z) * nng + z * hv, 0.f);
            }
        }
        __syncthreads();
    }
}

// ---------------- nd gather (CSR): tsum[n] = sum_e leaky(p[src]+ea@W1b^T) ---
__global__ void __launch_bounds__(256) nd_gather_kernel(
    const float* __restrict__ p, const float* __restrict__ ea,
    const int* __restrict__ src, const int* __restrict__ off,
    const int* __restrict__ eid, const float* __restrict__ w1,
    float* __restrict__ tsum)
{
    __shared__ float W1b[16 * 128];   // [k][j]
    const int tid = threadIdx.x;
    for (int idx = tid; idx < 16 * 128; idx += 256) {
        int k = idx >> 7, j = idx & 127;
        W1b[idx] = w1[j * 144 + 128 + k];
    }
    __syncthreads();
    int n = blockIdx.x * 8 + (tid >> 5);
    if (n >= NN) return;
    int lane = tid & 31;
    int beg = off[n], end = off[n + 1];
    float4 acc = make_float4(0.f, 0.f, 0.f, 0.f);
    const float4* W1b4 = (const float4*)W1b;
    const float4* p4 = (const float4*)p;
    for (int e = beg; e < end; ++e) {
        int ed = eid[e];
        int s = src[ed];
        float eav = (lane < 16) ? __ldg(&ea[(size_t)ed * 16 + lane]) : 0.f;
        float4 t = p4[(size_t)s * 32 + lane];
#pragma unroll
        for (int k = 0; k < 16; ++k) {
            float ek = __shfl_sync(0xFFFFFFFFu, eav, k);
            float4 w = W1b4[k * 32 + lane];
            t.x += ek * w.x; t.y += ek * w.y; t.z += ek * w.z; t.w += ek * w.w;
        }
        t.x = (t.x >= 0.f) ? t.x : 0.01f * t.x;
        t.y = (t.y >= 0.f) ? t.y : 0.01f * t.y;
        t.z = (t.z >= 0.f) ? t.z : 0.01f * t.z;
        t.w = (t.w >= 0.f) ? t.w : 0.01f * t.w;
        acc.x += t.x; acc.y += t.y; acc.z += t.z; acc.w += t.w;
    }
    ((float4*)tsum)[(size_t)n * 32 + lane] = acc;
}

// ---------------- GAT attention dots ----------------
__global__ void attn_dots_kernel(const float* __restrict__ xp, const float* __restrict__ asrc,
                                 const float* __restrict__ adst, float* __restrict__ as_,
                                 float* __restrict__ ad_) {
    int n = (blockIdx.x * blockDim.x + threadIdx.x) >> 5;
    int lane = threadIdx.x & 31;
    if (n >= NN) return;
    float4 v = ((const float4*)xp)[(size_t)n * 32 + lane];
    float4 w1 = ((const float4*)asrc)[lane];
    float4 w2 = ((const float4*)adst)[lane];
    float sa = v.x * w1.x + v.y * w1.y + v.z * w1.z + v.w * w1.w;
    float sd = v.x * w2.x + v.y * w2.y + v.z * w2.z + v.w * w2.w;
#pragma unroll
    for (int o = 16; o; o >>= 1) {
        sa += __shfl_xor_sync(0xFFFFFFFFu, sa, o);
        sd += __shfl_xor_sync(0xFFFFFFFFu, sd, o);
    }
    if (lane == 0) { as_[n] = sa; ad_[n] = sd; }
}

// ---------------- GAT gather (CSR, online softmax, fused bias+elu) ----------
__global__ void __launch_bounds__(256) gat_gather_kernel(
    const int* __restrict__ src, const int* __restrict__ off, const int* __restrict__ eid,
    const float* __restrict__ as_, const float* __restrict__ ad_,
    const float* __restrict__ xp, const float* __restrict__ bias,
    float* __restrict__ hout)
{
    int n = blockIdx.x * 8 + (threadIdx.x >> 5);
    if (n >= NN) return;
    int lane = threadIdx.x & 31;
    int beg = off[n], end = off[n + 1];
    float adn = ad_[n];
    float m = -INFINITY, den = 0.f;
    float4 acc = make_float4(0.f, 0.f, 0.f, 0.f);
    const float4* xp4 = (const float4*)xp;
    for (int e = beg; e < end; ++e) {
        int ed = eid[e];
        int s = src[ed];
        float a = __ldg(&as_[s]) + adn;
        a = (a >= 0.f) ? a : 0.01f * a;
        if (a > m) {
            float f = __expf(m - a);   // exp(-inf)=0 on first edge
            den *= f;
            acc.x *= f; acc.y *= f; acc.z *= f; acc.w *= f;
            m = a;
        }
        float w = __expf(a - m);
        den += w;
        float4 v = xp4[(size_t)s * 32 + lane];
        acc.x += w * v.x; acc.y += w * v.y; acc.z += w * v.z; acc.w += w * v.w;
    }
    float inv = (den > 0.f) ? 1.f / den : 0.f;
    float4 b = ((const float4*)bias)[lane];
    float4 r;
    r.x = acc.x * inv + b.x; r.y = acc.y * inv + b.y;
    r.z = acc.z * inv + b.z; r.w = acc.w * inv + b.w;
    r.x = (r.x > 0.f) ? r.x : expm1f(r.x);
    r.y = (r.y > 0.f) ? r.y : expm1f(r.y);
    r.z = (r.z > 0.f) ? r.z : expm1f(r.z);
    r.w = (r.w > 0.f) ? r.w : expm1f(r.w);
    ((float4*)hout)[(size_t)n * 32 + lane] = r;
}

// ---------------- readout ----------------
__global__ void __launch_bounds__(128) graph_agg_kernel(const float* __restrict__ xcur,
                                                        const int* __restrict__ batch,
                                                        float* __restrict__ agg,
                                                        float* __restrict__ outv) {
    int g = blockIdx.x;
    int lo, hi;
    {
        int l = 0, r = NN;
        while (l < r) { int m = (l + r) >> 1; if (batch[m] < g) l = m + 1; else r = m; }
        lo = l;
    }
    {
        int l = lo, r = NN;
        while (l < r) { int m = (l + r) >> 1; if (batch[m] < g + 1) l = m + 1; else r = m; }
        hi = l;
    }
    float s = 0.f;
    for (int n = lo; n < hi; ++n) s += xcur[(size_t)n * 128 + threadIdx.x];
    agg[g * 128 + threadIdx.x] = s;
    outv[g * 128 + threadIdx.x] = fmaxf(s, 0.f);
}

__global__ void add_kernel(const float* __restrict__ a, const float* __restrict__ b,
                           float* __restrict__ c, int n) {
    int t = blockIdx.x * blockDim.x + threadIdx.x;
    if (t < n) c[t] = a[t] + b[t];
}

__global__ void lstm_combine_kernel(const float* __restrict__ gi, const float* __restrict__ gh,
                                    const float* __restrict__ hc, float* __restrict__ out) {
    int t = blockIdx.x * blockDim.x + threadIdx.x;
    if (t >= NG * 128) return;
    int g = t >> 7, j = t & 127;
    size_t base = (size_t)g * 512;
    float gI = gi[base + j]       + gh[base + j];
    float gF = gi[base + 128 + j] + gh[base + 128 + j];
    float gG = gi[base + 256 + j] + gh[base + 256 + j];
    float gO = gi[base + 384 + j] + gh[base + 384 + j];
    float c = hc[t];
    float c2 = sigm(gF) * c + sigm(gI) * tanhf(gG);
    out[t] = sigm(gO) * tanhf(c2);
}

__global__ void final_kernel(const float* __restrict__ outv, const float* __restrict__ w,
                             const float* __restrict__ b, float* __restrict__ res) {
    int g = (blockIdx.x * blockDim.x + threadIdx.x) >> 5;
    int lane = threadIdx.x & 31;
    if (g >= NG) return;
    float4 v = ((const float4*)outv)[(size_t)g * 32 + lane];
    float4 ww = ((const float4*)w)[lane];
    float s = v.x * ww.x + v.y * ww.y + v.z * ww.z + v.w * ww.w;
#pragma unroll
    for (int o = 16; o; o >>= 1) s += __shfl_xor_sync(0xFFFFFFFFu, s, o);
    if (lane == 0) res[g] = s + b[0];
}

// ---------------- host ----------------
#define SM_J1K64  ((128 * 66 + 16 * 64) * 4)
#define SM_J1K128 ((128 * 130 + 16 * 128) * 4)
#define SM_J3K128 ((384 * 130 + 16 * 128) * 4)

extern "C" void kernel_launch(void* const* d_in, const int* in_sizes, int n_in,
                              void* d_out, int out_size) {
    const float* x        = (const float*)d_in[0];
    const int*   ei       = (const int*)  d_in[1];
    const float* ea       = (const float*)d_in[2];
    const int*   batch    = (const int*)  d_in[3];
    const float* lin1_w   = (const float*)d_in[4];
    const float* lin1_b   = (const float*)d_in[5];
    const float* nd_lin1w = (const float*)d_in[6];
    const float* nd_lin2w = (const float*)d_in[7];
    const float* nd_bias  = (const float*)d_in[8];
    const float* gru0_wih = (const float*)d_in[9];
    const float* gru0_whh = (const float*)d_in[10];
    const float* gru0_bih = (const float*)d_in[11];
    const float* gru0_bhh = (const float*)d_in[12];
    const float* gat_w    = (const float*)d_in[13];
    const float* gat_asrc = (const float*)d_in[14];
    const float* gat_adst = (const float*)d_in[15];
    const float* gat_b    = (const float*)d_in[16];
    const float* gru_wih  = (const float*)d_in[17];
    const float* gru_whh  = (const float*)d_in[18];
    const float* gru_bih  = (const float*)d_in[19];
    const float* gru_bhh  = (const float*)d_in[20];
    const float* gin_w    = (const float*)d_in[21];
    const float* gin_b    = (const float*)d_in[22];
    const float* lstm_wih = (const float*)d_in[23];
    const float* lstm_whh = (const float*)d_in[24];
    const float* lstm_bih = (const float*)d_in[25];
    const float* lstm_bhh = (const float*)d_in[26];
    const float* lin2_w   = (const float*)d_in[27];
    const float* lin2_b   = (const float*)d_in[28];
    float* out = (float*)d_out;

    const int* src = ei;
    const int* dst = ei + NE;

    float *px1, *pp, *ph, *pxc, *pgi, *pas, *pad;
    float *pagg, *pgout, *pghh, *pgtmp, *pggi, *pggh;
    int *pcnt, *poff, *ppos, *peid;
    cudaGetSymbolAddress((void**)&px1, f_x1);
    cudaGetSymbolAddress((void**)&pp, f_p);
    cudaGetSymbolAddress((void**)&ph, f_h);
    cudaGetSymbolAddress((void**)&pxc, f_xcur);
    cudaGetSymbolAddress((void**)&pgi, f_gi);
    cudaGetSymbolAddress((void**)&pas, f_as);
    cudaGetSymbolAddress((void**)&pad, f_ad);
    cudaGetSymbolAddress((void**)&pagg, g_agg);
    cudaGetSymbolAddress((void**)&pgout, g_out);
    cudaGetSymbolAddress((void**)&pghh, g_hh);
    cudaGetSymbolAddress((void**)&pgtmp, g_tmp);
    cudaGetSymbolAddress((void**)&pggi, g_gi);
    cudaGetSymbolAddress((void**)&pggh, g_gh);
    cudaGetSymbolAddress((void**)&pcnt, c_cnt);
    cudaGetSymbolAddress((void**)&poff, c_off);
    cudaGetSymbolAddress((void**)&ppos, c_pos);
    cudaGetSymbolAddress((void**)&peid, c_eid);

    cudaFuncSetAttribute((const void*)dense_kernel<64, 1, 1, 0>, cudaFuncAttributeMaxDynamicSharedMemorySize, SM_J1K64);
    cudaFuncSetAttribute((const void*)dense_kernel<128, 1, 0, 0>, cudaFuncAttributeMaxDynamicSharedMemorySize, SM_J1K128);
    cudaFuncSetAttribute((const void*)dense_kernel<128, 1, 3, 0>, cudaFuncAttributeMaxDynamicSharedMemorySize, SM_J1K128);
    cudaFuncSetAttribute((const void*)dense_kernel<128, 3, 0, 0>, cudaFuncAttributeMaxDynamicSharedMemorySize, SM_J3K128);
    cudaFuncSetAttribute((const void*)dense_kernel<128, 3, 0, 1>, cudaFuncAttributeMaxDynamicSharedMemorySize, SM_J3K128);

    // persistent grids: weights loaded once per block, swept over many tiles
    const int GP1 = 444;   // JPT=1 K=128: 3 CTAs/SM
    const int GP1b = 592;  // JPT=1 K=64
    const int GP3 = 148;   // JPT=3: 1 CTA/SM
    const int tilesG = (NG + 15) / 16;   // 125
    const int ZB = 256;

    // ---- CSR build (by dst) ----
    zero_i_kernel<<<(NN + ZB - 1) / ZB, ZB>>>(pcnt, NN);
    hist_kernel<<<(NE + ZB - 1) / ZB, ZB>>>(dst, pcnt);
    scan_kernel<<<1, 1024>>>(pcnt, poff, ppos);
    fill_kernel<<<(NE + ZB - 1) / ZB, ZB>>>(dst, ppos, peid);

    // ---- x1 = leaky(x @ lin1_w.T + b) ----
    dense_kernel<64, 1, 1, 0><<<dim3(GP1b, 1), 128, SM_J1K64>>>(x, lin1_w, lin1_b, px1, nullptr, NN, 128, 64);
    // ---- p = x1 @ W1a.T ----
    dense_kernel<128, 1, 0, 0><<<dim3(GP1, 1), 128, SM_J1K128>>>(px1, nd_lin1w, nullptr, pp, nullptr, NN, 128, 144);
    // ---- tsum = segment_sum(leaky(p[src] + ea @ W1b.T)) ----
    nd_gather_kernel<<<(NN + 7) / 8, 256>>>(pp, ea, src, poff, peid, nd_lin1w, pgi);
    // ---- h = elu(tsum @ W2.T + nd_bias) ----
    dense_kernel<128, 1, 3, 0><<<dim3(GP1, 1), 128, SM_J1K128>>>(pgi, nd_lin2w, nd_bias, ph, nullptr, NN, 128, 128);
    // ---- GRU0: xcur = relu(gru(h, x1)) ----
    dense_kernel<128, 3, 0, 0><<<dim3(GP3, 1), 128, SM_J3K128>>>(ph, gru0_wih, gru0_bih, pgi, nullptr, NN, 384, 128);
    dense_kernel<128, 3, 0, 1><<<dim3(GP3, 1), 128, SM_J3K128>>>(px1, gru0_whh, gru0_bhh, pxc, pgi, NN, 384, 128);

    // ---- GAT layers ----
    for (int l = 0; l < 2; ++l) {
        dense_kernel<128, 1, 0, 0><<<dim3(GP1, 1), 128, SM_J1K128>>>(pxc, gat_w + (size_t)l * 128 * 128, nullptr, pp, nullptr, NN, 128, 128);
        attn_dots_kernel<<<(NN * 32 + ZB - 1) / ZB, ZB>>>(pp, gat_asrc + l * 128, gat_adst + l * 128, pas, pad);
        gat_gather_kernel<<<(NN + 7) / 8, 256>>>(src, poff, peid, pas, pad, pp, gat_b + l * 128, ph);
        dense_kernel<128, 3, 0, 0><<<dim3(GP3, 1), 128, SM_J3K128>>>(ph, gru_wih + (size_t)l * 384 * 128, gru_bih + l * 384, pgi, nullptr, NN, 384, 128);
        dense_kernel<128, 3, 0, 1><<<dim3(GP3, 1), 128, SM_J3K128>>>(pxc, gru_whh + (size_t)l * 384 * 128, gru_bhh + l * 384, pxc, pgi, NN, 384, 128);
    }

    // ---- readout ----
    graph_agg_kernel<<<NG, 128>>>(pxc, batch, pagg, pgout);
    for (int t = 0; t < 2; ++t) {
        add_kernel<<<(NG * 128 + ZB - 1) / ZB, ZB>>>(pgout, pagg, pgtmp, NG * 128);
        dense_kernel<128, 1, 3, 0><<<dim3(tilesG, 1), 128, SM_J1K128>>>(pgtmp, gin_w, gin_b, pghh, nullptr, NG, 128, 128);
        dense_kernel<128, 1, 0, 0><<<dim3(tilesG, 4), 128, SM_J1K128>>>(pgout, lstm_wih, lstm_bih, pggi, nullptr, NG, 512, 128);
        dense_kernel<128, 1, 0, 0><<<dim3(tilesG, 4), 128, SM_J1K128>>>(pghh, lstm_whh, lstm_bhh, pggh, nullptr, NG, 512, 128);
        lstm_combine_kernel<<<(NG * 128 + ZB - 1) / ZB, ZB>>>(pggi, pggh, pghh, pgout);
    }
    final_kernel<<<(NG * 32 + 127) / 128, 128>>>(pgout, lin2_w, lin2_b, out);
}

// round 5
// speedup vs baseline: 1.8726x; 1.8726x over previous
#include <cuda_runtime.h>
#include <math.h>

#define NN 50000
#define NE 500000
#define NG 2000

typedef unsigned long long u64t;

// ---------------- scratch (device globals) ----------------
__device__ float f_x1  [NN * 128];
__device__ float f_p   [NN * 128];
__device__ float f_h   [NN * 128];
__device__ float f_xcur[NN * 128];
__device__ float f_gi  [NN * 3 * 128];  // also reused as tsum (first NN*128)
__device__ float f_as  [NN];
__device__ float f_ad  [NN];
__device__ float g_agg [NG * 128];
__device__ float g_out [NG * 128];
__device__ float g_hh  [NG * 128];
__device__ float g_tmp [NG * 128];
__device__ float g_gi  [NG * 4 * 128];
__device__ float g_gh  [NG * 4 * 128];
// CSR
__device__ int c_cnt[NN];
__device__ int c_off[NN + 1];
__device__ int c_pos[NN];
__device__ int c_eid[NE];

__device__ __forceinline__ float sigm(float x) { return 1.0f / (1.0f + expf(-x)); }

__device__ __forceinline__ void ffma2(u64t& d, u64t a, u64t b) {
    asm("fma.rn.f32x2 %0, %1, %2, %0;" : "+l"(d) : "l"(a), "l"(b));
}
__device__ __forceinline__ u64t pack2(float lo, float hi) {
    u64t r;
    asm("mov.b64 %0, {%1, %2};" : "=l"(r) : "f"(lo), "f"(hi));
    return r;
}
__device__ __forceinline__ float hsum2(u64t v) {
    float lo, hi;
    asm("mov.b64 {%0, %1}, %2;" : "=f"(lo), "=f"(hi) : "l"(v));
    return lo + hi;
}

// ---------------- CSR build ----------------
__global__ void zero_i_kernel(int* p, int n) {
    int t = blockIdx.x * blockDim.x + threadIdx.x;
    if (t < n) p[t] = 0;
}
__global__ void hist_kernel(const int* __restrict__ dst, int* __restrict__ cnt) {
    int e = blockIdx.x * blockDim.x + threadIdx.x;
    if (e < NE) atomicAdd(&cnt[dst[e]], 1);
}
__global__ void __launch_bounds__(1024) scan_kernel(const int* __restrict__ cnt,
                                                    int* __restrict__ off, int* __restrict__ pos) {
    __shared__ int sm[1024];
    __shared__ int s_carry;
    const int tid = threadIdx.x;
    if (tid == 0) s_carry = 0;
    __syncthreads();
    const int CH = 1024 * 8;
    for (int base = 0; base < NN; base += CH) {
        int v[8]; int s = 0;
        int i0 = base + tid * 8;
#pragma unroll
        for (int j = 0; j < 8; ++j) {
            int i = i0 + j;
            v[j] = (i < NN) ? cnt[i] : 0;
            s += v[j];
        }
        sm[tid] = s;
        __syncthreads();
        for (int d = 1; d < 1024; d <<= 1) {
            int t = (tid >= d) ? sm[tid - d] : 0;
            __syncthreads();
            sm[tid] += t;
            __syncthreads();
        }
        int pref = sm[tid] - s + s_carry;
        int total = sm[1023];
#pragma unroll
        for (int j = 0; j < 8; ++j) {
            int i = i0 + j;
            if (i < NN) { off[i] = pref; pos[i] = pref; }
            pref += v[j];
        }
        __syncthreads();
        if (tid == 0) s_carry += total;
        __syncthreads();
    }
    if (tid == 0) off[NN] = NE;
}
__global__ void fill_kernel(const int* __restrict__ dst, int* __restrict__ pos,
                            int* __restrict__ eid) {
    int e = blockIdx.x * blockDim.x + threadIdx.x;
    if (e < NE) {
        int idx = atomicAdd(&pos[dst[e]], 1);
        eid[idx] = e;
    }
}

// ---------------- dense GEMM JPT=1 (exact round-3 form; known good) --------
template <int K, int ACT>
__global__ void __launch_bounds__(128) dense_kernel(
    const float* __restrict__ A, const float* __restrict__ W,
    const float* __restrict__ bias, float* __restrict__ out,
    int n, int Jtotal, int wstride)
{
    constexpr int KP = K + 4;
    constexpr int NT = 16;
    constexpr int NPRE = NT * K / 512;
    extern __shared__ float sm[];
    float* Ws  = sm;              // 128 * KP
    float* ins = sm + 128 * KP;   // NT * K
    const int tid = threadIdx.x;
    const int jbase = blockIdx.y * 128;

    for (int idx = tid; idx < 128 * K; idx += 128) {
        int r = idx / K, k = idx - r * K;
        Ws[r * KP + k] = W[(size_t)(jbase + r) * wstride + k];
    }
    float b = bias ? bias[jbase + tid] : 0.0f;

    const int stride = gridDim.x * NT;
    int t0 = blockIdx.x * NT;
    float4 pre[NPRE];
    if (t0 < n) {
        int lim = min(NT, n - t0) * (K / 4);
#pragma unroll
        for (int i = 0; i < NPRE; ++i) {
            int idx = tid + i * 128;
            pre[i] = (idx < lim) ? ((const float4*)(A + (size_t)t0 * K))[idx]
                                 : make_float4(0.f, 0.f, 0.f, 0.f);
        }
    }
    __syncthreads();

    const float4* wrow = (const float4*)(Ws + (size_t)tid * KP);

    for (; t0 < n; t0 += stride) {
        int cnt = min(NT, n - t0);
#pragma unroll
        for (int i = 0; i < NPRE; ++i)
            ((float4*)ins)[tid + i * 128] = pre[i];
        __syncthreads();
        int tn = t0 + stride;
        if (tn < n) {
            int lim = min(NT, n - tn) * (K / 4);
#pragma unroll
            for (int i = 0; i < NPRE; ++i) {
                int idx = tid + i * 128;
                pre[i] = (idx < lim) ? ((const float4*)(A + (size_t)tn * K))[idx]
                                     : make_float4(0.f, 0.f, 0.f, 0.f);
            }
        }
        float acc[NT];
#pragma unroll
        for (int q = 0; q < NT; ++q) acc[q] = 0.f;

        const float4* ins4 = (const float4*)ins;
#pragma unroll 4
        for (int k4 = 0; k4 < K / 4; ++k4) {
            float4 w = wrow[k4];
#pragma unroll
            for (int q = 0; q < NT; ++q) {
                float4 v = ins4[q * (K / 4) + k4];
                acc[q] += w.x * v.x + w.y * v.y + w.z * v.z + w.w * v.w;
            }
        }
        for (int q = 0; q < cnt; ++q) {
            float r = acc[q] + b;
            if (ACT == 1) r = (r >= 0.f) ? r : 0.01f * r;
            else if (ACT == 2) r = fmaxf(r, 0.f);
            else if (ACT == 3) r = (r > 0.f) ? r : expm1f(r);
            out[(size_t)(t0 + q) * Jtotal + jbase + tid] = r;
        }
        __syncthreads();
    }
}

// ---------------- dense3: N=384 GRU-gate GEMM, 256 threads, FFMA2 ----------
// EPI==0: out[node*384 + j + c*128] = acc + b   (gi buffer)
// EPI==1: fused GRU combine; gi precomputed, hprev = A row; out[node*128+j]
template <int EPI>
__global__ void __launch_bounds__(256) dense3_kernel(
    const float* __restrict__ A, const float* __restrict__ W,
    const float* __restrict__ bias, float* __restrict__ out,
    const float* __restrict__ gi, int n)
{
    constexpr int K = 128, KP = 132, NT = 16;
    extern __shared__ float sm[];
    float* Ws  = sm;                 // 384 * KP
    float* ins = sm + 384 * KP;      // NT * K
    const int tid = threadIdx.x;
    const int j = tid & 127;
    const int qbase = (tid >> 7) * 8;   // 0 or 8

    for (int idx = tid; idx < 384 * K; idx += 256) {
        int r = idx >> 7, k = idx & 127;
        Ws[r * KP + k] = W[(size_t)r * K + k];
    }
    float b[3];
#pragma unroll
    for (int c = 0; c < 3; ++c) b[c] = bias[j + c * 128];

    const int stride = gridDim.x * NT;
    int t0 = blockIdx.x * NT;
    float4 pre[2];
    if (t0 < n) {
        int lim = min(NT, n - t0) * (K / 4);
#pragma unroll
        for (int i = 0; i < 2; ++i) {
            int idx = tid + i * 256;
            pre[i] = (idx < lim) ? ((const float4*)(A + (size_t)t0 * K))[idx]
                                 : make_float4(0.f, 0.f, 0.f, 0.f);
        }
    }
    __syncthreads();

    const float4* wrow[3];
#pragma unroll
    for (int c = 0; c < 3; ++c)
        wrow[c] = (const float4*)(Ws + (size_t)(c * 128 + j) * KP);

    for (; t0 < n; t0 += stride) {
        int cnt = min(NT, n - t0);
#pragma unroll
        for (int i = 0; i < 2; ++i)
            ((float4*)ins)[tid + i * 256] = pre[i];
        __syncthreads();
        int tn = t0 + stride;
        if (tn < n) {
            int lim = min(NT, n - tn) * (K / 4);
#pragma unroll
            for (int i = 0; i < 2; ++i) {
                int idx = tid + i * 256;
                pre[i] = (idx < lim) ? ((const float4*)(A + (size_t)tn * K))[idx]
                                     : make_float4(0.f, 0.f, 0.f, 0.f);
            }
        }
        u64t acc[3][8];
#pragma unroll
        for (int c = 0; c < 3; ++c)
#pragma unroll
            for (int q = 0; q < 8; ++q) acc[c][q] = 0ULL;

        const float4* ins4 = (const float4*)ins + qbase * (K / 4);
#pragma unroll 4
        for (int k4 = 0; k4 < K / 4; ++k4) {
            u64t w01[3], w23[3];
#pragma unroll
            for (int c = 0; c < 3; ++c) {
                float4 w = wrow[c][k4];
                w01[c] = pack2(w.x, w.y);
                w23[c] = pack2(w.z, w.w);
            }
#pragma unroll
            for (int q = 0; q < 8; ++q) {
                float4 v = ins4[q * (K / 4) + k4];
                u64t v01 = pack2(v.x, v.y);
                u64t v23 = pack2(v.z, v.w);
#pragma unroll
                for (int c = 0; c < 3; ++c) {
                    ffma2(acc[c][q], w01[c], v01);
                    ffma2(acc[c][q], w23[c], v23);
                }
            }
        }
        if (EPI == 0) {
#pragma unroll
            for (int q = 0; q < 8; ++q) {
                if (qbase + q < cnt) {
                    size_t node = t0 + qbase + q;
#pragma unroll
                    for (int c = 0; c < 3; ++c)
                        out[node * 384 + j + c * 128] = hsum2(acc[c][q]) + b[c];
                }
            }
        } else {
#pragma unroll
            for (int q = 0; q < 8; ++q) {
                if (qbase + q < cnt) {
                    size_t node = t0 + qbase + q;
                    float hr = hsum2(acc[0][q]) + b[0];
                    float hz = hsum2(acc[1][q]) + b[1];
                    float hn = hsum2(acc[2][q]) + b[2];
                    size_t gbase = node * 384 + j;
                    float r = sigm(gi[gbase] + hr);
                    float z = sigm(gi[gbase + 128] + hz);
                    float nng = tanhf(gi[gbase + 256] + r * hn);
                    float hv = ins[(qbase + q) * 128 + j];
                    out[node * 128 + j] = fmaxf((1.f - z) * nng + z * hv, 0.f);
                }
            }
        }
        __syncthreads();
    }
}

// ---------------- nd gather (CSR) ----------------
__global__ void __launch_bounds__(256) nd_gather_kernel(
    const float* __restrict__ p, const float* __restrict__ ea,
    const int* __restrict__ src, const int* __restrict__ off,
    const int* __restrict__ eid, const float* __restrict__ w1,
    float* __restrict__ tsum)
{
    __shared__ float W1b[16 * 128];   // [k][j]
    const int tid = threadIdx.x;
    for (int idx = tid; idx < 16 * 128; idx += 256) {
        int k = idx >> 7, j = idx & 127;
        W1b[idx] = w1[j * 144 + 128 + k];
    }
    __syncthreads();
    int n = blockIdx.x * 8 + (tid >> 5);
    if (n >= NN) return;
    int lane = tid & 31;
    int beg = off[n], end = off[n + 1];
    float4 acc = make_float4(0.f, 0.f, 0.f, 0.f);
    const float4* W1b4 = (const float4*)W1b;
    const float4* p4 = (const float4*)p;
    for (int e = beg; e < end; ++e) {
        int ed = eid[e];
        int s = src[ed];
        float eav = (lane < 16) ? __ldg(&ea[(size_t)ed * 16 + lane]) : 0.f;
        float4 t = p4[(size_t)s * 32 + lane];
#pragma unroll
        for (int k = 0; k < 16; ++k) {
            float ek = __shfl_sync(0xFFFFFFFFu, eav, k);
            float4 w = W1b4[k * 32 + lane];
            t.x += ek * w.x; t.y += ek * w.y; t.z += ek * w.z; t.w += ek * w.w;
        }
        t.x = (t.x >= 0.f) ? t.x : 0.01f * t.x;
        t.y = (t.y >= 0.f) ? t.y : 0.01f * t.y;
        t.z = (t.z >= 0.f) ? t.z : 0.01f * t.z;
        t.w = (t.w >= 0.f) ? t.w : 0.01f * t.w;
        acc.x += t.x; acc.y += t.y; acc.z += t.z; acc.w += t.w;
    }
    ((float4*)tsum)[(size_t)n * 32 + lane] = acc;
}

// ---------------- GAT attention dots ----------------
__global__ void attn_dots_kernel(const float* __restrict__ xp, const float* __restrict__ asrc,
                                 const float* __restrict__ adst, float* __restrict__ as_,
                                 float* __restrict__ ad_) {
    int n = (blockIdx.x * blockDim.x + threadIdx.x) >> 5;
    int lane = threadIdx.x & 31;
    if (n >= NN) return;
    float4 v = ((const float4*)xp)[(size_t)n * 32 + lane];
    float4 w1 = ((const float4*)asrc)[lane];
    float4 w2 = ((const float4*)adst)[lane];
    float sa = v.x * w1.x + v.y * w1.y + v.z * w1.z + v.w * w1.w;
    float sd = v.x * w2.x + v.y * w2.y + v.z * w2.z + v.w * w2.w;
#pragma unroll
    for (int o = 16; o; o >>= 1) {
        sa += __shfl_xor_sync(0xFFFFFFFFu, sa, o);
        sd += __shfl_xor_sync(0xFFFFFFFFu, sd, o);
    }
    if (lane == 0) { as_[n] = sa; ad_[n] = sd; }
}

// ---------------- GAT gather (CSR, online softmax, fused bias+elu) ----------
__global__ void __launch_bounds__(256) gat_gather_kernel(
    const int* __restrict__ src, const int* __restrict__ off, const int* __restrict__ eid,
    const float* __restrict__ as_, const float* __restrict__ ad_,
    const float* __restrict__ xp, const float* __restrict__ bias,
    float* __restrict__ hout)
{
    int n = blockIdx.x * 8 + (threadIdx.x >> 5);
    if (n >= NN) return;
    int lane = threadIdx.x & 31;
    int beg = off[n], end = off[n + 1];
    float adn = ad_[n];
    float m = -INFINITY, den = 0.f;
    float4 acc = make_float4(0.f, 0.f, 0.f, 0.f);
    const float4* xp4 = (const float4*)xp;
    for (int e = beg; e < end; ++e) {
        int ed = eid[e];
        int s = src[ed];
        float a = __ldg(&as_[s]) + adn;
        a = (a >= 0.f) ? a : 0.01f * a;
        if (a > m) {
            float f = __expf(m - a);
            den *= f;
            acc.x *= f; acc.y *= f; acc.z *= f; acc.w *= f;
            m = a;
        }
        float w = __expf(a - m);
        den += w;
        float4 v = xp4[(size_t)s * 32 + lane];
        acc.x += w * v.x; acc.y += w * v.y; acc.z += w * v.z; acc.w += w * v.w;
    }
    float inv = (den > 0.f) ? 1.f / den : 0.f;
    float4 b = ((const float4*)bias)[lane];
    float4 r;
    r.x = acc.x * inv + b.x; r.y = acc.y * inv + b.y;
    r.z = acc.z * inv + b.z; r.w = acc.w * inv + b.w;
    r.x = (r.x > 0.f) ? r.x : expm1f(r.x);
    r.y = (r.y > 0.f) ? r.y : expm1f(r.y);
    r.z = (r.z > 0.f) ? r.z : expm1f(r.z);
    r.w = (r.w > 0.f) ? r.w : expm1f(r.w);
    ((float4*)hout)[(size_t)n * 32 + lane] = r;
}

// ---------------- readout ----------------
__global__ void __launch_bounds__(128) graph_agg_kernel(const float* __restrict__ xcur,
                                                        const int* __restrict__ batch,
                                                        float* __restrict__ agg,
                                                        float* __restrict__ outv) {
    int g = blockIdx.x;
    int lo, hi;
    {
        int l = 0, r = NN;
        while (l < r) { int m = (l + r) >> 1; if (batch[m] < g) l = m + 1; else r = m; }
        lo = l;
    }
    {
        int l = lo, r = NN;
        while (l < r) { int m = (l + r) >> 1; if (batch[m] < g + 1) l = m + 1; else r = m; }
        hi = l;
    }
    float s = 0.f;
    for (int n = lo; n < hi; ++n) s += xcur[(size_t)n * 128 + threadIdx.x];
    agg[g * 128 + threadIdx.x] = s;
    outv[g * 128 + threadIdx.x] = fmaxf(s, 0.f);
}

__global__ void add_kernel(const float* __restrict__ a, const float* __restrict__ b,
                           float* __restrict__ c, int n) {
    int t = blockIdx.x * blockDim.x + threadIdx.x;
    if (t < n) c[t] = a[t] + b[t];
}

__global__ void lstm_combine_kernel(const float* __restrict__ gi, const float* __restrict__ gh,
                                    const float* __restrict__ hc, float* __restrict__ out) {
    int t = blockIdx.x * blockDim.x + threadIdx.x;
    if (t >= NG * 128) return;
    int g = t >> 7, j = t & 127;
    size_t base = (size_t)g * 512;
    float gI = gi[base + j]       + gh[base + j];
    float gF = gi[base + 128 + j] + gh[base + 128 + j];
    float gG = gi[base + 256 + j] + gh[base + 256 + j];
    float gO = gi[base + 384 + j] + gh[base + 384 + j];
    float c = hc[t];
    float c2 = sigm(gF) * c + sigm(gI) * tanhf(gG);
    out[t] = sigm(gO) * tanhf(c2);
}

__global__ void final_kernel(const float* __restrict__ outv, const float* __restrict__ w,
                             const float* __restrict__ b, float* __restrict__ res) {
    int g = (blockIdx.x * blockDim.x + threadIdx.x) >> 5;
    int lane = threadIdx.x & 31;
    if (g >= NG) return;
    float4 v = ((const float4*)outv)[(size_t)g * 32 + lane];
    float4 ww = ((const float4*)w)[lane];
    float s = v.x * ww.x + v.y * ww.y + v.z * ww.z + v.w * ww.w;
#pragma unroll
    for (int o = 16; o; o >>= 1) s += __shfl_xor_sync(0xFFFFFFFFu, s, o);
    if (lane == 0) res[g] = s + b[0];
}

// ---------------- host ----------------
#define SM_J1K64  ((128 * 68 + 16 * 64) * 4)
#define SM_J1K128 ((128 * 132 + 16 * 128) * 4)
#define SM_D3     ((384 * 132 + 16 * 128) * 4)

extern "C" void kernel_launch(void* const* d_in, const int* in_sizes, int n_in,
                              void* d_out, int out_size) {
    const float* x        = (const float*)d_in[0];
    const int*   ei       = (const int*)  d_in[1];
    const float* ea       = (const float*)d_in[2];
    const int*   batch    = (const int*)  d_in[3];
    const float* lin1_w   = (const float*)d_in[4];
    const float* lin1_b   = (const float*)d_in[5];
    const float* nd_lin1w = (const float*)d_in[6];
    const float* nd_lin2w = (const float*)d_in[7];
    const float* nd_bias  = (const float*)d_in[8];
    const float* gru0_wih = (const float*)d_in[9];
    const float* gru0_whh = (const float*)d_in[10];
    const float* gru0_bih = (const float*)d_in[11];
    const float* gru0_bhh = (const float*)d_in[12];
    const float* gat_w    = (const float*)d_in[13];
    const float* gat_asrc = (const float*)d_in[14];
    const float* gat_adst = (const float*)d_in[15];
    const float* gat_b    = (const float*)d_in[16];
    const float* gru_wih  = (const float*)d_in[17];
    const float* gru_whh  = (const float*)d_in[18];
    const float* gru_bih  = (const float*)d_in[19];
    const float* gru_bhh  = (const float*)d_in[20];
    const float* gin_w    = (const float*)d_in[21];
    const float* gin_b    = (const float*)d_in[22];
    const float* lstm_wih = (const float*)d_in[23];
    const float* lstm_whh = (const float*)d_in[24];
    const float* lstm_bih = (const float*)d_in[25];
    const float* lstm_bhh = (const float*)d_in[26];
    const float* lin2_w   = (const float*)d_in[27];
    const float* lin2_b   = (const float*)d_in[28];
    float* out = (float*)d_out;

    const int* src = ei;
    const int* dst = ei + NE;

    float *px1, *pp, *ph, *pxc, *pgi, *pas, *pad;
    float *pagg, *pgout, *pghh, *pgtmp, *pggi, *pggh;
    int *pcnt, *poff, *ppos, *peid;
    cudaGetSymbolAddress((void**)&px1, f_x1);
    cudaGetSymbolAddress((void**)&pp, f_p);
    cudaGetSymbolAddress((void**)&ph, f_h);
    cudaGetSymbolAddress((void**)&pxc, f_xcur);
    cudaGetSymbolAddress((void**)&pgi, f_gi);
    cudaGetSymbolAddress((void**)&pas, f_as);
    cudaGetSymbolAddress((void**)&pad, f_ad);
    cudaGetSymbolAddress((void**)&pagg, g_agg);
    cudaGetSymbolAddress((void**)&pgout, g_out);
    cudaGetSymbolAddress((void**)&pghh, g_hh);
    cudaGetSymbolAddress((void**)&pgtmp, g_tmp);
    cudaGetSymbolAddress((void**)&pggi, g_gi);
    cudaGetSymbolAddress((void**)&pggh, g_gh);
    cudaGetSymbolAddress((void**)&pcnt, c_cnt);
    cudaGetSymbolAddress((void**)&poff, c_off);
    cudaGetSymbolAddress((void**)&ppos, c_pos);
    cudaGetSymbolAddress((void**)&peid, c_eid);

    cudaFuncSetAttribute((const void*)dense_kernel<64, 1>, cudaFuncAttributeMaxDynamicSharedMemorySize, SM_J1K64);
    cudaFuncSetAttribute((const void*)dense_kernel<128, 0>, cudaFuncAttributeMaxDynamicSharedMemorySize, SM_J1K128);
    cudaFuncSetAttribute((const void*)dense_kernel<128, 3>, cudaFuncAttributeMaxDynamicSharedMemorySize, SM_J1K128);
    cudaFuncSetAttribute((const void*)dense3_kernel<0>, cudaFuncAttributeMaxDynamicSharedMemorySize, SM_D3);
    cudaFuncSetAttribute((const void*)dense3_kernel<1>, cudaFuncAttributeMaxDynamicSharedMemorySize, SM_D3);

    const int GP1 = 444;   // JPT=1 K=128: 3 CTAs/SM
    const int GP1b = 592;  // JPT=1 K=64
    const int GP3 = 148;   // dense3: 1 CTA/SM, 256 threads
    const int tilesG = (NG + 15) / 16;
    const int ZB = 256;

    // launch order arranged so ncu slot 5 = p GEMM (dense JPT1 K=128)
    // 0) x1 = leaky(x @ lin1_w.T + b)
    dense_kernel<64, 1><<<dim3(GP1b, 1), 128, SM_J1K64>>>(x, lin1_w, lin1_b, px1, NN, 128, 64);
    // 1-4) CSR build (by dst)
    zero_i_kernel<<<(NN + ZB - 1) / ZB, ZB>>>(pcnt, NN);
    hist_kernel<<<(NE + ZB - 1) / ZB, ZB>>>(dst, pcnt);
    scan_kernel<<<1, 1024>>>(pcnt, poff, ppos);
    fill_kernel<<<(NE + ZB - 1) / ZB, ZB>>>(dst, ppos, peid);
    // 5) p = x1 @ W1a.T   <-- profiled launch
    dense_kernel<128, 0><<<dim3(GP1, 1), 128, SM_J1K128>>>(px1, nd_lin1w, nullptr, pp, NN, 128, 144);
    // tsum = segment_sum(leaky(p[src] + ea @ W1b.T))
    nd_gather_kernel<<<(NN + 7) / 8, 256>>>(pp, ea, src, poff, peid, nd_lin1w, pgi);
    // h = elu(tsum @ W2.T + nd_bias)
    dense_kernel<128, 3><<<dim3(GP1, 1), 128, SM_J1K128>>>(pgi, nd_lin2w, nd_bias, ph, NN, 128, 128);
    // GRU0
    dense3_kernel<0><<<GP3, 256, SM_D3>>>(ph, gru0_wih, gru0_bih, pgi, nullptr, NN);
    dense3_kernel<1><<<GP3, 256, SM_D3>>>(px1, gru0_whh, gru0_bhh, pxc, pgi, NN);

    // GAT layers
    for (int l = 0; l < 2; ++l) {
        dense_kernel<128, 0><<<dim3(GP1, 1), 128, SM_J1K128>>>(pxc, gat_w + (size_t)l * 128 * 128, nullptr, pp, NN, 128, 128);
        attn_dots_kernel<<<(NN * 32 + ZB - 1) / ZB, ZB>>>(pp, gat_asrc + l * 128, gat_adst + l * 128, pas, pad);
        gat_gather_kernel<<<(NN + 7) / 8, 256>>>(src, poff, peid, pas, pad, pp, gat_b + l * 128, ph);
        dense3_kernel<0><<<GP3, 256, SM_D3>>>(ph, gru_wih + (size_t)l * 384 * 128, gru_bih + l * 384, pgi, nullptr, NN);
        dense3_kernel<1><<<GP3, 256, SM_D3>>>(pxc, gru_whh + (size_t)l * 384 * 128, gru_bhh + l * 384, pxc, pgi, NN);
    }

    // readout
    graph_agg_kernel<<<NG, 128>>>(pxc, batch, pagg, pgout);
    for (int t = 0; t < 2; ++t) {
        add_kernel<<<(NG * 128 + ZB - 1) / ZB, ZB>>>(pgout, pagg, pgtmp, NG * 128);
        dense_kernel<128, 3><<<dim3(tilesG, 1), 128, SM_J1K128>>>(pgtmp, gin_w, gin_b, pghh, NG, 128, 128);
        dense_kernel<128, 0><<<dim3(tilesG, 4), 128, SM_J1K128>>>(pgout, lstm_wih, lstm_bih, pggi, NG, 512, 128);
        dense_kernel<128, 0><<<dim3(tilesG, 4), 128, SM_J1K128>>>(pghh, lstm_whh, lstm_bhh, pggh, NG, 512, 128);
        lstm_combine_kernel<<<(NG * 128 + ZB - 1) / ZB, ZB>>>(pggi, pggh, pghh, pgout);
    }
    final_kernel<<<(NG * 32 + 127) / 128, 128>>>(pgout, lin2_w, lin2_b, out);
}

// round 6
// speedup vs baseline: 1.9156x; 1.0230x over previous
#include <cuda_runtime.h>
#include <math.h>

#define NN 50000
#define NE 500000
#define NG 2000

typedef unsigned long long u64t;

// ---------------- scratch (device globals) ----------------
__device__ float f_x1  [NN * 128];
__device__ float f_p   [NN * 128];
__device__ float f_h   [NN * 128];
__device__ float f_xcur[NN * 128];
__device__ float f_gi  [NN * 3 * 128];  // also reused as tsum (first NN*128)
__device__ float f_as  [NN];
__device__ float f_ad  [NN];
__device__ float g_agg [NG * 128];
__device__ float g_out [NG * 128];
__device__ float g_hh  [NG * 128];
__device__ float g_tmp [NG * 128];
__device__ float g_gi  [NG * 4 * 128];
__device__ float g_gh  [NG * 4 * 128];
// CSR
__device__ int c_cnt[NN];
__device__ int c_off[NN + 1];
__device__ int c_pos[NN];
__device__ int c_eid[NE];
__device__ int c_part[64];

__device__ __forceinline__ float sigm(float x) { return 1.0f / (1.0f + expf(-x)); }

__device__ __forceinline__ void ffma2(u64t& d, u64t a, u64t b) {
    asm("fma.rn.f32x2 %0, %1, %2, %0;" : "+l"(d) : "l"(a), "l"(b));
}
__device__ __forceinline__ u64t pack2(float lo, float hi) {
    u64t r;
    asm("mov.b64 %0, {%1, %2};" : "=l"(r) : "f"(lo), "f"(hi));
    return r;
}
__device__ __forceinline__ float hsum2(u64t v) {
    float lo, hi;
    asm("mov.b64 {%0, %1}, %2;" : "=f"(lo), "=f"(hi) : "l"(v));
    return lo + hi;
}

// ---------------- CSR build ----------------
__global__ void zero_i_kernel(int* p, int n) {
    int t = blockIdx.x * blockDim.x + threadIdx.x;
    if (t < n) p[t] = 0;
}
__global__ void hist_kernel(const int* __restrict__ dst, int* __restrict__ cnt) {
    int e = blockIdx.x * blockDim.x + threadIdx.x;
    if (e < NE) atomicAdd(&cnt[dst[e]], 1);
}
// phase 1: per-1024-chunk sums
__global__ void __launch_bounds__(256) scan_part_kernel(const int* __restrict__ cnt,
                                                        int* __restrict__ part) {
    __shared__ int sm[256];
    int base = blockIdx.x * 1024;
    int s = 0;
    for (int i = threadIdx.x; i < 1024; i += 256) {
        int idx = base + i;
        s += (idx < NN) ? cnt[idx] : 0;
    }
    sm[threadIdx.x] = s;
    __syncthreads();
    for (int d = 128; d; d >>= 1) {
        if (threadIdx.x < d) sm[threadIdx.x] += sm[threadIdx.x + d];
        __syncthreads();
    }
    if (threadIdx.x == 0) part[blockIdx.x] = sm[0];
}
// phase 2: tiny serial exclusive scan of partials
__global__ void scan_mid_kernel(int* part, int npart) {
    if (threadIdx.x == 0) {
        int run = 0;
        for (int i = 0; i < npart; ++i) { int v = part[i]; part[i] = run; run += v; }
    }
}
// phase 3: per-chunk exclusive scan + global offset
__global__ void __launch_bounds__(256) scan_final_kernel(const int* __restrict__ cnt,
                                                         const int* __restrict__ part,
                                                         int* __restrict__ off,
                                                         int* __restrict__ pos) {
    __shared__ int wsum[8];
    int base = blockIdx.x * 1024;
    int lane = threadIdx.x & 31, wid = threadIdx.x >> 5;
    int v[4]; int s = 0;
    int i0 = base + threadIdx.x * 4;
#pragma unroll
    for (int i = 0; i < 4; ++i) {
        int idx = i0 + i;
        v[i] = (idx < NN) ? cnt[idx] : 0;
        s += v[i];
    }
    int ps = s;
#pragma unroll
    for (int o = 1; o < 32; o <<= 1) {
        int t = __shfl_up_sync(0xFFFFFFFFu, ps, o);
        if (lane >= o) ps += t;
    }
    if (lane == 31) wsum[wid] = ps;
    __syncthreads();
    if (threadIdx.x == 0) {
        int run = 0;
#pragma unroll
        for (int w = 0; w < 8; ++w) { int t = wsum[w]; wsum[w] = run; run += t; }
    }
    __syncthreads();
    int excl = ps - s + wsum[wid] + part[blockIdx.x];
#pragma unroll
    for (int i = 0; i < 4; ++i) {
        int idx = i0 + i;
        if (idx < NN) { off[idx] = excl; pos[idx] = excl; }
        excl += v[i];
    }
    if (blockIdx.x == 0 && threadIdx.x == 0) off[NN] = NE;
}
__global__ void fill_kernel(const int* __restrict__ dst, int* __restrict__ pos,
                            int* __restrict__ eid) {
    int e = blockIdx.x * blockDim.x + threadIdx.x;
    if (e < NE) {
        int idx = atomicAdd(&pos[dst[e]], 1);
        eid[idx] = e;
    }
}

// ---------------- dense GEMM JPT=1 generic (used for K=64 + graph-level) ---
template <int K, int ACT>
__global__ void __launch_bounds__(128) dense_kernel(
    const float* __restrict__ A, const float* __restrict__ W,
    const float* __restrict__ bias, float* __restrict__ out,
    int n, int Jtotal, int wstride)
{
    constexpr int KP = K + 4;
    constexpr int NT = 16;
    constexpr int NPRE = NT * K / 512;
    extern __shared__ float sm[];
    float* Ws  = sm;              // 128 * KP
    float* ins = sm + 128 * KP;   // NT * K
    const int tid = threadIdx.x;
    const int jbase = blockIdx.y * 128;

    for (int idx = tid; idx < 128 * K; idx += 128) {
        int r = idx / K, k = idx - r * K;
        Ws[r * KP + k] = W[(size_t)(jbase + r) * wstride + k];
    }
    float b = bias ? bias[jbase + tid] : 0.0f;

    const int stride = gridDim.x * NT;
    int t0 = blockIdx.x * NT;
    float4 pre[NPRE];
    if (t0 < n) {
        int lim = min(NT, n - t0) * (K / 4);
#pragma unroll
        for (int i = 0; i < NPRE; ++i) {
            int idx = tid + i * 128;
            pre[i] = (idx < lim) ? ((const float4*)(A + (size_t)t0 * K))[idx]
                                 : make_float4(0.f, 0.f, 0.f, 0.f);
        }
    }
    __syncthreads();

    const float4* wrow = (const float4*)(Ws + (size_t)tid * KP);

    for (; t0 < n; t0 += stride) {
        int cnt = min(NT, n - t0);
#pragma unroll
        for (int i = 0; i < NPRE; ++i)
            ((float4*)ins)[tid + i * 128] = pre[i];
        __syncthreads();
        int tn = t0 + stride;
        if (tn < n) {
            int lim = min(NT, n - tn) * (K / 4);
#pragma unroll
            for (int i = 0; i < NPRE; ++i) {
                int idx = tid + i * 128;
                pre[i] = (idx < lim) ? ((const float4*)(A + (size_t)tn * K))[idx]
                                     : make_float4(0.f, 0.f, 0.f, 0.f);
            }
        }
        float acc[NT];
#pragma unroll
        for (int q = 0; q < NT; ++q) acc[q] = 0.f;

        const float4* ins4 = (const float4*)ins;
#pragma unroll 4
        for (int k4 = 0; k4 < K / 4; ++k4) {
            float4 w = wrow[k4];
#pragma unroll
            for (int q = 0; q < NT; ++q) {
                float4 v = ins4[q * (K / 4) + k4];
                acc[q] += w.x * v.x + w.y * v.y + w.z * v.z + w.w * v.w;
            }
        }
        for (int q = 0; q < cnt; ++q) {
            float r = acc[q] + b;
            if (ACT == 1) r = (r >= 0.f) ? r : 0.01f * r;
            else if (ACT == 2) r = fmaxf(r, 0.f);
            else if (ACT == 3) r = (r > 0.f) ? r : expm1f(r);
            out[(size_t)(t0 + q) * Jtotal + jbase + tid] = r;
        }
        __syncthreads();
    }
}

// ---------------- dense1: K=128 J=128 GEMM, 256 threads, FFMA2 -------------
template <int ACT>
__global__ void __launch_bounds__(256) dense1_kernel(
    const float* __restrict__ A, const float* __restrict__ W,
    const float* __restrict__ bias, float* __restrict__ out,
    int n, int Jtotal, int wstride)
{
    constexpr int K = 128, KP = 132, NT = 16;
    extern __shared__ float sm[];
    float* Ws  = sm;                 // 128 * KP
    float* ins = sm + 128 * KP;      // NT * K
    const int tid = threadIdx.x;
    const int j = tid & 127;
    const int qbase = (tid >> 7) * 8;   // 0 or 8
    const int jbase = blockIdx.y * 128;

    for (int idx = tid; idx < 128 * K; idx += 256) {
        int r = idx >> 7, k = idx & 127;
        Ws[r * KP + k] = W[(size_t)(jbase + r) * wstride + k];
    }
    float b = bias ? bias[jbase + j] : 0.0f;

    const int stride = gridDim.x * NT;
    int t0 = blockIdx.x * NT;
    float4 pre[2];
    if (t0 < n) {
        int lim = min(NT, n - t0) * (K / 4);
#pragma unroll
        for (int i = 0; i < 2; ++i) {
            int idx = tid + i * 256;
            pre[i] = (idx < lim) ? ((const float4*)(A + (size_t)t0 * K))[idx]
                                 : make_float4(0.f, 0.f, 0.f, 0.f);
        }
    }
    __syncthreads();

    const float4* wrow = (const float4*)(Ws + (size_t)j * KP);

    for (; t0 < n; t0 += stride) {
        int cnt = min(NT, n - t0);
#pragma unroll
        for (int i = 0; i < 2; ++i)
            ((float4*)ins)[tid + i * 256] = pre[i];
        __syncthreads();
        int tn = t0 + stride;
        if (tn < n) {
            int lim = min(NT, n - tn) * (K / 4);
#pragma unroll
            for (int i = 0; i < 2; ++i) {
                int idx = tid + i * 256;
                pre[i] = (idx < lim) ? ((const float4*)(A + (size_t)tn * K))[idx]
                                     : make_float4(0.f, 0.f, 0.f, 0.f);
            }
        }
        u64t acc[8];
#pragma unroll
        for (int q = 0; q < 8; ++q) acc[q] = 0ULL;

        const float4* ins4 = (const float4*)ins + qbase * (K / 4);
#pragma unroll 4
        for (int k4 = 0; k4 < K / 4; ++k4) {
            float4 w = wrow[k4];
            u64t w01 = pack2(w.x, w.y);
            u64t w23 = pack2(w.z, w.w);
#pragma unroll
            for (int q = 0; q < 8; ++q) {
                float4 v = ins4[q * (K / 4) + k4];
                ffma2(acc[q], w01, pack2(v.x, v.y));
                ffma2(acc[q], w23, pack2(v.z, v.w));
            }
        }
#pragma unroll
        for (int q = 0; q < 8; ++q) {
            if (qbase + q < cnt) {
                float r = hsum2(acc[q]) + b;
                if (ACT == 1) r = (r >= 0.f) ? r : 0.01f * r;
                else if (ACT == 2) r = fmaxf(r, 0.f);
                else if (ACT == 3) r = (r > 0.f) ? r : expm1f(r);
                out[(size_t)(t0 + qbase + q) * Jtotal + jbase + j] = r;
            }
        }
        __syncthreads();
    }
}

// ---------------- dense3: N=384 GRU-gate GEMM, 256 threads, FFMA2 ----------
template <int EPI>
__global__ void __launch_bounds__(256) dense3_kernel(
    const float* __restrict__ A, const float* __restrict__ W,
    const float* __restrict__ bias, float* __restrict__ out,
    const float* __restrict__ gi, int n)
{
    constexpr int K = 128, KP = 132, NT = 16;
    extern __shared__ float sm[];
    float* Ws  = sm;                 // 384 * KP
    float* ins = sm + 384 * KP;      // NT * K
    const int tid = threadIdx.x;
    const int j = tid & 127;
    const int qbase = (tid >> 7) * 8;   // 0 or 8

    for (int idx = tid; idx < 384 * K; idx += 256) {
        int r = idx >> 7, k = idx & 127;
        Ws[r * KP + k] = W[(size_t)r * K + k];
    }
    float b[3];
#pragma unroll
    for (int c = 0; c < 3; ++c) b[c] = bias[j + c * 128];

    const int stride = gridDim.x * NT;
    int t0 = blockIdx.x * NT;
    float4 pre[2];
    if (t0 < n) {
        int lim = min(NT, n - t0) * (K / 4);
#pragma unroll
        for (int i = 0; i < 2; ++i) {
            int idx = tid + i * 256;
            pre[i] = (idx < lim) ? ((const float4*)(A + (size_t)t0 * K))[idx]
                                 : make_float4(0.f, 0.f, 0.f, 0.f);
        }
    }
    __syncthreads();

    const float4* wrow[3];
#pragma unroll
    for (int c = 0; c < 3; ++c)
        wrow[c] = (const float4*)(Ws + (size_t)(c * 128 + j) * KP);

    for (; t0 < n; t0 += stride) {
        int cnt = min(NT, n - t0);
#pragma unroll
        for (int i = 0; i < 2; ++i)
            ((float4*)ins)[tid + i * 256] = pre[i];
        __syncthreads();
        int tn = t0 + stride;
        if (tn < n) {
            int lim = min(NT, n - tn) * (K / 4);
#pragma unroll
            for (int i = 0; i < 2; ++i) {
                int idx = tid + i * 256;
                pre[i] = (idx < lim) ? ((const float4*)(A + (size_t)tn * K))[idx]
                                     : make_float4(0.f, 0.f, 0.f, 0.f);
            }
        }
        u64t acc[3][8];
#pragma unroll
        for (int c = 0; c < 3; ++c)
#pragma unroll
            for (int q = 0; q < 8; ++q) acc[c][q] = 0ULL;

        const float4* ins4 = (const float4*)ins + qbase * (K / 4);
#pragma unroll 4
        for (int k4 = 0; k4 < K / 4; ++k4) {
            u64t w01[3], w23[3];
#pragma unroll
            for (int c = 0; c < 3; ++c) {
                float4 w = wrow[c][k4];
                w01[c] = pack2(w.x, w.y);
                w23[c] = pack2(w.z, w.w);
            }
#pragma unroll
            for (int q = 0; q < 8; ++q) {
                float4 v = ins4[q * (K / 4) + k4];
                u64t v01 = pack2(v.x, v.y);
                u64t v23 = pack2(v.z, v.w);
#pragma unroll
                for (int c = 0; c < 3; ++c) {
                    ffma2(acc[c][q], w01[c], v01);
                    ffma2(acc[c][q], w23[c], v23);
                }
            }
        }
        if (EPI == 0) {
#pragma unroll
            for (int q = 0; q < 8; ++q) {
                if (qbase + q < cnt) {
                    size_t node = t0 + qbase + q;
#pragma unroll
                    for (int c = 0; c < 3; ++c)
                        out[node * 384 + j + c * 128] = hsum2(acc[c][q]) + b[c];
                }
            }
        } else {
#pragma unroll
            for (int q = 0; q < 8; ++q) {
                if (qbase + q < cnt) {
                    size_t node = t0 + qbase + q;
                    float hr = hsum2(acc[0][q]) + b[0];
                    float hz = hsum2(acc[1][q]) + b[1];
                    float hn = hsum2(acc[2][q]) + b[2];
                    size_t gbase = node * 384 + j;
                    float r = sigm(gi[gbase] + hr);
                    float z = sigm(gi[gbase + 128] + hz);
                    float nng = tanhf(gi[gbase + 256] + r * hn);
                    float hv = ins[(qbase + q) * 128 + j];
                    out[node * 128 + j] = fmaxf((1.f - z) * nng + z * hv, 0.f);
                }
            }
        }
        __syncthreads();
    }
}

// ---------------- nd gather (CSR) ----------------
__global__ void __launch_bounds__(256) nd_gather_kernel(
    const float* __restrict__ p, const float* __restrict__ ea,
    const int* __restrict__ src, const int* __restrict__ off,
    const int* __restrict__ eid, const float* __restrict__ w1,
    float* __restrict__ tsum)
{
    __shared__ float W1b[16 * 128];   // [k][j]
    const int tid = threadIdx.x;
    for (int idx = tid; idx < 16 * 128; idx += 256) {
        int k = idx >> 7, j = idx & 127;
        W1b[idx] = w1[j * 144 + 128 + k];
    }
    __syncthreads();
    int n = blockIdx.x * 8 + (tid >> 5);
    if (n >= NN) return;
    int lane = tid & 31;
    int beg = off[n], end = off[n + 1];
    float4 acc = make_float4(0.f, 0.f, 0.f, 0.f);
    const float4* W1b4 = (const float4*)W1b;
    const float4* p4 = (const float4*)p;
    for (int e = beg; e < end; ++e) {
        int ed = eid[e];
        int s = src[ed];
        float eav = (lane < 16) ? __ldg(&ea[(size_t)ed * 16 + lane]) : 0.f;
        float4 t = p4[(size_t)s * 32 + lane];
#pragma unroll
        for (int k = 0; k < 16; ++k) {
            float ek = __shfl_sync(0xFFFFFFFFu, eav, k);
            float4 w = W1b4[k * 32 + lane];
            t.x += ek * w.x; t.y += ek * w.y; t.z += ek * w.z; t.w += ek * w.w;
        }
        t.x = (t.x >= 0.f) ? t.x : 0.01f * t.x;
        t.y = (t.y >= 0.f) ? t.y : 0.01f * t.y;
        t.z = (t.z >= 0.f) ? t.z : 0.01f * t.z;
        t.w = (t.w >= 0.f) ? t.w : 0.01f * t.w;
        acc.x += t.x; acc.y += t.y; acc.z += t.z; acc.w += t.w;
    }
    ((float4*)tsum)[(size_t)n * 32 + lane] = acc;
}

// ---------------- GAT attention dots ----------------
__global__ void attn_dots_kernel(const float* __restrict__ xp, const float* __restrict__ asrc,
                                 const float* __restrict__ adst, float* __restrict__ as_,
                                 float* __restrict__ ad_) {
    int n = (blockIdx.x * blockDim.x + threadIdx.x) >> 5;
    int lane = threadIdx.x & 31;
    if (n >= NN) return;
    float4 v = ((const float4*)xp)[(size_t)n * 32 + lane];
    float4 w1 = ((const float4*)asrc)[lane];
    float4 w2 = ((const float4*)adst)[lane];
    float sa = v.x * w1.x + v.y * w1.y + v.z * w1.z + v.w * w1.w;
    float sd = v.x * w2.x + v.y * w2.y + v.z * w2.z + v.w * w2.w;
#pragma unroll
    for (int o = 16; o; o >>= 1) {
        sa += __shfl_xor_sync(0xFFFFFFFFu, sa, o);
        sd += __shfl_xor_sync(0xFFFFFFFFu, sd, o);
    }
    if (lane == 0) { as_[n] = sa; ad_[n] = sd; }
}

// ---------------- GAT gather (CSR, online softmax, fused bias+elu) ----------
__global__ void __launch_bounds__(256) gat_gather_kernel(
    const int* __restrict__ src, const int* __restrict__ off, const int* __restrict__ eid,
    const float* __restrict__ as_, const float* __restrict__ ad_,
    const float* __restrict__ xp, const float* __restrict__ bias,
    float* __restrict__ hout)
{
    int n = blockIdx.x * 8 + (threadIdx.x >> 5);
    if (n >= NN) return;
    int lane = threadIdx.x & 31;
    int beg = off[n], end = off[n + 1];
    float adn = ad_[n];
    float m = -INFINITY, den = 0.f;
    float4 acc = make_float4(0.f, 0.f, 0.f, 0.f);
    const float4* xp4 = (const float4*)xp;
    for (int e = beg; e < end; ++e) {
        int ed = eid[e];
        int s = src[ed];
        float a = __ldg(&as_[s]) + adn;
        a = (a >= 0.f) ? a : 0.01f * a;
        if (a > m) {
            float f = __expf(m - a);
            den *= f;
            acc.x *= f; acc.y *= f; acc.z *= f; acc.w *= f;
            m = a;
        }
        float w = __expf(a - m);
        den += w;
        float4 v = xp4[(size_t)s * 32 + lane];
        acc.x += w * v.x; acc.y += w * v.y; acc.z += w * v.z; acc.w += w * v.w;
    }
    float inv = (den > 0.f) ? 1.f / den : 0.f;
    float4 b = ((const float4*)bias)[lane];
    float4 r;
    r.x = acc.x * inv + b.x; r.y = acc.y * inv + b.y;
    r.z = acc.z * inv + b.z; r.w = acc.w * inv + b.w;
    r.x = (r.x > 0.f) ? r.x : expm1f(r.x);
    r.y = (r.y > 0.f) ? r.y : expm1f(r.y);
    r.z = (r.z > 0.f) ? r.z : expm1f(r.z);
    r.w = (r.w > 0.f) ? r.w : expm1f(r.w);
    ((float4*)hout)[(size_t)n * 32 + lane] = r;
}

// ---------------- readout ----------------
__global__ void __launch_bounds__(128) graph_agg_kernel(const float* __restrict__ xcur,
                                                        const int* __restrict__ batch,
                                                        float* __restrict__ agg,
                                                        float* __restrict__ outv) {
    int g = blockIdx.x;
    int lo, hi;
    {
        int l = 0, r = NN;
        while (l < r) { int m = (l + r) >> 1; if (batch[m] < g) l = m + 1; else r = m; }
        lo = l;
    }
    {
        int l = lo, r = NN;
        while (l < r) { int m = (l + r) >> 1; if (batch[m] < g + 1) l = m + 1; else r = m; }
        hi = l;
    }
    float s = 0.f;
    for (int n = lo; n < hi; ++n) s += xcur[(size_t)n * 128 + threadIdx.x];
    agg[g * 128 + threadIdx.x] = s;
    outv[g * 128 + threadIdx.x] = fmaxf(s, 0.f);
}

__global__ void add_kernel(const float* __restrict__ a, const float* __restrict__ b,
                           float* __restrict__ c, int n) {
    int t = blockIdx.x * blockDim.x + threadIdx.x;
    if (t < n) c[t] = a[t] + b[t];
}

__global__ void lstm_combine_kernel(const float* __restrict__ gi, const float* __restrict__ gh,
                                    const float* __restrict__ hc, float* __restrict__ out) {
    int t = blockIdx.x * blockDim.x + threadIdx.x;
    if (t >= NG * 128) return;
    int g = t >> 7, j = t & 127;
    size_t base = (size_t)g * 512;
    float gI = gi[base + j]       + gh[base + j];
    float gF = gi[base + 128 + j] + gh[base + 128 + j];
    float gG = gi[base + 256 + j] + gh[base + 256 + j];
    float gO = gi[base + 384 + j] + gh[base + 384 + j];
    float c = hc[t];
    float c2 = sigm(gF) * c + sigm(gI) * tanhf(gG);
    out[t] = sigm(gO) * tanhf(c2);
}

__global__ void final_kernel(const float* __restrict__ outv, const float* __restrict__ w,
                             const float* __restrict__ b, float* __restrict__ res) {
    int g = (blockIdx.x * blockDim.x + threadIdx.x) >> 5;
    int lane = threadIdx.x & 31;
    if (g >= NG) return;
    float4 v = ((const float4*)outv)[(size_t)g * 32 + lane];
    float4 ww = ((const float4*)w)[lane];
    float s = v.x * ww.x + v.y * ww.y + v.z * ww.z + v.w * ww.w;
#pragma unroll
    for (int o = 16; o; o >>= 1) s += __shfl_xor_sync(0xFFFFFFFFu, s, o);
    if (lane == 0) res[g] = s + b[0];
}

// ---------------- host ----------------
#define SM_J1K64  ((128 * 68 + 16 * 64) * 4)
#define SM_J1K128 ((128 * 132 + 16 * 128) * 4)
#define SM_D1     ((128 * 132 + 16 * 128) * 4)
#define SM_D3     ((384 * 132 + 16 * 128) * 4)

extern "C" void kernel_launch(void* const* d_in, const int* in_sizes, int n_in,
                              void* d_out, int out_size) {
    const float* x        = (const float*)d_in[0];
    const int*   ei       = (const int*)  d_in[1];
    const float* ea       = (const float*)d_in[2];
    const int*   batch    = (const int*)  d_in[3];
    const float* lin1_w   = (const float*)d_in[4];
    const float* lin1_b   = (const float*)d_in[5];
    const float* nd_lin1w = (const float*)d_in[6];
    const float* nd_lin2w = (const float*)d_in[7];
    const float* nd_bias  = (const float*)d_in[8];
    const float* gru0_wih = (const float*)d_in[9];
    const float* gru0_whh = (const float*)d_in[10];
    const float* gru0_bih = (const float*)d_in[11];
    const float* gru0_bhh = (const float*)d_in[12];
    const float* gat_w    = (const float*)d_in[13];
    const float* gat_asrc = (const float*)d_in[14];
    const float* gat_adst = (const float*)d_in[15];
    const float* gat_b    = (const float*)d_in[16];
    const float* gru_wih  = (const float*)d_in[17];
    const float* gru_whh  = (const float*)d_in[18];
    const float* gru_bih  = (const float*)d_in[19];
    const float* gru_bhh  = (const float*)d_in[20];
    const float* gin_w    = (const float*)d_in[21];
    const float* gin_b    = (const float*)d_in[22];
    const float* lstm_wih = (const float*)d_in[23];
    const float* lstm_whh = (const float*)d_in[24];
    const float* lstm_bih = (const float*)d_in[25];
    const float* lstm_bhh = (const float*)d_in[26];
    const float* lin2_w   = (const float*)d_in[27];
    const float* lin2_b   = (const float*)d_in[28];
    float* out = (float*)d_out;

    const int* src = ei;
    const int* dst = ei + NE;

    float *px1, *pp, *ph, *pxc, *pgi, *pas, *pad;
    float *pagg, *pgout, *pghh, *pgtmp, *pggi, *pggh;
    int *pcnt, *poff, *ppos, *peid, *ppart;
    cudaGetSymbolAddress((void**)&px1, f_x1);
    cudaGetSymbolAddress((void**)&pp, f_p);
    cudaGetSymbolAddress((void**)&ph, f_h);
    cudaGetSymbolAddress((void**)&pxc, f_xcur);
    cudaGetSymbolAddress((void**)&pgi, f_gi);
    cudaGetSymbolAddress((void**)&pas, f_as);
    cudaGetSymbolAddress((void**)&pad, f_ad);
    cudaGetSymbolAddress((void**)&pagg, g_agg);
    cudaGetSymbolAddress((void**)&pgout, g_out);
    cudaGetSymbolAddress((void**)&pghh, g_hh);
    cudaGetSymbolAddress((void**)&pgtmp, g_tmp);
    cudaGetSymbolAddress((void**)&pggi, g_gi);
    cudaGetSymbolAddress((void**)&pggh, g_gh);
    cudaGetSymbolAddress((void**)&pcnt, c_cnt);
    cudaGetSymbolAddress((void**)&poff, c_off);
    cudaGetSymbolAddress((void**)&ppos, c_pos);
    cudaGetSymbolAddress((void**)&peid, c_eid);
    cudaGetSymbolAddress((void**)&ppart, c_part);

    cudaFuncSetAttribute((const void*)dense_kernel<64, 1>, cudaFuncAttributeMaxDynamicSharedMemorySize, SM_J1K64);
    cudaFuncSetAttribute((const void*)dense_kernel<128, 0>, cudaFuncAttributeMaxDynamicSharedMemorySize, SM_J1K128);
    cudaFuncSetAttribute((const void*)dense_kernel<128, 3>, cudaFuncAttributeMaxDynamicSharedMemorySize, SM_J1K128);
    cudaFuncSetAttribute((const void*)dense1_kernel<0>, cudaFuncAttributeMaxDynamicSharedMemorySize, SM_D1);
    cudaFuncSetAttribute((const void*)dense1_kernel<3>, cudaFuncAttributeMaxDynamicSharedMemorySize, SM_D1);
    cudaFuncSetAttribute((const void*)dense3_kernel<0>, cudaFuncAttributeMaxDynamicSharedMemorySize, SM_D3);
    cudaFuncSetAttribute((const void*)dense3_kernel<1>, cudaFuncAttributeMaxDynamicSharedMemorySize, SM_D3);

    const int GP1b = 592;  // dense K=64 (128 threads)
    const int GPD1 = 296;  // dense1: 2 CTAs/SM, 256 threads
    const int GP3 = 148;   // dense3: 1 CTA/SM, 256 threads
    const int NPART = (NN + 1023) / 1024;   // 49
    const int tilesG = (NG + 15) / 16;
    const int ZB = 256;

    // 0) x1 = leaky(x @ lin1_w.T + b)
    dense_kernel<64, 1><<<dim3(GP1b, 1), 128, SM_J1K64>>>(x, lin1_w, lin1_b, px1, NN, 128, 64);
    // CSR build (by dst): hist -> 3-phase parallel scan -> fill
    zero_i_kernel<<<(NN + ZB - 1) / ZB, ZB>>>(pcnt, NN);
    hist_kernel<<<(NE + ZB - 1) / ZB, ZB>>>(dst, pcnt);
    scan_part_kernel<<<NPART, 256>>>(pcnt, ppart);
    scan_mid_kernel<<<1, 32>>>(ppart, NPART);
    scan_final_kernel<<<NPART, 256>>>(pcnt, ppart, poff, ppos);
    fill_kernel<<<(NE + ZB - 1) / ZB, ZB>>>(dst, ppos, peid);
    // p = x1 @ W1a.T
    dense1_kernel<0><<<dim3(GPD1, 1), 256, SM_D1>>>(px1, nd_lin1w, nullptr, pp, NN, 128, 144);
    // tsum = segment_sum(leaky(p[src] + ea @ W1b.T))
    nd_gather_kernel<<<(NN + 7) / 8, 256>>>(pp, ea, src, poff, peid, nd_lin1w, pgi);
    // h = elu(tsum @ W2.T + nd_bias)
    dense1_kernel<3><<<dim3(GPD1, 1), 256, SM_D1>>>(pgi, nd_lin2w, nd_bias, ph, NN, 128, 128);
    // GRU0
    dense3_kernel<0><<<GP3, 256, SM_D3>>>(ph, gru0_wih, gru0_bih, pgi, nullptr, NN);
    dense3_kernel<1><<<GP3, 256, SM_D3>>>(px1, gru0_whh, gru0_bhh, pxc, pgi, NN);

    // GAT layers
    for (int l = 0; l < 2; ++l) {
        dense1_kernel<0><<<dim3(GPD1, 1), 256, SM_D1>>>(pxc, gat_w + (size_t)l * 128 * 128, nullptr, pp, NN, 128, 128);
        attn_dots_kernel<<<(NN * 32 + ZB - 1) / ZB, ZB>>>(pp, gat_asrc + l * 128, gat_adst + l * 128, pas, pad);
        gat_gather_kernel<<<(NN + 7) / 8, 256>>>(src, poff, peid, pas, pad, pp, gat_b + l * 128, ph);
        dense3_kernel<0><<<GP3, 256, SM_D3>>>(ph, gru_wih + (size_t)l * 384 * 128, gru_bih + l * 384, pgi, nullptr, NN);
        dense3_kernel<1><<<GP3, 256, SM_D3>>>(pxc, gru_whh + (size_t)l * 384 * 128, gru_bhh + l * 384, pxc, pgi, NN);
    }

    // readout
    graph_agg_kernel<<<NG, 128>>>(pxc, batch, pagg, pgout);
    for (int t = 0; t < 2; ++t) {
        add_kernel<<<(NG * 128 + ZB - 1) / ZB, ZB>>>(pgout, pagg, pgtmp, NG * 128);
        dense_kernel<128, 3><<<dim3(tilesG, 1), 128, SM_J1K128>>>(pgtmp, gin_w, gin_b, pghh, NG, 128, 128);
        dense_kernel<128, 0><<<dim3(tilesG, 4), 128, SM_J1K128>>>(pgout, lstm_wih, lstm_bih, pggi, NG, 512, 128);
        dense_kernel<128, 0><<<dim3(tilesG, 4), 128, SM_J1K128>>>(pghh, lstm_whh, lstm_bhh, pggh, NG, 512, 128);
        lstm_combine_kernel<<<(NG * 128 + ZB - 1) / ZB, ZB>>>(pggi, pggh, pghh, pgout);
    }
    final_kernel<<<(NG * 32 + 127) / 128, 128>>>(pgout, lin2_w, lin2_b, out);
}

// round 7
// speedup vs baseline: 2.3700x; 1.2372x over previous
#include <cuda_runtime.h>
#include <math.h>

#define NN 50000
#define NE 500000
#define NG 2000

typedef unsigned long long u64t;

// ---------------- scratch (device globals) ----------------
__device__ float f_x1  [NN * 128];
__device__ float f_p   [NN * 128];
__device__ float f_h   [NN * 128];
__device__ float f_xcur[NN * 128];
__device__ float f_gi  [NN * 3 * 128];  // also reused as tsum (first NN*128)
__device__ float f_as  [NN];
__device__ float f_ad  [NN];
__device__ float g_agg [NG * 128];
__device__ float g_out [NG * 128];
__device__ float g_hh  [NG * 128];
__device__ float g_tmp [NG * 128];
__device__ float g_gi  [NG * 4 * 128];
__device__ float g_gh  [NG * 4 * 128];
// CSR
__device__ int c_cnt[NN];
__device__ int c_off[NN + 1];
__device__ int c_pos[NN];
__device__ int c_eid[NE];
__device__ int c_part[64];

__device__ __forceinline__ float sigm(float x) { return 1.0f / (1.0f + expf(-x)); }

__device__ __forceinline__ void ffma2(u64t& d, u64t a, u64t b) {
    asm("fma.rn.f32x2 %0, %1, %2, %0;" : "+l"(d) : "l"(a), "l"(b));
}
__device__ __forceinline__ u64t pack2(float lo, float hi) {
    u64t r;
    asm("mov.b64 %0, {%1, %2};" : "=l"(r) : "f"(lo), "f"(hi));
    return r;
}
__device__ __forceinline__ float hsum2(u64t v) {
    float lo, hi;
    asm("mov.b64 {%0, %1}, %2;" : "=f"(lo), "=f"(hi) : "l"(v));
    return lo + hi;
}

// ---------------- CSR build ----------------
__global__ void zero_i_kernel(int* p, int n) {
    int t = blockIdx.x * blockDim.x + threadIdx.x;
    if (t < n) p[t] = 0;
}
__global__ void hist_kernel(const int* __restrict__ dst, int* __restrict__ cnt) {
    int e = blockIdx.x * blockDim.x + threadIdx.x;
    if (e < NE) atomicAdd(&cnt[dst[e]], 1);
}
__global__ void __launch_bounds__(256) scan_part_kernel(const int* __restrict__ cnt,
                                                        int* __restrict__ part) {
    __shared__ int sm[256];
    int base = blockIdx.x * 1024;
    int s = 0;
    for (int i = threadIdx.x; i < 1024; i += 256) {
        int idx = base + i;
        s += (idx < NN) ? cnt[idx] : 0;
    }
    sm[threadIdx.x] = s;
    __syncthreads();
    for (int d = 128; d; d >>= 1) {
        if (threadIdx.x < d) sm[threadIdx.x] += sm[threadIdx.x + d];
        __syncthreads();
    }
    if (threadIdx.x == 0) part[blockIdx.x] = sm[0];
}
__global__ void scan_mid_kernel(int* part, int npart) {
    if (threadIdx.x == 0) {
        int run = 0;
        for (int i = 0; i < npart; ++i) { int v = part[i]; part[i] = run; run += v; }
    }
}
__global__ void __launch_bounds__(256) scan_final_kernel(const int* __restrict__ cnt,
                                                         const int* __restrict__ part,
                                                         int* __restrict__ off,
                                                         int* __restrict__ pos) {
    __shared__ int wsum[8];
    int base = blockIdx.x * 1024;
    int lane = threadIdx.x & 31, wid = threadIdx.x >> 5;
    int v[4]; int s = 0;
    int i0 = base + threadIdx.x * 4;
#pragma unroll
    for (int i = 0; i < 4; ++i) {
        int idx = i0 + i;
        v[i] = (idx < NN) ? cnt[idx] : 0;
        s += v[i];
    }
    int ps = s;
#pragma unroll
    for (int o = 1; o < 32; o <<= 1) {
        int t = __shfl_up_sync(0xFFFFFFFFu, ps, o);
        if (lane >= o) ps += t;
    }
    if (lane == 31) wsum[wid] = ps;
    __syncthreads();
    if (threadIdx.x == 0) {
        int run = 0;
#pragma unroll
        for (int w = 0; w < 8; ++w) { int t = wsum[w]; wsum[w] = run; run += t; }
    }
    __syncthreads();
    int excl = ps - s + wsum[wid] + part[blockIdx.x];
#pragma unroll
    for (int i = 0; i < 4; ++i) {
        int idx = i0 + i;
        if (idx < NN) { off[idx] = excl; pos[idx] = excl; }
        excl += v[i];
    }
    if (blockIdx.x == 0 && threadIdx.x == 0) off[NN] = NE;
}
__global__ void fill_kernel(const int* __restrict__ dst, int* __restrict__ pos,
                            int* __restrict__ eid) {
    int e = blockIdx.x * blockDim.x + threadIdx.x;
    if (e < NE) {
        int idx = atomicAdd(&pos[dst[e]], 1);
        eid[idx] = e;
    }
}

// ---------------- dense GEMM JPT=1 generic (K=64 + graph-level) -----------
template <int K, int ACT>
__global__ void __launch_bounds__(128) dense_kernel(
    const float* __restrict__ A, const float* __restrict__ W,
    const float* __restrict__ bias, float* __restrict__ out,
    int n, int Jtotal, int wstride)
{
    constexpr int KP = K + 4;
    constexpr int NT = 16;
    constexpr int NPRE = NT * K / 512;
    extern __shared__ float sm[];
    float* Ws  = sm;              // 128 * KP
    float* ins = sm + 128 * KP;   // NT * K
    const int tid = threadIdx.x;
    const int jbase = blockIdx.y * 128;

    for (int idx = tid; idx < 128 * K; idx += 128) {
        int r = idx / K, k = idx - r * K;
        Ws[r * KP + k] = W[(size_t)(jbase + r) * wstride + k];
    }
    float b = bias ? bias[jbase + tid] : 0.0f;

    const int stride = gridDim.x * NT;
    int t0 = blockIdx.x * NT;
    float4 pre[NPRE];
    if (t0 < n) {
        int lim = min(NT, n - t0) * (K / 4);
#pragma unroll
        for (int i = 0; i < NPRE; ++i) {
            int idx = tid + i * 128;
            pre[i] = (idx < lim) ? ((const float4*)(A + (size_t)t0 * K))[idx]
                                 : make_float4(0.f, 0.f, 0.f, 0.f);
        }
    }
    __syncthreads();

    const float4* wrow = (const float4*)(Ws + (size_t)tid * KP);

    for (; t0 < n; t0 += stride) {
        int cnt = min(NT, n - t0);
#pragma unroll
        for (int i = 0; i < NPRE; ++i)
            ((float4*)ins)[tid + i * 128] = pre[i];
        __syncthreads();
        int tn = t0 + stride;
        if (tn < n) {
            int lim = min(NT, n - tn) * (K / 4);
#pragma unroll
            for (int i = 0; i < NPRE; ++i) {
                int idx = tid + i * 128;
                pre[i] = (idx < lim) ? ((const float4*)(A + (size_t)tn * K))[idx]
                                     : make_float4(0.f, 0.f, 0.f, 0.f);
            }
        }
        float acc[NT];
#pragma unroll
        for (int q = 0; q < NT; ++q) acc[q] = 0.f;

        const float4* ins4 = (const float4*)ins;
#pragma unroll 4
        for (int k4 = 0; k4 < K / 4; ++k4) {
            float4 w = wrow[k4];
#pragma unroll
            for (int q = 0; q < NT; ++q) {
                float4 v = ins4[q * (K / 4) + k4];
                acc[q] += w.x * v.x + w.y * v.y + w.z * v.z + w.w * v.w;
            }
        }
        for (int q = 0; q < cnt; ++q) {
            float r = acc[q] + b;
            if (ACT == 1) r = (r >= 0.f) ? r : 0.01f * r;
            else if (ACT == 2) r = fmaxf(r, 0.f);
            else if (ACT == 3) r = (r > 0.f) ? r : expm1f(r);
            out[(size_t)(t0 + q) * Jtotal + jbase + tid] = r;
        }
        __syncthreads();
    }
}

// ---------------- dense1: K=128 J=128 GEMM, 256 threads, FFMA2 -------------
template <int ACT>
__global__ void __launch_bounds__(256) dense1_kernel(
    const float* __restrict__ A, const float* __restrict__ W,
    const float* __restrict__ bias, float* __restrict__ out,
    int n, int Jtotal, int wstride)
{
    constexpr int K = 128, KP = 132, NT = 16;
    extern __shared__ float sm[];
    float* Ws  = sm;                 // 128 * KP
    float* ins = sm + 128 * KP;      // NT * K
    const int tid = threadIdx.x;
    const int j = tid & 127;
    const int qbase = (tid >> 7) * 8;   // 0 or 8
    const int jbase = blockIdx.y * 128;

    for (int idx = tid; idx < 128 * K; idx += 256) {
        int r = idx >> 7, k = idx & 127;
        Ws[r * KP + k] = W[(size_t)(jbase + r) * wstride + k];
    }
    float b = bias ? bias[jbase + j] : 0.0f;

    const int stride = gridDim.x * NT;
    int t0 = blockIdx.x * NT;
    float4 pre[2];
    if (t0 < n) {
        int lim = min(NT, n - t0) * (K / 4);
#pragma unroll
        for (int i = 0; i < 2; ++i) {
            int idx = tid + i * 256;
            pre[i] = (idx < lim) ? ((const float4*)(A + (size_t)t0 * K))[idx]
                                 : make_float4(0.f, 0.f, 0.f, 0.f);
        }
    }
    __syncthreads();

    const float4* wrow = (const float4*)(Ws + (size_t)j * KP);

    for (; t0 < n; t0 += stride) {
        int cnt = min(NT, n - t0);
#pragma unroll
        for (int i = 0; i < 2; ++i)
            ((float4*)ins)[tid + i * 256] = pre[i];
        __syncthreads();
        int tn = t0 + stride;
        if (tn < n) {
            int lim = min(NT, n - tn) * (K / 4);
#pragma unroll
            for (int i = 0; i < 2; ++i) {
                int idx = tid + i * 256;
                pre[i] = (idx < lim) ? ((const float4*)(A + (size_t)tn * K))[idx]
                                     : make_float4(0.f, 0.f, 0.f, 0.f);
            }
        }
        u64t acc[8];
#pragma unroll
        for (int q = 0; q < 8; ++q) acc[q] = 0ULL;

        const float4* ins4 = (const float4*)ins + qbase * (K / 4);
#pragma unroll 4
        for (int k4 = 0; k4 < K / 4; ++k4) {
            float4 w = wrow[k4];
            u64t w01 = pack2(w.x, w.y);
            u64t w23 = pack2(w.z, w.w);
#pragma unroll
            for (int q = 0; q < 8; ++q) {
                float4 v = ins4[q * (K / 4) + k4];
                ffma2(acc[q], w01, pack2(v.x, v.y));
                ffma2(acc[q], w23, pack2(v.z, v.w));
            }
        }
#pragma unroll
        for (int q = 0; q < 8; ++q) {
            if (qbase + q < cnt) {
                float r = hsum2(acc[q]) + b;
                if (ACT == 1) r = (r >= 0.f) ? r : 0.01f * r;
                else if (ACT == 2) r = fmaxf(r, 0.f);
                else if (ACT == 3) r = (r > 0.f) ? r : expm1f(r);
                out[(size_t)(t0 + qbase + q) * Jtotal + jbase + j] = r;
            }
        }
        __syncthreads();
    }
}

// ---------------- dense3: N=384 GRU-gate GEMM, 512 threads, NT=32, FFMA2 ---
template <int EPI>
__global__ void __launch_bounds__(512) dense3_kernel(
    const float* __restrict__ A, const float* __restrict__ W,
    const float* __restrict__ bias, float* __restrict__ out,
    const float* __restrict__ gi, int n)
{
    constexpr int K = 128, KP = 132, NT = 32;
    extern __shared__ float sm[];
    float* Ws  = sm;                 // 384 * KP
    float* ins = sm + 384 * KP;      // NT * K
    const int tid = threadIdx.x;
    const int j = tid & 127;
    const int qbase = (tid >> 7) * 8;   // 0, 8, 16, 24

    for (int idx = tid; idx < 384 * K; idx += 512) {
        int r = idx >> 7, k = idx & 127;
        Ws[r * KP + k] = W[(size_t)r * K + k];
    }
    float b[3];
#pragma unroll
    for (int c = 0; c < 3; ++c) b[c] = bias[j + c * 128];

    const int stride = gridDim.x * NT;
    int t0 = blockIdx.x * NT;
    float4 pre[2];
    if (t0 < n) {
        int lim = min(NT, n - t0) * (K / 4);
#pragma unroll
        for (int i = 0; i < 2; ++i) {
            int idx = tid + i * 512;
            pre[i] = (idx < lim) ? ((const float4*)(A + (size_t)t0 * K))[idx]
                                 : make_float4(0.f, 0.f, 0.f, 0.f);
        }
    }
    __syncthreads();

    const float4* wrow[3];
#pragma unroll
    for (int c = 0; c < 3; ++c)
        wrow[c] = (const float4*)(Ws + (size_t)(c * 128 + j) * KP);

    for (; t0 < n; t0 += stride) {
        int cnt = min(NT, n - t0);
#pragma unroll
        for (int i = 0; i < 2; ++i)
            ((float4*)ins)[tid + i * 512] = pre[i];
        __syncthreads();
        int tn = t0 + stride;
        if (tn < n) {
            int lim = min(NT, n - tn) * (K / 4);
#pragma unroll
            for (int i = 0; i < 2; ++i) {
                int idx = tid + i * 512;
                pre[i] = (idx < lim) ? ((const float4*)(A + (size_t)tn * K))[idx]
                                     : make_float4(0.f, 0.f, 0.f, 0.f);
            }
        }
        u64t acc[3][8];
#pragma unroll
        for (int c = 0; c < 3; ++c)
#pragma unroll
            for (int q = 0; q < 8; ++q) acc[c][q] = 0ULL;

        const float4* ins4 = (const float4*)ins + qbase * (K / 4);
#pragma unroll 4
        for (int k4 = 0; k4 < K / 4; ++k4) {
            u64t w01[3], w23[3];
#pragma unroll
            for (int c = 0; c < 3; ++c) {
                float4 w = wrow[c][k4];
                w01[c] = pack2(w.x, w.y);
                w23[c] = pack2(w.z, w.w);
            }
#pragma unroll
            for (int q = 0; q < 8; ++q) {
                float4 v = ins4[q * (K / 4) + k4];
                u64t v01 = pack2(v.x, v.y);
                u64t v23 = pack2(v.z, v.w);
#pragma unroll
                for (int c = 0; c < 3; ++c) {
                    ffma2(acc[c][q], w01[c], v01);
                    ffma2(acc[c][q], w23[c], v23);
                }
            }
        }
        if (EPI == 0) {
#pragma unroll
            for (int q = 0; q < 8; ++q) {
                if (qbase + q < cnt) {
                    size_t node = t0 + qbase + q;
#pragma unroll
                    for (int c = 0; c < 3; ++c)
                        out[node * 384 + j + c * 128] = hsum2(acc[c][q]) + b[c];
                }
            }
        } else {
#pragma unroll
            for (int q = 0; q < 8; ++q) {
                if (qbase + q < cnt) {
                    size_t node = t0 + qbase + q;
                    float hr = hsum2(acc[0][q]) + b[0];
                    float hz = hsum2(acc[1][q]) + b[1];
                    float hn = hsum2(acc[2][q]) + b[2];
                    size_t gbase = node * 384 + j;
                    float r = sigm(gi[gbase] + hr);
                    float z = sigm(gi[gbase + 128] + hz);
                    float nng = tanhf(gi[gbase + 256] + r * hn);
                    float hv = ins[(qbase + q) * 128 + j];
                    out[node * 128 + j] = fmaxf((1.f - z) * nng + z * hv, 0.f);
                }
            }
        }
        __syncthreads();
    }
}

// ---------------- nd gather (CSR, prefetched) ----------------
__global__ void __launch_bounds__(256) nd_gather_kernel(
    const float* __restrict__ p, const float* __restrict__ ea,
    const int* __restrict__ src, const int* __restrict__ off,
    const int* __restrict__ eid, const float* __restrict__ w1,
    float* __restrict__ tsum)
{
    __shared__ float W1b[16 * 128];   // [k][j]
    const int tid = threadIdx.x;
    for (int idx = tid; idx < 16 * 128; idx += 256) {
        int k = idx >> 7, j = idx & 127;
        W1b[idx] = w1[j * 144 + 128 + k];
    }
    __syncthreads();
    int n = blockIdx.x * 8 + (tid >> 5);
    if (n >= NN) return;
    int lane = tid & 31;
    int beg = off[n], end = off[n + 1];
    float4 acc = make_float4(0.f, 0.f, 0.f, 0.f);
    const float4* W1b4 = (const float4*)W1b;
    const float4* p4 = (const float4*)p;
    if (beg < end) {
        int s = src[eid[beg]];
        int ed = eid[beg];
        for (int e = beg; e < end; ++e) {
            int s_cur = s, ed_cur = ed;
            if (e + 1 < end) {             // prefetch next edge's indices
                ed = eid[e + 1];
                s = src[ed];
            }
            float eav = (lane < 16) ? __ldg(&ea[(size_t)ed_cur * 16 + lane]) : 0.f;
            float4 t = p4[(size_t)s_cur * 32 + lane];
#pragma unroll
            for (int k = 0; k < 16; ++k) {
                float ek = __shfl_sync(0xFFFFFFFFu, eav, k);
                float4 w = W1b4[k * 32 + lane];
                t.x += ek * w.x; t.y += ek * w.y; t.z += ek * w.z; t.w += ek * w.w;
            }
            t.x = (t.x >= 0.f) ? t.x : 0.01f * t.x;
            t.y = (t.y >= 0.f) ? t.y : 0.01f * t.y;
            t.z = (t.z >= 0.f) ? t.z : 0.01f * t.z;
            t.w = (t.w >= 0.f) ? t.w : 0.01f * t.w;
            acc.x += t.x; acc.y += t.y; acc.z += t.z; acc.w += t.w;
        }
    }
    ((float4*)tsum)[(size_t)n * 32 + lane] = acc;
}

// ---------------- GAT attention dots ----------------
__global__ void attn_dots_kernel(const float* __restrict__ xp, const float* __restrict__ asrc,
                                 const float* __restrict__ adst, float* __restrict__ as_,
                                 float* __restrict__ ad_) {
    int n = (blockIdx.x * blockDim.x + threadIdx.x) >> 5;
    int lane = threadIdx.x & 31;
    if (n >= NN) return;
    float4 v = ((const float4*)xp)[(size_t)n * 32 + lane];
    float4 w1 = ((const float4*)asrc)[lane];
    float4 w2 = ((const float4*)adst)[lane];
    float sa = v.x * w1.x + v.y * w1.y + v.z * w1.z + v.w * w1.w;
    float sd = v.x * w2.x + v.y * w2.y + v.z * w2.z + v.w * w2.w;
#pragma unroll
    for (int o = 16; o; o >>= 1) {
        sa += __shfl_xor_sync(0xFFFFFFFFu, sa, o);
        sd += __shfl_xor_sync(0xFFFFFFFFu, sd, o);
    }
    if (lane == 0) { as_[n] = sa; ad_[n] = sd; }
}

// ---------------- GAT gather (CSR, online softmax, prefetched) -------------
__global__ void __launch_bounds__(256) gat_gather_kernel(
    const int* __restrict__ src, const int* __restrict__ off, const int* __restrict__ eid,
    const float* __restrict__ as_, const float* __restrict__ ad_,
    const float* __restrict__ xp, const float* __restrict__ bias,
    float* __restrict__ hout)
{
    int n = blockIdx.x * 8 + (threadIdx.x >> 5);
    if (n >= NN) return;
    int lane = threadIdx.x & 31;
    int beg = off[n], end = off[n + 1];
    float adn = ad_[n];
    float m = -INFINITY, den = 0.f;
    float4 acc = make_float4(0.f, 0.f, 0.f, 0.f);
    const float4* xp4 = (const float4*)xp;
    if (beg < end) {
        int s = src[eid[beg]];
        float av = __ldg(&as_[s]);
        for (int e = beg; e < end; ++e) {
            int s_cur = s; float a = av + adn;
            if (e + 1 < end) {            // prefetch next edge's scalar chain
                s = src[eid[e + 1]];
                av = __ldg(&as_[s]);
            }
            float4 v = xp4[(size_t)s_cur * 32 + lane];
            a = (a >= 0.f) ? a : 0.01f * a;
            if (a > m) {
                float f = __expf(m - a);
                den *= f;
                acc.x *= f; acc.y *= f; acc.z *= f; acc.w *= f;
                m = a;
            }
            float w = __expf(a - m);
            den += w;
            acc.x += w * v.x; acc.y += w * v.y; acc.z += w * v.z; acc.w += w * v.w;
        }
    }
    float inv = (den > 0.f) ? 1.f / den : 0.f;
    float4 b = ((const float4*)bias)[lane];
    float4 r;
    r.x = acc.x * inv + b.x; r.y = acc.y * inv + b.y;
    r.z = acc.z * inv + b.z; r.w = acc.w * inv + b.w;
    r.x = (r.x > 0.f) ? r.x : expm1f(r.x);
    r.y = (r.y > 0.f) ? r.y : expm1f(r.y);
    r.z = (r.z > 0.f) ? r.z : expm1f(r.z);
    r.w = (r.w > 0.f) ? r.w : expm1f(r.w);
    ((float4*)hout)[(size_t)n * 32 + lane] = r;
}

// ---------------- readout ----------------
__global__ void __launch_bounds__(128) graph_agg_kernel(const float* __restrict__ xcur,
                                                        const int* __restrict__ batch,
                                                        float* __restrict__ agg,
                                                        float* __restrict__ outv) {
    int g = blockIdx.x;
    int lo, hi;
    {
        int l = 0, r = NN;
        while (l < r) { int m = (l + r) >> 1; if (batch[m] < g) l = m + 1; else r = m; }
        lo = l;
    }
    {
        int l = lo, r = NN;
        while (l < r) { int m = (l + r) >> 1; if (batch[m] < g + 1) l = m + 1; else r = m; }
        hi = l;
    }
    float s = 0.f;
    for (int n = lo; n < hi; ++n) s += xcur[(size_t)n * 128 + threadIdx.x];
    agg[g * 128 + threadIdx.x] = s;
    outv[g * 128 + threadIdx.x] = fmaxf(s, 0.f);
}

__global__ void add_kernel(const float* __restrict__ a, const float* __restrict__ b,
                           float* __restrict__ c, int n) {
    int t = blockIdx.x * blockDim.x + threadIdx.x;
    if (t < n) c[t] = a[t] + b[t];
}

__global__ void lstm_combine_kernel(const float* __restrict__ gi, const float* __restrict__ gh,
                                    const float* __restrict__ hc, float* __restrict__ out) {
    int t = blockIdx.x * blockDim.x + threadIdx.x;
    if (t >= NG * 128) return;
    int g = t >> 7, j = t & 127;
    size_t base = (size_t)g * 512;
    float gI = gi[base + j]       + gh[base + j];
    float gF = gi[base + 128 + j] + gh[base + 128 + j];
    float gG = gi[base + 256 + j] + gh[base + 256 + j];
    float gO = gi[base + 384 + j] + gh[base + 384 + j];
    float c = hc[t];
    float c2 = sigm(gF) * c + sigm(gI) * tanhf(gG);
    out[t] = sigm(gO) * tanhf(c2);
}

__global__ void final_kernel(const float* __restrict__ outv, const float* __restrict__ w,
                             const float* __restrict__ b, float* __restrict__ res) {
    int g = (blockIdx.x * blockDim.x + threadIdx.x) >> 5;
    int lane = threadIdx.x & 31;
    if (g >= NG) return;
    float4 v = ((const float4*)outv)[(size_t)g * 32 + lane];
    float4 ww = ((const float4*)w)[lane];
    float s = v.x * ww.x + v.y * ww.y + v.z * ww.z + v.w * ww.w;
#pragma unroll
    for (int o = 16; o; o >>= 1) s += __shfl_xor_sync(0xFFFFFFFFu, s, o);
    if (lane == 0) res[g] = s + b[0];
}

// ---------------- host ----------------
#define SM_J1K64  ((128 * 68 + 16 * 64) * 4)
#define SM_J1K128 ((128 * 132 + 16 * 128) * 4)
#define SM_D1     ((128 * 132 + 16 * 128) * 4)
#define SM_D3     ((384 * 132 + 32 * 128) * 4)

extern "C" void kernel_launch(void* const* d_in, const int* in_sizes, int n_in,
                              void* d_out, int out_size) {
    const float* x        = (const float*)d_in[0];
    const int*   ei       = (const int*)  d_in[1];
    const float* ea       = (const float*)d_in[2];
    const int*   batch    = (const int*)  d_in[3];
    const float* lin1_w   = (const float*)d_in[4];
    const float* lin1_b   = (const float*)d_in[5];
    const float* nd_lin1w = (const float*)d_in[6];
    const float* nd_lin2w = (const float*)d_in[7];
    const float* nd_bias  = (const float*)d_in[8];
    const float* gru0_wih = (const float*)d_in[9];
    const float* gru0_whh = (const float*)d_in[10];
    const float* gru0_bih = (const float*)d_in[11];
    const float* gru0_bhh = (const float*)d_in[12];
    const float* gat_w    = (const float*)d_in[13];
    const float* gat_asrc = (const float*)d_in[14];
    const float* gat_adst = (const float*)d_in[15];
    const float* gat_b    = (const float*)d_in[16];
    const float* gru_wih  = (const float*)d_in[17];
    const float* gru_whh  = (const float*)d_in[18];
    const float* gru_bih  = (const float*)d_in[19];
    const float* gru_bhh  = (const float*)d_in[20];
    const float* gin_w    = (const float*)d_in[21];
    const float* gin_b    = (const float*)d_in[22];
    const float* lstm_wih = (const float*)d_in[23];
    const float* lstm_whh = (const float*)d_in[24];
    const float* lstm_bih = (const float*)d_in[25];
    const float* lstm_bhh = (const float*)d_in[26];
    const float* lin2_w   = (const float*)d_in[27];
    const float* lin2_b   = (const float*)d_in[28];
    float* out = (float*)d_out;

    const int* src = ei;
    const int* dst = ei + NE;

    float *px1, *pp, *ph, *pxc, *pgi, *pas, *pad;
    float *pagg, *pgout, *pghh, *pgtmp, *pggi, *pggh;
    int *pcnt, *poff, *ppos, *peid, *ppart;
    cudaGetSymbolAddress((void**)&px1, f_x1);
    cudaGetSymbolAddress((void**)&pp, f_p);
    cudaGetSymbolAddress((void**)&ph, f_h);
    cudaGetSymbolAddress((void**)&pxc, f_xcur);
    cudaGetSymbolAddress((void**)&pgi, f_gi);
    cudaGetSymbolAddress((void**)&pas, f_as);
    cudaGetSymbolAddress((void**)&pad, f_ad);
    cudaGetSymbolAddress((void**)&pagg, g_agg);
    cudaGetSymbolAddress((void**)&pgout, g_out);
    cudaGetSymbolAddress((void**)&pghh, g_hh);
    cudaGetSymbolAddress((void**)&pgtmp, g_tmp);
    cudaGetSymbolAddress((void**)&pggi, g_gi);
    cudaGetSymbolAddress((void**)&pggh, g_gh);
    cudaGetSymbolAddress((void**)&pcnt, c_cnt);
    cudaGetSymbolAddress((void**)&poff, c_off);
    cudaGetSymbolAddress((void**)&ppos, c_pos);
    cudaGetSymbolAddress((void**)&peid, c_eid);
    cudaGetSymbolAddress((void**)&ppart, c_part);

    cudaFuncSetAttribute((const void*)dense_kernel<64, 1>, cudaFuncAttributeMaxDynamicSharedMemorySize, SM_J1K64);
    cudaFuncSetAttribute((const void*)dense_kernel<128, 0>, cudaFuncAttributeMaxDynamicSharedMemorySize, SM_J1K128);
    cudaFuncSetAttribute((const void*)dense_kernel<128, 3>, cudaFuncAttributeMaxDynamicSharedMemorySize, SM_J1K128);
    cudaFuncSetAttribute((const void*)dense1_kernel<0>, cudaFuncAttributeMaxDynamicSharedMemorySize, SM_D1);
    cudaFuncSetAttribute((const void*)dense1_kernel<3>, cudaFuncAttributeMaxDynamicSharedMemorySize, SM_D1);
    cudaFuncSetAttribute((const void*)dense3_kernel<0>, cudaFuncAttributeMaxDynamicSharedMemorySize, SM_D3);
    cudaFuncSetAttribute((const void*)dense3_kernel<1>, cudaFuncAttributeMaxDynamicSharedMemorySize, SM_D3);

    const int GP1b = 592;  // dense K=64 (128 threads)
    const int GPD1 = 296;  // dense1: 2 CTAs/SM, 256 threads
    const int GP3 = 148;   // dense3: 1 CTA/SM, 512 threads, NT=32
    const int NPART = (NN + 1023) / 1024;   // 49
    const int tilesG = (NG + 15) / 16;
    const int ZB = 256;

    // launch order: index 3 (ncu capture slot) = dense1 p-GEMM
    // 0) x1 = leaky(x @ lin1_w.T + b)
    dense_kernel<64, 1><<<dim3(GP1b, 1), 128, SM_J1K64>>>(x, lin1_w, lin1_b, px1, NN, 128, 64);
    // 1-2) CSR phase A
    zero_i_kernel<<<(NN + ZB - 1) / ZB, ZB>>>(pcnt, NN);
    hist_kernel<<<(NE + ZB - 1) / ZB, ZB>>>(dst, pcnt);
    // 3) p = x1 @ W1a.T   <-- PROFILED
    dense1_kernel<0><<<dim3(GPD1, 1), 256, SM_D1>>>(px1, nd_lin1w, nullptr, pp, NN, 128, 144);
    // 4-7) CSR phase B
    scan_part_kernel<<<NPART, 256>>>(pcnt, ppart);
    scan_mid_kernel<<<1, 32>>>(ppart, NPART);
    scan_final_kernel<<<NPART, 256>>>(pcnt, ppart, poff, ppos);
    fill_kernel<<<(NE + ZB - 1) / ZB, ZB>>>(dst, ppos, peid);
    // tsum = segment_sum(leaky(p[src] + ea @ W1b.T))
    nd_gather_kernel<<<(NN + 7) / 8, 256>>>(pp, ea, src, poff, peid, nd_lin1w, pgi);
    // h = elu(tsum @ W2.T + nd_bias)
    dense1_kernel<3><<<dim3(GPD1, 1), 256, SM_D1>>>(pgi, nd_lin2w, nd_bias, ph, NN, 128, 128);
    // GRU0
    dense3_kernel<0><<<GP3, 512, SM_D3>>>(ph, gru0_wih, gru0_bih, pgi, nullptr, NN);
    dense3_kernel<1><<<GP3, 512, SM_D3>>>(px1, gru0_whh, gru0_bhh, pxc, pgi, NN);

    // GAT layers
    for (int l = 0; l < 2; ++l) {
        dense1_kernel<0><<<dim3(GPD1, 1), 256, SM_D1>>>(pxc, gat_w + (size_t)l * 128 * 128, nullptr, pp, NN, 128, 128);
        attn_dots_kernel<<<(NN * 32 + ZB - 1) / ZB, ZB>>>(pp, gat_asrc + l * 128, gat_adst + l * 128, pas, pad);
        gat_gather_kernel<<<(NN + 7) / 8, 256>>>(src, poff, peid, pas, pad, pp, gat_b + l * 128, ph);
        dense3_kernel<0><<<GP3, 512, SM_D3>>>(ph, gru_wih + (size_t)l * 384 * 128, gru_bih + l * 384, pgi, nullptr, NN);
        dense3_kernel<1><<<GP3, 512, SM_D3>>>(pxc, gru_whh + (size_t)l * 384 * 128, gru_bhh + l * 384, pxc, pgi, NN);
    }

    // readout
    graph_agg_kernel<<<NG, 128>>>(pxc, batch, pagg, pgout);
    for (int t = 0; t < 2; ++t) {
        add_kernel<<<(NG * 128 + ZB - 1) / ZB, ZB>>>(pgout, pagg, pgtmp, NG * 128);
        dense_kernel<128, 3><<<dim3(tilesG, 1), 128, SM_J1K128>>>(pgtmp, gin_w, gin_b, pghh, NG, 128, 128);
        dense_kernel<128, 0><<<dim3(tilesG, 4), 128, SM_J1K128>>>(pgout, lstm_wih, lstm_bih, pggi, NG, 512, 128);
        dense_kernel<128, 0><<<dim3(tilesG, 4), 128, SM_J1K128>>>(pghh, lstm_whh, lstm_bhh, pggh, NG, 512, 128);
        lstm_combine_kernel<<<(NG * 128 + ZB - 1) / ZB, ZB>>>(pggi, pggh, pghh, pgout);
    }
    final_kernel<<<(NG * 32 + 127) / 128, 128>>>(pgout, lin2_w, lin2_b, out);
}

// round 8
// speedup vs baseline: 2.4543x; 1.0356x over previous
#include <cuda_runtime.h>
#include <math.h>

#define NN 50000
#define NE 500000
#define NG 2000

typedef unsigned long long u64t;

// ---------------- scratch (device globals) ----------------
__device__ float f_x1  [NN * 128];
__device__ float f_p   [NN * 128];
__device__ float f_h   [NN * 128];
__device__ float f_xcur[NN * 128];
__device__ float f_gi  [NN * 3 * 128];  // also reused as tsum (first NN*128)
__device__ float f_as  [NN];
__device__ float f_ad  [NN];
__device__ float g_agg [NG * 128];
__device__ float g_out [NG * 128];
__device__ float g_hh  [NG * 128];
__device__ float g_tmp [NG * 128];
__device__ float g_gi  [NG * 4 * 128];
__device__ float g_gh  [NG * 4 * 128];
// CSR
__device__ int c_cnt[NN];
__device__ int c_off[NN + 1];
__device__ int c_pos[NN];
__device__ int c_eid[NE];
__device__ int c_part[64];

__device__ __forceinline__ float sigm(float x) { return 1.0f / (1.0f + expf(-x)); }

__device__ __forceinline__ void ffma2(u64t& d, u64t a, u64t b) {
    asm("fma.rn.f32x2 %0, %1, %2, %0;" : "+l"(d) : "l"(a), "l"(b));
}
__device__ __forceinline__ u64t pack2(float lo, float hi) {
    u64t r;
    asm("mov.b64 %0, {%1, %2};" : "=l"(r) : "f"(lo), "f"(hi));
    return r;
}
__device__ __forceinline__ float hsum2(u64t v) {
    float lo, hi;
    asm("mov.b64 {%0, %1}, %2;" : "=f"(lo), "=f"(hi) : "l"(v));
    return lo + hi;
}
__device__ __forceinline__ void cp_async16(void* smem_dst, const void* gmem_src) {
    unsigned sa = (unsigned)__cvta_generic_to_shared(smem_dst);
    asm volatile("cp.async.ca.shared.global [%0], [%1], 16;" :: "r"(sa), "l"(gmem_src));
}
__device__ __forceinline__ void cp_async_wait_all() {
    asm volatile("cp.async.commit_group;");
    asm volatile("cp.async.wait_group 0;");
}

// ---------------- CSR build ----------------
__global__ void zero_i_kernel(int* p, int n) {
    int t = blockIdx.x * blockDim.x + threadIdx.x;
    if (t < n) p[t] = 0;
}
__global__ void hist_kernel(const int* __restrict__ dst, int* __restrict__ cnt) {
    int e = blockIdx.x * blockDim.x + threadIdx.x;
    if (e < NE) atomicAdd(&cnt[dst[e]], 1);
}
__global__ void __launch_bounds__(256) scan_part_kernel(const int* __restrict__ cnt,
                                                        int* __restrict__ part) {
    __shared__ int sm[256];
    int base = blockIdx.x * 1024;
    int s = 0;
    for (int i = threadIdx.x; i < 1024; i += 256) {
        int idx = base + i;
        s += (idx < NN) ? cnt[idx] : 0;
    }
    sm[threadIdx.x] = s;
    __syncthreads();
    for (int d = 128; d; d >>= 1) {
        if (threadIdx.x < d) sm[threadIdx.x] += sm[threadIdx.x + d];
        __syncthreads();
    }
    if (threadIdx.x == 0) part[blockIdx.x] = sm[0];
}
__global__ void scan_mid_kernel(int* part, int npart) {
    if (threadIdx.x == 0) {
        int run = 0;
        for (int i = 0; i < npart; ++i) { int v = part[i]; part[i] = run; run += v; }
    }
}
__global__ void __launch_bounds__(256) scan_final_kernel(const int* __restrict__ cnt,
                                                         const int* __restrict__ part,
                                                         int* __restrict__ off,
                                                         int* __restrict__ pos) {
    __shared__ int wsum[8];
    int base = blockIdx.x * 1024;
    int lane = threadIdx.x & 31, wid = threadIdx.x >> 5;
    int v[4]; int s = 0;
    int i0 = base + threadIdx.x * 4;
#pragma unroll
    for (int i = 0; i < 4; ++i) {
        int idx = i0 + i;
        v[i] = (idx < NN) ? cnt[idx] : 0;
        s += v[i];
    }
    int ps = s;
#pragma unroll
    for (int o = 1; o < 32; o <<= 1) {
        int t = __shfl_up_sync(0xFFFFFFFFu, ps, o);
        if (lane >= o) ps += t;
    }
    if (lane == 31) wsum[wid] = ps;
    __syncthreads();
    if (threadIdx.x == 0) {
        int run = 0;
#pragma unroll
        for (int w = 0; w < 8; ++w) { int t = wsum[w]; wsum[w] = run; run += t; }
    }
    __syncthreads();
    int excl = ps - s + wsum[wid] + part[blockIdx.x];
#pragma unroll
    for (int i = 0; i < 4; ++i) {
        int idx = i0 + i;
        if (idx < NN) { off[idx] = excl; pos[idx] = excl; }
        excl += v[i];
    }
    if (blockIdx.x == 0 && threadIdx.x == 0) off[NN] = NE;
}
__global__ void fill_kernel(const int* __restrict__ dst, int* __restrict__ pos,
                            int* __restrict__ eid) {
    int e = blockIdx.x * blockDim.x + threadIdx.x;
    if (e < NE) {
        int idx = atomicAdd(&pos[dst[e]], 1);
        eid[idx] = e;
    }
}

// ---------------- dense GEMM JPT=1 generic (K=64 + graph-level) -----------
template <int K, int ACT>
__global__ void __launch_bounds__(128) dense_kernel(
    const float* __restrict__ A, const float* __restrict__ W,
    const float* __restrict__ bias, float* __restrict__ out,
    int n, int Jtotal, int wstride)
{
    constexpr int KP = K + 4;
    constexpr int NT = 16;
    constexpr int NPRE = NT * K / 512;
    extern __shared__ float sm[];
    float* Ws  = sm;              // 128 * KP
    float* ins = sm + 128 * KP;   // NT * K
    const int tid = threadIdx.x;
    const int jbase = blockIdx.y * 128;

    for (int idx = tid; idx < 128 * K; idx += 128) {
        int r = idx / K, k = idx - r * K;
        Ws[r * KP + k] = W[(size_t)(jbase + r) * wstride + k];
    }
    float b = bias ? bias[jbase + tid] : 0.0f;

    const int stride = gridDim.x * NT;
    int t0 = blockIdx.x * NT;
    float4 pre[NPRE];
    if (t0 < n) {
        int lim = min(NT, n - t0) * (K / 4);
#pragma unroll
        for (int i = 0; i < NPRE; ++i) {
            int idx = tid + i * 128;
            pre[i] = (idx < lim) ? ((const float4*)(A + (size_t)t0 * K))[idx]
                                 : make_float4(0.f, 0.f, 0.f, 0.f);
        }
    }
    __syncthreads();

    const float4* wrow = (const float4*)(Ws + (size_t)tid * KP);

    for (; t0 < n; t0 += stride) {
        int cnt = min(NT, n - t0);
#pragma unroll
        for (int i = 0; i < NPRE; ++i)
            ((float4*)ins)[tid + i * 128] = pre[i];
        __syncthreads();
        int tn = t0 + stride;
        if (tn < n) {
            int lim = min(NT, n - tn) * (K / 4);
#pragma unroll
            for (int i = 0; i < NPRE; ++i) {
                int idx = tid + i * 128;
                pre[i] = (idx < lim) ? ((const float4*)(A + (size_t)tn * K))[idx]
                                     : make_float4(0.f, 0.f, 0.f, 0.f);
            }
        }
        float acc[NT];
#pragma unroll
        for (int q = 0; q < NT; ++q) acc[q] = 0.f;

        const float4* ins4 = (const float4*)ins;
#pragma unroll 4
        for (int k4 = 0; k4 < K / 4; ++k4) {
            float4 w = wrow[k4];
#pragma unroll
            for (int q = 0; q < NT; ++q) {
                float4 v = ins4[q * (K / 4) + k4];
                acc[q] += w.x * v.x + w.y * v.y + w.z * v.z + w.w * v.w;
            }
        }
        for (int q = 0; q < cnt; ++q) {
            float r = acc[q] + b;
            if (ACT == 1) r = (r >= 0.f) ? r : 0.01f * r;
            else if (ACT == 2) r = fmaxf(r, 0.f);
            else if (ACT == 3) r = (r > 0.f) ? r : expm1f(r);
            out[(size_t)(t0 + q) * Jtotal + jbase + tid] = r;
        }
        __syncthreads();
    }
}

// ---------------- dense1: K=128 J=128 GEMM, JPT=4 x Q=8, NT=64, FFMA2 ------
// thread owns j = (tid&31) + 32c (c=0..3) and nodes qbase..qbase+7
template <int ACT>
__global__ void __launch_bounds__(256, 2) dense1_kernel(
    const float* __restrict__ A, const float* __restrict__ W,
    const float* __restrict__ bias, float* __restrict__ out,
    int n, int Jtotal, int wstride)
{
    constexpr int K = 128, KP = 132, NT = 64;
    extern __shared__ float sm[];
    float* Ws  = sm;                 // 128 * KP  (67.6 KB)
    float* ins = sm + 128 * KP;      // 64 * 128  (32 KB)
    const int tid = threadIdx.x;
    const int jc = tid & 31;
    const int qbase = (tid >> 5) * 8;   // 0..56
    const int jbase = blockIdx.y * 128;

    for (int idx = tid; idx < 128 * K; idx += 256) {
        int r = idx >> 7, k = idx & 127;
        Ws[r * KP + k] = W[(size_t)(jbase + r) * wstride + k];
    }
    float b[4];
#pragma unroll
    for (int c = 0; c < 4; ++c)
        b[c] = bias ? bias[jbase + jc + c * 32] : 0.0f;

    const float4* wrow[4];
#pragma unroll
    for (int c = 0; c < 4; ++c)
        wrow[c] = (const float4*)(Ws + (size_t)(jc + c * 32) * KP);

    const int stride = gridDim.x * NT;
    __syncthreads();

    for (int t0 = blockIdx.x * NT; t0 < n; t0 += stride) {
        int cnt = min(NT, n - t0);
        int lim = cnt * (K / 4);
        const float4* Ap = (const float4*)(A + (size_t)t0 * K);
        float4* ins4w = (float4*)ins;
#pragma unroll
        for (int i = 0; i < 8; ++i) {
            int idx = tid + i * 256;
            if (idx < lim) cp_async16(ins4w + idx, Ap + idx);
            else ins4w[idx] = make_float4(0.f, 0.f, 0.f, 0.f);
        }
        cp_async_wait_all();
        __syncthreads();

        u64t acc[4][8];
#pragma unroll
        for (int c = 0; c < 4; ++c)
#pragma unroll
            for (int q = 0; q < 8; ++q) acc[c][q] = 0ULL;

        const float4* ins4 = (const float4*)ins + qbase * (K / 4);
#pragma unroll 2
        for (int k4 = 0; k4 < K / 4; ++k4) {
            u64t w01[4], w23[4];
#pragma unroll
            for (int c = 0; c < 4; ++c) {
                float4 w = wrow[c][k4];
                w01[c] = pack2(w.x, w.y);
                w23[c] = pack2(w.z, w.w);
            }
#pragma unroll
            for (int q = 0; q < 8; ++q) {
                float4 v = ins4[q * (K / 4) + k4];
                u64t v01 = pack2(v.x, v.y);
                u64t v23 = pack2(v.z, v.w);
#pragma unroll
                for (int c = 0; c < 4; ++c) {
                    ffma2(acc[c][q], w01[c], v01);
                    ffma2(acc[c][q], w23[c], v23);
                }
            }
        }
#pragma unroll
        for (int q = 0; q < 8; ++q) {
            if (qbase + q < cnt) {
                size_t row = (size_t)(t0 + qbase + q) * Jtotal + jbase;
#pragma unroll
                for (int c = 0; c < 4; ++c) {
                    float r = hsum2(acc[c][q]) + b[c];
                    if (ACT == 1) r = (r >= 0.f) ? r : 0.01f * r;
                    else if (ACT == 2) r = fmaxf(r, 0.f);
                    else if (ACT == 3) r = (r > 0.f) ? r : expm1f(r);
                    out[row + jc + c * 32] = r;
                }
            }
        }
        __syncthreads();
    }
}

// ---------------- dense3: N=384 GRU-gate GEMM, 512 threads, NT=32, FFMA2 ---
template <int EPI>
__global__ void __launch_bounds__(512) dense3_kernel(
    const float* __restrict__ A, const float* __restrict__ W,
    const float* __restrict__ bias, float* __restrict__ out,
    const float* __restrict__ gi, int n)
{
    constexpr int K = 128, KP = 132, NT = 32;
    extern __shared__ float sm[];
    float* Ws  = sm;                 // 384 * KP
    float* ins = sm + 384 * KP;      // NT * K
    const int tid = threadIdx.x;
    const int j = tid & 127;
    const int qbase = (tid >> 7) * 8;   // 0, 8, 16, 24

    for (int idx = tid; idx < 384 * K; idx += 512) {
        int r = idx >> 7, k = idx & 127;
        Ws[r * KP + k] = W[(size_t)r * K + k];
    }
    float b[3];
#pragma unroll
    for (int c = 0; c < 3; ++c) b[c] = bias[j + c * 128];

    const int stride = gridDim.x * NT;
    int t0 = blockIdx.x * NT;
    float4 pre[2];
    if (t0 < n) {
        int lim = min(NT, n - t0) * (K / 4);
#pragma unroll
        for (int i = 0; i < 2; ++i) {
            int idx = tid + i * 512;
            pre[i] = (idx < lim) ? ((const float4*)(A + (size_t)t0 * K))[idx]
                                 : make_float4(0.f, 0.f, 0.f, 0.f);
        }
    }
    __syncthreads();

    const float4* wrow[3];
#pragma unroll
    for (int c = 0; c < 3; ++c)
        wrow[c] = (const float4*)(Ws + (size_t)(c * 128 + j) * KP);

    for (; t0 < n; t0 += stride) {
        int cnt = min(NT, n - t0);
#pragma unroll
        for (int i = 0; i < 2; ++i)
            ((float4*)ins)[tid + i * 512] = pre[i];
        __syncthreads();
        int tn = t0 + stride;
        if (tn < n) {
            int lim = min(NT, n - tn) * (K / 4);
#pragma unroll
            for (int i = 0; i < 2; ++i) {
                int idx = tid + i * 512;
                pre[i] = (idx < lim) ? ((const float4*)(A + (size_t)tn * K))[idx]
                                     : make_float4(0.f, 0.f, 0.f, 0.f);
            }
        }
        u64t acc[3][8];
#pragma unroll
        for (int c = 0; c < 3; ++c)
#pragma unroll
            for (int q = 0; q < 8; ++q) acc[c][q] = 0ULL;

        const float4* ins4 = (const float4*)ins + qbase * (K / 4);
#pragma unroll 4
        for (int k4 = 0; k4 < K / 4; ++k4) {
            u64t w01[3], w23[3];
#pragma unroll
            for (int c = 0; c < 3; ++c) {
                float4 w = wrow[c][k4];
                w01[c] = pack2(w.x, w.y);
                w23[c] = pack2(w.z, w.w);
            }
#pragma unroll
            for (int q = 0; q < 8; ++q) {
                float4 v = ins4[q * (K / 4) + k4];
                u64t v01 = pack2(v.x, v.y);
                u64t v23 = pack2(v.z, v.w);
#pragma unroll
                for (int c = 0; c < 3; ++c) {
                    ffma2(acc[c][q], w01[c], v01);
                    ffma2(acc[c][q], w23[c], v23);
                }
            }
        }
        if (EPI == 0) {
#pragma unroll
            for (int q = 0; q < 8; ++q) {
                if (qbase + q < cnt) {
                    size_t node = t0 + qbase + q;
#pragma unroll
                    for (int c = 0; c < 3; ++c)
                        out[node * 384 + j + c * 128] = hsum2(acc[c][q]) + b[c];
                }
            }
        } else {
#pragma unroll
            for (int q = 0; q < 8; ++q) {
                if (qbase + q < cnt) {
                    size_t node = t0 + qbase + q;
                    float hr = hsum2(acc[0][q]) + b[0];
                    float hz = hsum2(acc[1][q]) + b[1];
                    float hn = hsum2(acc[2][q]) + b[2];
                    size_t gbase = node * 384 + j;
                    float r = sigm(gi[gbase] + hr);
                    float z = sigm(gi[gbase + 128] + hz);
                    float nng = tanhf(gi[gbase + 256] + r * hn);
                    float hv = ins[(qbase + q) * 128 + j];
                    out[node * 128 + j] = fmaxf((1.f - z) * nng + z * hv, 0.f);
                }
            }
        }
        __syncthreads();
    }
}

// ---------------- nd gather (CSR, prefetched) ----------------
__global__ void __launch_bounds__(256) nd_gather_kernel(
    const float* __restrict__ p, const float* __restrict__ ea,
    const int* __restrict__ src, const int* __restrict__ off,
    const int* __restrict__ eid, const float* __restrict__ w1,
    float* __restrict__ tsum)
{
    __shared__ float W1b[16 * 128];   // [k][j]
    const int tid = threadIdx.x;
    for (int idx = tid; idx < 16 * 128; idx += 256) {
        int k = idx >> 7, j = idx & 127;
        W1b[idx] = w1[j * 144 + 128 + k];
    }
    __syncthreads();
    int n = blockIdx.x * 8 + (tid >> 5);
    if (n >= NN) return;
    int lane = tid & 31;
    int beg = off[n], end = off[n + 1];
    float4 acc = make_float4(0.f, 0.f, 0.f, 0.f);
    const float4* W1b4 = (const float4*)W1b;
    const float4* p4 = (const float4*)p;
    if (beg < end) {
        int ed = eid[beg];
        int s = src[ed];
        for (int e = beg; e < end; ++e) {
            int s_cur = s, ed_cur = ed;
            if (e + 1 < end) {
                ed = eid[e + 1];
                s = src[ed];
            }
            float eav = (lane < 16) ? __ldg(&ea[(size_t)ed_cur * 16 + lane]) : 0.f;
            float4 t = p4[(size_t)s_cur * 32 + lane];
#pragma unroll
            for (int k = 0; k < 16; ++k) {
                float ek = __shfl_sync(0xFFFFFFFFu, eav, k);
                float4 w = W1b4[k * 32 + lane];
                t.x += ek * w.x; t.y += ek * w.y; t.z += ek * w.z; t.w += ek * w.w;
            }
            t.x = (t.x >= 0.f) ? t.x : 0.01f * t.x;
            t.y = (t.y >= 0.f) ? t.y : 0.01f * t.y;
            t.z = (t.z >= 0.f) ? t.z : 0.01f * t.z;
            t.w = (t.w >= 0.f) ? t.w : 0.01f * t.w;
            acc.x += t.x; acc.y += t.y; acc.z += t.z; acc.w += t.w;
        }
    }
    ((float4*)tsum)[(size_t)n * 32 + lane] = acc;
}

// ---------------- GAT attention dots ----------------
__global__ void attn_dots_kernel(const float* __restrict__ xp, const float* __restrict__ asrc,
                                 const float* __restrict__ adst, float* __restrict__ as_,
                                 float* __restrict__ ad_) {
    int n = (blockIdx.x * blockDim.x + threadIdx.x) >> 5;
    int lane = threadIdx.x & 31;
    if (n >= NN) return;
    float4 v = ((const float4*)xp)[(size_t)n * 32 + lane];
    float4 w1 = ((const float4*)asrc)[lane];
    float4 w2 = ((const float4*)adst)[lane];
    float sa = v.x * w1.x + v.y * w1.y + v.z * w1.z + v.w * w1.w;
    float sd = v.x * w2.x + v.y * w2.y + v.z * w2.z + v.w * w2.w;
#pragma unroll
    for (int o = 16; o; o >>= 1) {
        sa += __shfl_xor_sync(0xFFFFFFFFu, sa, o);
        sd += __shfl_xor_sync(0xFFFFFFFFu, sd, o);
    }
    if (lane == 0) { as_[n] = sa; ad_[n] = sd; }
}

// ---------------- GAT gather (CSR, online softmax, prefetched) -------------
__global__ void __launch_bounds__(256) gat_gather_kernel(
    const int* __restrict__ src, const int* __restrict__ off, const int* __restrict__ eid,
    const float* __restrict__ as_, const float* __restrict__ ad_,
    const float* __restrict__ xp, const float* __restrict__ bias,
    float* __restrict__ hout)
{
    int n = blockIdx.x * 8 + (threadIdx.x >> 5);
    if (n >= NN) return;
    int lane = threadIdx.x & 31;
    int beg = off[n], end = off[n + 1];
    float adn = ad_[n];
    float m = -INFINITY, den = 0.f;
    float4 acc = make_float4(0.f, 0.f, 0.f, 0.f);
    const float4* xp4 = (const float4*)xp;
    if (beg < end) {
        int s = src[eid[beg]];
        float av = __ldg(&as_[s]);
        for (int e = beg; e < end; ++e) {
            int s_cur = s; float a = av + adn;
            if (e + 1 < end) {
                s = src[eid[e + 1]];
                av = __ldg(&as_[s]);
            }
            float4 v = xp4[(size_t)s_cur * 32 + lane];
            a = (a >= 0.f) ? a : 0.01f * a;
            if (a > m) {
                float f = __expf(m - a);
                den *= f;
                acc.x *= f; acc.y *= f; acc.z *= f; acc.w *= f;
                m = a;
            }
            float w = __expf(a - m);
            den += w;
            acc.x += w * v.x; acc.y += w * v.y; acc.z += w * v.z; acc.w += w * v.w;
        }
    }
    float inv = (den > 0.f) ? 1.f / den : 0.f;
    float4 b = ((const float4*)bias)[lane];
    float4 r;
    r.x = acc.x * inv + b.x; r.y = acc.y * inv + b.y;
    r.z = acc.z * inv + b.z; r.w = acc.w * inv + b.w;
    r.x = (r.x > 0.f) ? r.x : expm1f(r.x);
    r.y = (r.y > 0.f) ? r.y : expm1f(r.y);
    r.z = (r.z > 0.f) ? r.z : expm1f(r.z);
    r.w = (r.w > 0.f) ? r.w : expm1f(r.w);
    ((float4*)hout)[(size_t)n * 32 + lane] = r;
}

// ---------------- readout ----------------
__global__ void __launch_bounds__(128) graph_agg_kernel(const float* __restrict__ xcur,
                                                        const int* __restrict__ batch,
                                                        float* __restrict__ agg,
                                                        float* __restrict__ outv) {
    int g = blockIdx.x;
    int lo, hi;
    {
        int l = 0, r = NN;
        while (l < r) { int m = (l + r) >> 1; if (batch[m] < g) l = m + 1; else r = m; }
        lo = l;
    }
    {
        int l = lo, r = NN;
        while (l < r) { int m = (l + r) >> 1; if (batch[m] < g + 1) l = m + 1; else r = m; }
        hi = l;
    }
    float s = 0.f;
    for (int n = lo; n < hi; ++n) s += xcur[(size_t)n * 128 + threadIdx.x];
    agg[g * 128 + threadIdx.x] = s;
    outv[g * 128 + threadIdx.x] = fmaxf(s, 0.f);
}

__global__ void add_kernel(const float* __restrict__ a, const float* __restrict__ b,
                           float* __restrict__ c, int n) {
    int t = blockIdx.x * blockDim.x + threadIdx.x;
    if (t < n) c[t] = a[t] + b[t];
}

__global__ void lstm_combine_kernel(const float* __restrict__ gi, const float* __restrict__ gh,
                                    const float* __restrict__ hc, float* __restrict__ out) {
    int t = blockIdx.x * blockDim.x + threadIdx.x;
    if (t >= NG * 128) return;
    int g = t >> 7, j = t & 127;
    size_t base = (size_t)g * 512;
    float gI = gi[base + j]       + gh[base + j];
    float gF = gi[base + 128 + j] + gh[base + 128 + j];
    float gG = gi[base + 256 + j] + gh[base + 256 + j];
    float gO = gi[base + 384 + j] + gh[base + 384 + j];
    float c = hc[t];
    float c2 = sigm(gF) * c + sigm(gI) * tanhf(gG);
    out[t] = sigm(gO) * tanhf(c2);
}

__global__ void final_kernel(const float* __restrict__ outv, const float* __restrict__ w,
                             const float* __restrict__ b, float* __restrict__ res) {
    int g = (blockIdx.x * blockDim.x + threadIdx.x) >> 5;
    int lane = threadIdx.x & 31;
    if (g >= NG) return;
    float4 v = ((const float4*)outv)[(size_t)g * 32 + lane];
    float4 ww = ((const float4*)w)[lane];
    float s = v.x * ww.x + v.y * ww.y + v.z * ww.z + v.w * ww.w;
#pragma unroll
    for (int o = 16; o; o >>= 1) s += __shfl_xor_sync(0xFFFFFFFFu, s, o);
    if (lane == 0) res[g] = s + b[0];
}

// ---------------- host ----------------
#define SM_J1K64  ((128 * 68 + 16 * 64) * 4)
#define SM_J1K128 ((128 * 132 + 16 * 128) * 4)
#define SM_D1     ((128 * 132 + 64 * 128) * 4)
#define SM_D3     ((384 * 132 + 32 * 128) * 4)

extern "C" void kernel_launch(void* const* d_in, const int* in_sizes, int n_in,
                              void* d_out, int out_size) {
    const float* x        = (const float*)d_in[0];
    const int*   ei       = (const int*)  d_in[1];
    const float* ea       = (const float*)d_in[2];
    const int*   batch    = (const int*)  d_in[3];
    const float* lin1_w   = (const float*)d_in[4];
    const float* lin1_b   = (const float*)d_in[5];
    const float* nd_lin1w = (const float*)d_in[6];
    const float* nd_lin2w = (const float*)d_in[7];
    const float* nd_bias  = (const float*)d_in[8];
    const float* gru0_wih = (const float*)d_in[9];
    const float* gru0_whh = (const float*)d_in[10];
    const float* gru0_bih = (const float*)d_in[11];
    const float* gru0_bhh = (const float*)d_in[12];
    const float* gat_w    = (const float*)d_in[13];
    const float* gat_asrc = (const float*)d_in[14];
    const float* gat_adst = (const float*)d_in[15];
    const float* gat_b    = (const float*)d_in[16];
    const float* gru_wih  = (const float*)d_in[17];
    const float* gru_whh  = (const float*)d_in[18];
    const float* gru_bih  = (const float*)d_in[19];
    const float* gru_bhh  = (const float*)d_in[20];
    const float* gin_w    = (const float*)d_in[21];
    const float* gin_b    = (const float*)d_in[22];
    const float* lstm_wih = (const float*)d_in[23];
    const float* lstm_whh = (const float*)d_in[24];
    const float* lstm_bih = (const float*)d_in[25];
    const float* lstm_bhh = (const float*)d_in[26];
    const float* lin2_w   = (const float*)d_in[27];
    const float* lin2_b   = (const float*)d_in[28];
    float* out = (float*)d_out;

    const int* src = ei;
    const int* dst = ei + NE;

    float *px1, *pp, *ph, *pxc, *pgi, *pas, *pad;
    float *pagg, *pgout, *pghh, *pgtmp, *pggi, *pggh;
    int *pcnt, *poff, *ppos, *peid, *ppart;
    cudaGetSymbolAddress((void**)&px1, f_x1);
    cudaGetSymbolAddress((void**)&pp, f_p);
    cudaGetSymbolAddress((void**)&ph, f_h);
    cudaGetSymbolAddress((void**)&pxc, f_xcur);
    cudaGetSymbolAddress((void**)&pgi, f_gi);
    cudaGetSymbolAddress((void**)&pas, f_as);
    cudaGetSymbolAddress((void**)&pad, f_ad);
    cudaGetSymbolAddress((void**)&pagg, g_agg);
    cudaGetSymbolAddress((void**)&pgout, g_out);
    cudaGetSymbolAddress((void**)&pghh, g_hh);
    cudaGetSymbolAddress((void**)&pgtmp, g_tmp);
    cudaGetSymbolAddress((void**)&pggi, g_gi);
    cudaGetSymbolAddress((void**)&pggh, g_gh);
    cudaGetSymbolAddress((void**)&pcnt, c_cnt);
    cudaGetSymbolAddress((void**)&poff, c_off);
    cudaGetSymbolAddress((void**)&ppos, c_pos);
    cudaGetSymbolAddress((void**)&peid, c_eid);
    cudaGetSymbolAddress((void**)&ppart, c_part);

    cudaFuncSetAttribute((const void*)dense_kernel<64, 1>, cudaFuncAttributeMaxDynamicSharedMemorySize, SM_J1K64);
    cudaFuncSetAttribute((const void*)dense_kernel<128, 0>, cudaFuncAttributeMaxDynamicSharedMemorySize, SM_J1K128);
    cudaFuncSetAttribute((const void*)dense_kernel<128, 3>, cudaFuncAttributeMaxDynamicSharedMemorySize, SM_J1K128);
    cudaFuncSetAttribute((const void*)dense1_kernel<0>, cudaFuncAttributeMaxDynamicSharedMemorySize, SM_D1);
    cudaFuncSetAttribute((const void*)dense1_kernel<3>, cudaFuncAttributeMaxDynamicSharedMemorySize, SM_D1);
    cudaFuncSetAttribute((const void*)dense3_kernel<0>, cudaFuncAttributeMaxDynamicSharedMemorySize, SM_D3);
    cudaFuncSetAttribute((const void*)dense3_kernel<1>, cudaFuncAttributeMaxDynamicSharedMemorySize, SM_D3);

    const int GP1b = 592;  // dense K=64 (128 threads)
    const int GPD1 = 296;  // dense1: 2 CTAs/SM, 256 threads, NT=64
    const int GP3 = 148;   // dense3: 1 CTA/SM, 512 threads, NT=32
    const int NPART = (NN + 1023) / 1024;   // 49
    const int tilesG = (NG + 15) / 16;
    const int ZB = 256;

    // launch order: index 3 (ncu capture slot) = dense1 p-GEMM
    // 0) x1 = leaky(x @ lin1_w.T + b)
    dense_kernel<64, 1><<<dim3(GP1b, 1), 128, SM_J1K64>>>(x, lin1_w, lin1_b, px1, NN, 128, 64);
    // 1-2) CSR phase A
    zero_i_kernel<<<(NN + ZB - 1) / ZB, ZB>>>(pcnt, NN);
    hist_kernel<<<(NE + ZB - 1) / ZB, ZB>>>(dst, pcnt);
    // 3) p = x1 @ W1a.T   <-- PROFILED
    dense1_kernel<0><<<dim3(GPD1, 1), 256, SM_D1>>>(px1, nd_lin1w, nullptr, pp, NN, 128, 144);
    // 4-7) CSR phase B
    scan_part_kernel<<<NPART, 256>>>(pcnt, ppart);
    scan_mid_kernel<<<1, 32>>>(ppart, NPART);
    scan_final_kernel<<<NPART, 256>>>(pcnt, ppart, poff, ppos);
    fill_kernel<<<(NE + ZB - 1) / ZB, ZB>>>(dst, ppos, peid);
    // tsum = segment_sum(leaky(p[src] + ea @ W1b.T))
    nd_gather_kernel<<<(NN + 7) / 8, 256>>>(pp, ea, src, poff, peid, nd_lin1w, pgi);
    // h = elu(tsum @ W2.T + nd_bias)
    dense1_kernel<3><<<dim3(GPD1, 1), 256, SM_D1>>>(pgi, nd_lin2w, nd_bias, ph, NN, 128, 128);
    // GRU0
    dense3_kernel<0><<<GP3, 512, SM_D3>>>(ph, gru0_wih, gru0_bih, pgi, nullptr, NN);
    dense3_kernel<1><<<GP3, 512, SM_D3>>>(px1, gru0_whh, gru0_bhh, pxc, pgi, NN);

    // GAT layers
    for (int l = 0; l < 2; ++l) {
        dense1_kernel<0><<<dim3(GPD1, 1), 256, SM_D1>>>(pxc, gat_w + (size_t)l * 128 * 128, nullptr, pp, NN, 128, 128);
        attn_dots_kernel<<<(NN * 32 + ZB - 1) / ZB, ZB>>>(pp, gat_asrc + l * 128, gat_adst + l * 128, pas, pad);
        gat_gather_kernel<<<(NN + 7) / 8, 256>>>(src, poff, peid, pas, pad, pp, gat_b + l * 128, ph);
        dense3_kernel<0><<<GP3, 512, SM_D3>>>(ph, gru_wih + (size_t)l * 384 * 128, gru_bih + l * 384, pgi, nullptr, NN);
        dense3_kernel<1><<<GP3, 512, SM_D3>>>(pxc, gru_whh + (size_t)l * 384 * 128, gru_bhh + l * 384, pxc, pgi, NN);
    }

    // readout
    graph_agg_kernel<<<NG, 128>>>(pxc, batch, pagg, pgout);
    for (int t = 0; t < 2; ++t) {
        add_kernel<<<(NG * 128 + ZB - 1) / ZB, ZB>>>(pgout, pagg, pgtmp, NG * 128);
        dense_kernel<128, 3><<<dim3(tilesG, 1), 128, SM_J1K128>>>(pgtmp, gin_w, gin_b, pghh, NG, 128, 128);
        dense_kernel<128, 0><<<dim3(tilesG, 4), 128, SM_J1K128>>>(pgout, lstm_wih, lstm_bih, pggi, NG, 512, 128);
        dense_kernel<128, 0><<<dim3(tilesG, 4), 128, SM_J1K128>>>(pghh, lstm_whh, lstm_bhh, pggh, NG, 512, 128);
        lstm_combine_kernel<<<(NG * 128 + ZB - 1) / ZB, ZB>>>(pggi, pggh, pghh, pgout);
    }
    final_kernel<<<(NG * 32 + 127) / 128, 128>>>(pgout, lin2_w, lin2_b, out);
}

// round 9
// speedup vs baseline: 3.5636x; 1.4520x over previous
#include <cuda_runtime.h>
#include <cuda_bf16.h>
#include <math.h>

#define NN 50000
#define NE 500000
#define NG 2000

typedef unsigned long long u64t;

// ---------------- scratch (device globals) ----------------
__device__ float f_x1  [NN * 128];
__device__ float f_p   [NN * 128];
__device__ float f_h   [NN * 128];
__device__ float f_xcur[NN * 128];
__device__ float f_gi  [NN * 3 * 128];
__device__ float f_as  [NN];
__device__ float f_ad  [NN];
__device__ float g_agg [NG * 128];
__device__ float g_out [NG * 128];
__device__ float g_hh  [NG * 128];
__device__ float g_tmp [NG * 128];
__device__ float g_gi  [NG * 4 * 128];
__device__ float g_gh  [NG * 4 * 128];
__device__ int c_cnt[NN];
__device__ int c_off[NN + 1];
__device__ int c_pos[NN];
__device__ int c_eid[NE];
__device__ int c_part[64];

__device__ __forceinline__ float sigm(float x) { return 1.0f / (1.0f + expf(-x)); }

__device__ __forceinline__ void ffma2(u64t& d, u64t a, u64t b) {
    asm("fma.rn.f32x2 %0, %1, %2, %0;" : "+l"(d) : "l"(a), "l"(b));
}
__device__ __forceinline__ u64t pack2(float lo, float hi) {
    u64t r;
    asm("mov.b64 %0, {%1, %2};" : "=l"(r) : "f"(lo), "f"(hi));
    return r;
}
__device__ __forceinline__ float hsum2(u64t v) {
    float lo, hi;
    asm("mov.b64 {%0, %1}, %2;" : "=f"(lo), "=f"(hi) : "l"(v));
    return lo + hi;
}
__device__ __forceinline__ void cp_async16(void* smem_dst, const void* gmem_src) {
    unsigned sa = (unsigned)__cvta_generic_to_shared(smem_dst);
    asm volatile("cp.async.ca.shared.global [%0], [%1], 16;" :: "r"(sa), "l"(gmem_src));
}
__device__ __forceinline__ void cp_async_wait_all() {
    asm volatile("cp.async.commit_group;");
    asm volatile("cp.async.wait_group 0;");
}
__device__ __forceinline__ void ldm4(unsigned* r, unsigned addr) {
    asm volatile("ldmatrix.sync.aligned.m8n8.x4.shared.b16 {%0,%1,%2,%3}, [%4];"
        : "=r"(r[0]), "=r"(r[1]), "=r"(r[2]), "=r"(r[3]) : "r"(addr));
}
__device__ __forceinline__ void mma16816(float* c, const unsigned* a, const unsigned* b) {
    asm volatile("mma.sync.aligned.m16n8k16.row.col.f32.bf16.bf16.f32 "
        "{%0,%1,%2,%3}, {%4,%5,%6,%7}, {%8,%9}, {%0,%1,%2,%3};"
        : "+f"(c[0]), "+f"(c[1]), "+f"(c[2]), "+f"(c[3])
        : "r"(a[0]), "r"(a[1]), "r"(a[2]), "r"(a[3]), "r"(b[0]), "r"(b[1]));
}

// ---------------- CSR build ----------------
__global__ void zero_i_kernel(int* p, int n) {
    int t = blockIdx.x * blockDim.x + threadIdx.x;
    if (t < n) p[t] = 0;
}
__global__ void hist_kernel(const int* __restrict__ dst, int* __restrict__ cnt) {
    int e = blockIdx.x * blockDim.x + threadIdx.x;
    if (e < NE) atomicAdd(&cnt[dst[e]], 1);
}
__global__ void __launch_bounds__(256) scan_part_kernel(const int* __restrict__ cnt,
                                                        int* __restrict__ part) {
    __shared__ int sm[256];
    int base = blockIdx.x * 1024;
    int s = 0;
    for (int i = threadIdx.x; i < 1024; i += 256) {
        int idx = base + i;
        s += (idx < NN) ? cnt[idx] : 0;
    }
    sm[threadIdx.x] = s;
    __syncthreads();
    for (int d = 128; d; d >>= 1) {
        if (threadIdx.x < d) sm[threadIdx.x] += sm[threadIdx.x + d];
        __syncthreads();
    }
    if (threadIdx.x == 0) part[blockIdx.x] = sm[0];
}
__global__ void scan_mid_kernel(int* part, int npart) {
    if (threadIdx.x == 0) {
        int run = 0;
        for (int i = 0; i < npart; ++i) { int v = part[i]; part[i] = run; run += v; }
    }
}
__global__ void __launch_bounds__(256) scan_final_kernel(const int* __restrict__ cnt,
                                                         const int* __restrict__ part,
                                                         int* __restrict__ off,
                                                         int* __restrict__ pos) {
    __shared__ int wsum[8];
    int base = blockIdx.x * 1024;
    int lane = threadIdx.x & 31, wid = threadIdx.x >> 5;
    int v[4]; int s = 0;
    int i0 = base + threadIdx.x * 4;
#pragma unroll
    for (int i = 0; i < 4; ++i) {
        int idx = i0 + i;
        v[i] = (idx < NN) ? cnt[idx] : 0;
        s += v[i];
    }
    int ps = s;
#pragma unroll
    for (int o = 1; o < 32; o <<= 1) {
        int t = __shfl_up_sync(0xFFFFFFFFu, ps, o);
        if (lane >= o) ps += t;
    }
    if (lane == 31) wsum[wid] = ps;
    __syncthreads();
    if (threadIdx.x == 0) {
        int run = 0;
#pragma unroll
        for (int w = 0; w < 8; ++w) { int t = wsum[w]; wsum[w] = run; run += t; }
    }
    __syncthreads();
    int excl = ps - s + wsum[wid] + part[blockIdx.x];
#pragma unroll
    for (int i = 0; i < 4; ++i) {
        int idx = i0 + i;
        if (idx < NN) { off[idx] = excl; pos[idx] = excl; }
        excl += v[i];
    }
    if (blockIdx.x == 0 && threadIdx.x == 0) off[NN] = NE;
}
__global__ void fill_kernel(const int* __restrict__ dst, int* __restrict__ pos,
                            int* __restrict__ eid) {
    int e = blockIdx.x * blockDim.x + threadIdx.x;
    if (e < NE) {
        int idx = atomicAdd(&pos[dst[e]], 1);
        eid[idx] = e;
    }
}

// ---------------- dense GEMM JPT=1 generic (K=64 + graph-level) -----------
template <int K, int ACT>
__global__ void __launch_bounds__(128) dense_kernel(
    const float* __restrict__ A, const float* __restrict__ W,
    const float* __restrict__ bias, float* __restrict__ out,
    int n, int Jtotal, int wstride)
{
    constexpr int KP = K + 4;
    constexpr int NT = 16;
    constexpr int NPRE = NT * K / 512;
    extern __shared__ float sm[];
    float* Ws  = sm;
    float* ins = sm + 128 * KP;
    const int tid = threadIdx.x;
    const int jbase = blockIdx.y * 128;

    for (int idx = tid; idx < 128 * K; idx += 128) {
        int r = idx / K, k = idx - r * K;
        Ws[r * KP + k] = W[(size_t)(jbase + r) * wstride + k];
    }
    float b = bias ? bias[jbase + tid] : 0.0f;

    const int stride = gridDim.x * NT;
    int t0 = blockIdx.x * NT;
    float4 pre[NPRE];
    if (t0 < n) {
        int lim = min(NT, n - t0) * (K / 4);
#pragma unroll
        for (int i = 0; i < NPRE; ++i) {
            int idx = tid + i * 128;
            pre[i] = (idx < lim) ? ((const float4*)(A + (size_t)t0 * K))[idx]
                                 : make_float4(0.f, 0.f, 0.f, 0.f);
        }
    }
    __syncthreads();

    const float4* wrow = (const float4*)(Ws + (size_t)tid * KP);

    for (; t0 < n; t0 += stride) {
        int cnt = min(NT, n - t0);
#pragma unroll
        for (int i = 0; i < NPRE; ++i)
            ((float4*)ins)[tid + i * 128] = pre[i];
        __syncthreads();
        int tn = t0 + stride;
        if (tn < n) {
            int lim = min(NT, n - tn) * (K / 4);
#pragma unroll
            for (int i = 0; i < NPRE; ++i) {
                int idx = tid + i * 128;
                pre[i] = (idx < lim) ? ((const float4*)(A + (size_t)tn * K))[idx]
                                     : make_float4(0.f, 0.f, 0.f, 0.f);
            }
        }
        float acc[NT];
#pragma unroll
        for (int q = 0; q < NT; ++q) acc[q] = 0.f;

        const float4* ins4 = (const float4*)ins;
#pragma unroll 4
        for (int k4 = 0; k4 < K / 4; ++k4) {
            float4 w = wrow[k4];
#pragma unroll
            for (int q = 0; q < NT; ++q) {
                float4 v = ins4[q * (K / 4) + k4];
                acc[q] += w.x * v.x + w.y * v.y + w.z * v.z + w.w * v.w;
            }
        }
        for (int q = 0; q < cnt; ++q) {
            float r = acc[q] + b;
            if (ACT == 1) r = (r >= 0.f) ? r : 0.01f * r;
            else if (ACT == 2) r = fmaxf(r, 0.f);
            else if (ACT == 3) r = (r > 0.f) ? r : expm1f(r);
            out[(size_t)(t0 + q) * Jtotal + jbase + tid] = r;
        }
        __syncthreads();
    }
}

// ---------------- dense1: K=128 J=128 GEMM, JPT=4 x Q=8, NT=64, FFMA2 ------
template <int ACT>
__global__ void __launch_bounds__(256, 2) dense1_kernel(
    const float* __restrict__ A, const float* __restrict__ W,
    const float* __restrict__ bias, float* __restrict__ out,
    int n, int Jtotal, int wstride)
{
    constexpr int K = 128, KP = 132, NT = 64;
    extern __shared__ float sm[];
    float* Ws  = sm;
    float* ins = sm + 128 * KP;
    const int tid = threadIdx.x;
    const int jc = tid & 31;
    const int qbase = (tid >> 5) * 8;
    const int jbase = blockIdx.y * 128;

    for (int idx = tid; idx < 128 * K; idx += 256) {
        int r = idx >> 7, k = idx & 127;
        Ws[r * KP + k] = W[(size_t)(jbase + r) * wstride + k];
    }
    float b[4];
#pragma unroll
    for (int c = 0; c < 4; ++c)
        b[c] = bias ? bias[jbase + jc + c * 32] : 0.0f;

    const float4* wrow[4];
#pragma unroll
    for (int c = 0; c < 4; ++c)
        wrow[c] = (const float4*)(Ws + (size_t)(jc + c * 32) * KP);

    const int stride = gridDim.x * NT;
    __syncthreads();

    for (int t0 = blockIdx.x * NT; t0 < n; t0 += stride) {
        int cnt = min(NT, n - t0);
        int lim = cnt * (K / 4);
        const float4* Ap = (const float4*)(A + (size_t)t0 * K);
        float4* ins4w = (float4*)ins;
#pragma unroll
        for (int i = 0; i < 8; ++i) {
            int idx = tid + i * 256;
            if (idx < lim) cp_async16(ins4w + idx, Ap + idx);
            else ins4w[idx] = make_float4(0.f, 0.f, 0.f, 0.f);
        }
        cp_async_wait_all();
        __syncthreads();

        u64t acc[4][8];
#pragma unroll
        for (int c = 0; c < 4; ++c)
#pragma unroll
            for (int q = 0; q < 8; ++q) acc[c][q] = 0ULL;

        const float4* ins4 = (const float4*)ins + qbase * (K / 4);
#pragma unroll 2
        for (int k4 = 0; k4 < K / 4; ++k4) {
            u64t w01[4], w23[4];
#pragma unroll
            for (int c = 0; c < 4; ++c) {
                float4 w = wrow[c][k4];
                w01[c] = pack2(w.x, w.y);
                w23[c] = pack2(w.z, w.w);
            }
#pragma unroll
            for (int q = 0; q < 8; ++q) {
                float4 v = ins4[q * (K / 4) + k4];
                u64t v01 = pack2(v.x, v.y);
                u64t v23 = pack2(v.z, v.w);
#pragma unroll
                for (int c = 0; c < 4; ++c) {
                    ffma2(acc[c][q], w01[c], v01);
                    ffma2(acc[c][q], w23[c], v23);
                }
            }
        }
#pragma unroll
        for (int q = 0; q < 8; ++q) {
            if (qbase + q < cnt) {
                size_t row = (size_t)(t0 + qbase + q) * Jtotal + jbase;
#pragma unroll
                for (int c = 0; c < 4; ++c) {
                    float r = hsum2(acc[c][q]) + b[c];
                    if (ACT == 1) r = (r >= 0.f) ? r : 0.01f * r;
                    else if (ACT == 2) r = fmaxf(r, 0.f);
                    else if (ACT == 3) r = (r > 0.f) ? r : expm1f(r);
                    out[row + jc + c * 32] = r;
                }
            }
        }
        __syncthreads();
    }
}

// ---------------- dense3m: GRU-gate GEMM on tensor cores (split-bf16) ------
// out[n,384] = A[n,128] @ W^T (+bias) via 3-term bf16 split: AhWh + AhWl + AlWh
// 512 thr: warp w: wm=w>>3 node-half (16 rows), wg=w&7 gates {jb..jb+15}+{128,256}
// EPI==0: write gi. EPI==1: fused GRU combine (gi precomputed, hv = A row exact).
template <int EPI>
__global__ void __launch_bounds__(512) dense3m_kernel(
    const float* __restrict__ A, const float* __restrict__ W,
    const float* __restrict__ bias, float* __restrict__ out,
    const float* __restrict__ gi, int n)
{
    constexpr int KP2 = 136;   // bf16 row pad: 272B stride -> conflict-free ldmatrix
    constexpr int NT = 32;
    extern __shared__ __nv_bfloat16 smb[];
    __nv_bfloat16* Wh = smb;                       // 384*KP2
    __nv_bfloat16* Wl = smb + 384 * KP2;
    __nv_bfloat16* Ah = smb + 2 * 384 * KP2;       // NT*KP2
    __nv_bfloat16* Al = Ah + NT * KP2;
    const int tid = threadIdx.x;
    const int lane = tid & 31, w = tid >> 5;
    const int wm = w >> 3, wg = w & 7;
    const int jb = wg * 16;

    // convert W (fp32 [384][128]) -> split bf16 smem
    for (int idx = tid; idx < 384 * 32; idx += 512) {
        float4 v = ((const float4*)W)[idx];
        int r = idx >> 5, kk = (idx & 31) << 2;
        __nv_bfloat16 h0 = __float2bfloat16(v.x), h1 = __float2bfloat16(v.y);
        __nv_bfloat16 h2 = __float2bfloat16(v.z), h3 = __float2bfloat16(v.w);
        __nv_bfloat16 l0 = __float2bfloat16(v.x - __bfloat162float(h0));
        __nv_bfloat16 l1 = __float2bfloat16(v.y - __bfloat162float(h1));
        __nv_bfloat16 l2 = __float2bfloat16(v.z - __bfloat162float(h2));
        __nv_bfloat16 l3 = __float2bfloat16(v.w - __bfloat162float(h3));
        __nv_bfloat162 hA, hB, lA, lB;
        hA.x = h0; hA.y = h1; hB.x = h2; hB.y = h3;
        lA.x = l0; lA.y = l1; lB.x = l2; lB.y = l3;
        unsigned* ph_ = (unsigned*)&Wh[r * KP2 + kk];
        unsigned* pl_ = (unsigned*)&Wl[r * KP2 + kk];
        ph_[0] = *(unsigned*)&hA; ph_[1] = *(unsigned*)&hB;
        pl_[0] = *(unsigned*)&lA; pl_[1] = *(unsigned*)&lB;
    }

    // lane-fixed ldmatrix byte offsets
    const unsigned a_lane = (((lane & 15) * KP2) + (((lane >> 4) & 1) << 3)) * 2;
    const unsigned b_lane = ((((lane & 7) + (((lane >> 4) & 1) << 3)) * KP2)
                             + (((lane >> 3) & 1) << 3)) * 2;
    const unsigned sAh = (unsigned)__cvta_generic_to_shared(Ah) + a_lane + wm * 16 * KP2 * 2;
    const unsigned sAl = (unsigned)__cvta_generic_to_shared(Al) + a_lane + wm * 16 * KP2 * 2;
    const unsigned sWh = (unsigned)__cvta_generic_to_shared(Wh) + b_lane;
    const unsigned sWl = (unsigned)__cvta_generic_to_shared(Wl) + b_lane;

    __syncthreads();

    const int stride = gridDim.x * NT;
    for (int t0 = blockIdx.x * NT; t0 < n; t0 += stride) {
        int cnt = min(NT, n - t0);
        int lim4 = cnt * 32;
        // load + convert A tile
#pragma unroll
        for (int i = 0; i < 2; ++i) {
            int idx = tid + i * 512;
            float4 v = (idx < lim4) ? ((const float4*)(A + (size_t)t0 * 128))[idx]
                                    : make_float4(0.f, 0.f, 0.f, 0.f);
            int node = idx >> 5, kk = (idx & 31) << 2;
            __nv_bfloat16 h0 = __float2bfloat16(v.x), h1 = __float2bfloat16(v.y);
            __nv_bfloat16 h2 = __float2bfloat16(v.z), h3 = __float2bfloat16(v.w);
            __nv_bfloat16 l0 = __float2bfloat16(v.x - __bfloat162float(h0));
            __nv_bfloat16 l1 = __float2bfloat16(v.y - __bfloat162float(h1));
            __nv_bfloat16 l2 = __float2bfloat16(v.z - __bfloat162float(h2));
            __nv_bfloat16 l3 = __float2bfloat16(v.w - __bfloat162float(h3));
            __nv_bfloat162 hA, hB, lA, lB;
            hA.x = h0; hA.y = h1; hB.x = h2; hB.y = h3;
            lA.x = l0; lA.y = l1; lB.x = l2; lB.y = l3;
            unsigned* ph_ = (unsigned*)&Ah[node * KP2 + kk];
            unsigned* pl_ = (unsigned*)&Al[node * KP2 + kk];
            ph_[0] = *(unsigned*)&hA; ph_[1] = *(unsigned*)&hB;
            pl_[0] = *(unsigned*)&lA; pl_[1] = *(unsigned*)&lB;
        }
        __syncthreads();

        float acc[6][4];
#pragma unroll
        for (int c = 0; c < 6; ++c)
#pragma unroll
            for (int e = 0; e < 4; ++e) acc[c][e] = 0.f;

#pragma unroll
        for (int ks = 0; ks < 8; ++ks) {
            const unsigned kb = ks * 32;   // k*2 bytes, k = ks*16
            unsigned ah[4], al[4];
            ldm4(ah, sAh + kb);
            ldm4(al, sAl + kb);
#pragma unroll
            for (int pb = 0; pb < 3; ++pb) {
                const unsigned nb = (unsigned)(jb + pb * 128) * KP2 * 2 + kb;
                unsigned bh[4], bl[4];
                ldm4(bh, sWh + nb);
                ldm4(bl, sWl + nb);
                mma16816(acc[pb * 2 + 0], ah, bh + 0);
                mma16816(acc[pb * 2 + 0], ah, bl + 0);
                mma16816(acc[pb * 2 + 0], al, bh + 0);
                mma16816(acc[pb * 2 + 1], ah, bh + 2);
                mma16816(acc[pb * 2 + 1], ah, bl + 2);
                mma16816(acc[pb * 2 + 1], al, bh + 2);
            }
        }

        const int rbase = wm * 16 + (lane >> 2);
        const int colb = (lane & 3) * 2;
#pragma unroll
        for (int half = 0; half < 2; ++half) {
            int rl = rbase + half * 8;
            if (rl < cnt) {
                size_t node = (size_t)(t0 + rl);
                if (EPI == 0) {
#pragma unroll
                    for (int pb = 0; pb < 3; ++pb)
#pragma unroll
                        for (int sub = 0; sub < 2; ++sub) {
                            int gate = jb + pb * 128 + sub * 8 + colb;
                            float2 v;
                            v.x = acc[pb * 2 + sub][half * 2 + 0] + __ldg(&bias[gate]);
                            v.y = acc[pb * 2 + sub][half * 2 + 1] + __ldg(&bias[gate + 1]);
                            *(float2*)&out[node * 384 + gate] = v;
                        }
                } else {
#pragma unroll
                    for (int sub = 0; sub < 2; ++sub) {
                        int j = jb + sub * 8 + colb;
                        float2 res;
#pragma unroll
                        for (int e = 0; e < 2; ++e) {
                            int je = j + e;
                            float hr = acc[sub][half * 2 + e] + __ldg(&bias[je]);
                            float hz = acc[2 + sub][half * 2 + e] + __ldg(&bias[128 + je]);
                            float hn = acc[4 + sub][half * 2 + e] + __ldg(&bias[256 + je]);
                            float r = sigm(gi[node * 384 + je] + hr);
                            float z = sigm(gi[node * 384 + 128 + je] + hz);
                            float nn = tanhf(gi[node * 384 + 256 + je] + r * hn);
                            float hv = A[node * 128 + je];
                            float o = fmaxf((1.f - z) * nn + z * hv, 0.f);
                            if (e == 0) res.x = o; else res.y = o;
                        }
                        *(float2*)&out[node * 128 + j] = res;
                    }
                }
            }
        }
        __syncthreads();
    }
}

// ---------------- nd gather (CSR, prefetched) ----------------
__global__ void __launch_bounds__(256) nd_gather_kernel(
    const float* __restrict__ p, const float* __restrict__ ea,
    const int* __restrict__ src, const int* __restrict__ off,
    const int* __restrict__ eid, const float* __restrict__ w1,
    float* __restrict__ tsum)
{
    __shared__ float W1b[16 * 128];
    const int tid = threadIdx.x;
    for (int idx = tid; idx < 16 * 128; idx += 256) {
        int k = idx >> 7, j = idx & 127;
        W1b[idx] = w1[j * 144 + 128 + k];
    }
    __syncthreads();
    int n = blockIdx.x * 8 + (tid >> 5);
    if (n >= NN) return;
    int lane = tid & 31;
    int beg = off[n], end = off[n + 1];
    float4 acc = make_float4(0.f, 0.f, 0.f, 0.f);
    const float4* W1b4 = (const float4*)W1b;
    const float4* p4 = (const float4*)p;
    if (beg < end) {
        int ed = eid[beg];
        int s = src[ed];
        for (int e = beg; e < end; ++e) {
            int s_cur = s, ed_cur = ed;
            if (e + 1 < end) {
                ed = eid[e + 1];
                s = src[ed];
            }
            float eav = (lane < 16) ? __ldg(&ea[(size_t)ed_cur * 16 + lane]) : 0.f;
            float4 t = p4[(size_t)s_cur * 32 + lane];
#pragma unroll
            for (int k = 0; k < 16; ++k) {
                float ek = __shfl_sync(0xFFFFFFFFu, eav, k);
                float4 w = W1b4[k * 32 + lane];
                t.x += ek * w.x; t.y += ek * w.y; t.z += ek * w.z; t.w += ek * w.w;
            }
            t.x = (t.x >= 0.f) ? t.x : 0.01f * t.x;
            t.y = (t.y >= 0.f) ? t.y : 0.01f * t.y;
            t.z = (t.z >= 0.f) ? t.z : 0.01f * t.z;
            t.w = (t.w >= 0.f) ? t.w : 0.01f * t.w;
            acc.x += t.x; acc.y += t.y; acc.z += t.z; acc.w += t.w;
        }
    }
    ((float4*)tsum)[(size_t)n * 32 + lane] = acc;
}

// ---------------- GAT attention dots ----------------
__global__ void attn_dots_kernel(const float* __restrict__ xp, const float* __restrict__ asrc,
                                 const float* __restrict__ adst, float* __restrict__ as_,
                                 float* __restrict__ ad_) {
    int n = (blockIdx.x * blockDim.x + threadIdx.x) >> 5;
    int lane = threadIdx.x & 31;
    if (n >= NN) return;
    float4 v = ((const float4*)xp)[(size_t)n * 32 + lane];
    float4 w1 = ((const float4*)asrc)[lane];
    float4 w2 = ((const float4*)adst)[lane];
    float sa = v.x * w1.x + v.y * w1.y + v.z * w1.z + v.w * w1.w;
    float sd = v.x * w2.x + v.y * w2.y + v.z * w2.z + v.w * w2.w;
#pragma unroll
    for (int o = 16; o; o >>= 1) {
        sa += __shfl_xor_sync(0xFFFFFFFFu, sa, o);
        sd += __shfl_xor_sync(0xFFFFFFFFu, sd, o);
    }
    if (lane == 0) { as_[n] = sa; ad_[n] = sd; }
}

// ---------------- GAT gather (CSR, online softmax, prefetched) -------------
__global__ void __launch_bounds__(256) gat_gather_kernel(
    const int* __restrict__ src, const int* __restrict__ off, const int* __restrict__ eid,
    const float* __restrict__ as_, const float* __restrict__ ad_,
    const float* __restrict__ xp, const float* __restrict__ bias,
    float* __restrict__ hout)
{
    int n = blockIdx.x * 8 + (threadIdx.x >> 5);
    if (n >= NN) return;
    int lane = threadIdx.x & 31;
    int beg = off[n], end = off[n + 1];
    float adn = ad_[n];
    float m = -INFINITY, den = 0.f;
    float4 acc = make_float4(0.f, 0.f, 0.f, 0.f);
    const float4* xp4 = (const float4*)xp;
    if (beg < end) {
        int s = src[eid[beg]];
        float av = __ldg(&as_[s]);
        for (int e = beg; e < end; ++e) {
            int s_cur = s; float a = av + adn;
            if (e + 1 < end) {
                s = src[eid[e + 1]];
                av = __ldg(&as_[s]);
            }
            float4 v = xp4[(size_t)s_cur * 32 + lane];
            a = (a >= 0.f) ? a : 0.01f * a;
            if (a > m) {
                float f = __expf(m - a);
                den *= f;
                acc.x *= f; acc.y *= f; acc.z *= f; acc.w *= f;
                m = a;
            }
            float w = __expf(a - m);
            den += w;
            acc.x += w * v.x; acc.y += w * v.y; acc.z += w * v.z; acc.w += w * v.w;
        }
    }
    float inv = (den > 0.f) ? 1.f / den : 0.f;
    float4 b = ((const float4*)bias)[lane];
    float4 r;
    r.x = acc.x * inv + b.x; r.y = acc.y * inv + b.y;
    r.z = acc.z * inv + b.z; r.w = acc.w * inv + b.w;
    r.x = (r.x > 0.f) ? r.x : expm1f(r.x);
    r.y = (r.y > 0.f) ? r.y : expm1f(r.y);
    r.z = (r.z > 0.f) ? r.z : expm1f(r.z);
    r.w = (r.w > 0.f) ? r.w : expm1f(r.w);
    ((float4*)hout)[(size_t)n * 32 + lane] = r;
}

// ---------------- readout ----------------
__global__ void __launch_bounds__(128) graph_agg_kernel(const float* __restrict__ xcur,
                                                        const int* __restrict__ batch,
                                                        float* __restrict__ agg,
                                                        float* __restrict__ outv) {
    int g = blockIdx.x;
    int lo, hi;
    {
        int l = 0, r = NN;
        while (l < r) { int m = (l + r) >> 1; if (batch[m] < g) l = m + 1; else r = m; }
        lo = l;
    }
    {
        int l = lo, r = NN;
        while (l < r) { int m = (l + r) >> 1; if (batch[m] < g + 1) l = m + 1; else r = m; }
        hi = l;
    }
    float s = 0.f;
    for (int n = lo; n < hi; ++n) s += xcur[(size_t)n * 128 + threadIdx.x];
    agg[g * 128 + threadIdx.x] = s;
    outv[g * 128 + threadIdx.x] = fmaxf(s, 0.f);
}

__global__ void add_kernel(const float* __restrict__ a, const float* __restrict__ b,
                           float* __restrict__ c, int n) {
    int t = blockIdx.x * blockDim.x + threadIdx.x;
    if (t < n) c[t] = a[t] + b[t];
}

__global__ void lstm_combine_kernel(const float* __restrict__ gi, const float* __restrict__ gh,
                                    const float* __restrict__ hc, float* __restrict__ out) {
    int t = blockIdx.x * blockDim.x + threadIdx.x;
    if (t >= NG * 128) return;
    int g = t >> 7, j = t & 127;
    size_t base = (size_t)g * 512;
    float gI = gi[base + j]       + gh[base + j];
    float gF = gi[base + 128 + j] + gh[base + 128 + j];
    float gG = gi[base + 256 + j] + gh[base + 256 + j];
    float gO = gi[base + 384 + j] + gh[base + 384 + j];
    float c = hc[t];
    float c2 = sigm(gF) * c + sigm(gI) * tanhf(gG);
    out[t] = sigm(gO) * tanhf(c2);
}

__global__ void final_kernel(const float* __restrict__ outv, const float* __restrict__ w,
                             const float* __restrict__ b, float* __restrict__ res) {
    int g = (blockIdx.x * blockDim.x + threadIdx.x) >> 5;
    int lane = threadIdx.x & 31;
    if (g >= NG) return;
    float4 v = ((const float4*)outv)[(size_t)g * 32 + lane];
    float4 ww = ((const float4*)w)[lane];
    float s = v.x * ww.x + v.y * ww.y + v.z * ww.z + v.w * ww.w;
#pragma unroll
    for (int o = 16; o; o >>= 1) s += __shfl_xor_sync(0xFFFFFFFFu, s, o);
    if (lane == 0) res[g] = s + b[0];
}

// ---------------- host ----------------
#define SM_J1K64  ((128 * 68 + 16 * 64) * 4)
#define SM_J1K128 ((128 * 132 + 16 * 128) * 4)
#define SM_D1     ((128 * 132 + 64 * 128) * 4)
#define SM_M3     ((2 * 384 * 136 + 2 * 32 * 136) * 2)

extern "C" void kernel_launch(void* const* d_in, const int* in_sizes, int n_in,
                              void* d_out, int out_size) {
    const float* x        = (const float*)d_in[0];
    const int*   ei       = (const int*)  d_in[1];
    const float* ea       = (const float*)d_in[2];
    const int*   batch    = (const int*)  d_in[3];
    const float* lin1_w   = (const float*)d_in[4];
    const float* lin1_b   = (const float*)d_in[5];
    const float* nd_lin1w = (const float*)d_in[6];
    const float* nd_lin2w = (const float*)d_in[7];
    const float* nd_bias  = (const float*)d_in[8];
    const float* gru0_wih = (const float*)d_in[9];
    const float* gru0_whh = (const float*)d_in[10];
    const float* gru0_bih = (const float*)d_in[11];
    const float* gru0_bhh = (const float*)d_in[12];
    const float* gat_w    = (const float*)d_in[13];
    const float* gat_asrc = (const float*)d_in[14];
    const float* gat_adst = (const float*)d_in[15];
    const float* gat_b    = (const float*)d_in[16];
    const float* gru_wih  = (const float*)d_in[17];
    const float* gru_whh  = (const float*)d_in[18];
    const float* gru_bih  = (const float*)d_in[19];
    const float* gru_bhh  = (const float*)d_in[20];
    const float* gin_w    = (const float*)d_in[21];
    const float* gin_b    = (const float*)d_in[22];
    const float* lstm_wih = (const float*)d_in[23];
    const float* lstm_whh = (const float*)d_in[24];
    const float* lstm_bih = (const float*)d_in[25];
    const float* lstm_bhh = (const float*)d_in[26];
    const float* lin2_w   = (const float*)d_in[27];
    const float* lin2_b   = (const float*)d_in[28];
    float* out = (float*)d_out;

    const int* src = ei;
    const int* dst = ei + NE;

    float *px1, *pp, *ph, *pxc, *pgi, *pas, *pad;
    float *pagg, *pgout, *pghh, *pgtmp, *pggi, *pggh;
    int *pcnt, *poff, *ppos, *peid, *ppart;
    cudaGetSymbolAddress((void**)&px1, f_x1);
    cudaGetSymbolAddress((void**)&pp, f_p);
    cudaGetSymbolAddress((void**)&ph, f_h);
    cudaGetSymbolAddress((void**)&pxc, f_xcur);
    cudaGetSymbolAddress((void**)&pgi, f_gi);
    cudaGetSymbolAddress((void**)&pas, f_as);
    cudaGetSymbolAddress((void**)&pad, f_ad);
    cudaGetSymbolAddress((void**)&pagg, g_agg);
    cudaGetSymbolAddress((void**)&pgout, g_out);
    cudaGetSymbolAddress((void**)&pghh, g_hh);
    cudaGetSymbolAddress((void**)&pgtmp, g_tmp);
    cudaGetSymbolAddress((void**)&pggi, g_gi);
    cudaGetSymbolAddress((void**)&pggh, g_gh);
    cudaGetSymbolAddress((void**)&pcnt, c_cnt);
    cudaGetSymbolAddress((void**)&poff, c_off);
    cudaGetSymbolAddress((void**)&ppos, c_pos);
    cudaGetSymbolAddress((void**)&peid, c_eid);
    cudaGetSymbolAddress((void**)&ppart, c_part);

    cudaFuncSetAttribute((const void*)dense_kernel<64, 1>, cudaFuncAttributeMaxDynamicSharedMemorySize, SM_J1K64);
    cudaFuncSetAttribute((const void*)dense_kernel<128, 0>, cudaFuncAttributeMaxDynamicSharedMemorySize, SM_J1K128);
    cudaFuncSetAttribute((const void*)dense_kernel<128, 3>, cudaFuncAttributeMaxDynamicSharedMemorySize, SM_J1K128);
    cudaFuncSetAttribute((const void*)dense1_kernel<0>, cudaFuncAttributeMaxDynamicSharedMemorySize, SM_D1);
    cudaFuncSetAttribute((const void*)dense1_kernel<3>, cudaFuncAttributeMaxDynamicSharedMemorySize, SM_D1);
    cudaFuncSetAttribute((const void*)dense3m_kernel<0>, cudaFuncAttributeMaxDynamicSharedMemorySize, SM_M3);
    cudaFuncSetAttribute((const void*)dense3m_kernel<1>, cudaFuncAttributeMaxDynamicSharedMemorySize, SM_M3);

    const int GP1b = 592;
    const int GPD1 = 296;
    const int GP3 = 148;
    const int NPART = (NN + 1023) / 1024;
    const int tilesG = (NG + 15) / 16;
    const int ZB = 256;

    // 0) x1 = leaky(x @ lin1_w.T + b)
    dense_kernel<64, 1><<<dim3(GP1b, 1), 128, SM_J1K64>>>(x, lin1_w, lin1_b, px1, NN, 128, 64);
    // 1-2) CSR phase A
    zero_i_kernel<<<(NN + ZB - 1) / ZB, ZB>>>(pcnt, NN);
    hist_kernel<<<(NE + ZB - 1) / ZB, ZB>>>(dst, pcnt);
    // 3) p = x1 @ W1a.T   <-- PROFILED
    dense1_kernel<0><<<dim3(GPD1, 1), 256, SM_D1>>>(px1, nd_lin1w, nullptr, pp, NN, 128, 144);
    // 4-7) CSR phase B
    scan_part_kernel<<<NPART, 256>>>(pcnt, ppart);
    scan_mid_kernel<<<1, 32>>>(ppart, NPART);
    scan_final_kernel<<<NPART, 256>>>(pcnt, ppart, poff, ppos);
    fill_kernel<<<(NE + ZB - 1) / ZB, ZB>>>(dst, ppos, peid);
    // tsum
    nd_gather_kernel<<<(NN + 7) / 8, 256>>>(pp, ea, src, poff, peid, nd_lin1w, pgi);
    // h = elu(tsum @ W2.T + nd_bias)
    dense1_kernel<3><<<dim3(GPD1, 1), 256, SM_D1>>>(pgi, nd_lin2w, nd_bias, ph, NN, 128, 128);
    // GRU0 (tensor-core split-bf16)
    dense3m_kernel<0><<<GP3, 512, SM_M3>>>(ph, gru0_wih, gru0_bih, pgi, nullptr, NN);
    dense3m_kernel<1><<<GP3, 512, SM_M3>>>(px1, gru0_whh, gru0_bhh, pxc, pgi, NN);

    // GAT layers
    for (int l = 0; l < 2; ++l) {
        dense1_kernel<0><<<dim3(GPD1, 1), 256, SM_D1>>>(pxc, gat_w + (size_t)l * 128 * 128, nullptr, pp, NN, 128, 128);
        attn_dots_kernel<<<(NN * 32 + ZB - 1) / ZB, ZB>>>(pp, gat_asrc + l * 128, gat_adst + l * 128, pas, pad);
        gat_gather_kernel<<<(NN + 7) / 8, 256>>>(src, poff, peid, pas, pad, pp, gat_b + l * 128, ph);
        dense3m_kernel<0><<<GP3, 512, SM_M3>>>(ph, gru_wih + (size_t)l * 384 * 128, gru_bih + l * 384, pgi, nullptr, NN);
        dense3m_kernel<1><<<GP3, 512, SM_M3>>>(pxc, gru_whh + (size_t)l * 384 * 128, gru_bhh + l * 384, pxc, pgi, NN);
    }

    // readout
    graph_agg_kernel<<<NG, 128>>>(pxc, batch, pagg, pgout);
    for (int t = 0; t < 2; ++t) {
        add_kernel<<<(NG * 128 + ZB - 1) / ZB, ZB>>>(pgout, pagg, pgtmp, NG * 128);
        dense_kernel<128, 3><<<dim3(tilesG, 1), 128, SM_J1K128>>>(pgtmp, gin_w, gin_b, pghh, NG, 128, 128);
        dense_kernel<128, 0><<<dim3(tilesG, 4), 128, SM_J1K128>>>(pgout, lstm_wih, lstm_bih, pggi, NG, 512, 128);
        dense_kernel<128, 0><<<dim3(tilesG, 4), 128, SM_J1K128>>>(pghh, lstm_whh, lstm_bhh, pggh, NG, 512, 128);
        lstm_combine_kernel<<<(NG * 128 + ZB - 1) / ZB, ZB>>>(pggi, pggh, pghh, pgout);
    }
    final_kernel<<<(NG * 32 + 127) / 128, 128>>>(pgout, lin2_w, lin2_b, out);
}

// round 10
// speedup vs baseline: 3.9376x; 1.1050x over previous
#include <cuda_runtime.h>
#include <cuda_bf16.h>
#include <math.h>

#define NN 50000
#define NE 500000
#define NG 2000

typedef unsigned long long u64t;

// ---------------- scratch (device globals) ----------------
__device__ float f_x1  [NN * 128];
__device__ float f_p   [NN * 128];
__device__ float f_h   [NN * 128];
__device__ float f_xcur[NN * 128];
__device__ float f_gi  [NN * 3 * 128];
__device__ float f_as  [NN];
__device__ float f_ad  [NN];
__device__ float g_agg [NG * 128];
__device__ float g_out [NG * 128];
__device__ float g_hh  [NG * 128];
__device__ float g_tmp [NG * 128];
__device__ float g_gi  [NG * 4 * 128];
__device__ float g_gh  [NG * 4 * 128];
__device__ int c_cnt[NN];
__device__ int c_off[NN + 1];
__device__ int c_pos[NN];
__device__ int c_eid[NE];
__device__ int c_part[64];

__device__ __forceinline__ float sigm(float x) { return 1.0f / (1.0f + expf(-x)); }

__device__ __forceinline__ void ldm4(unsigned* r, unsigned addr) {
    asm volatile("ldmatrix.sync.aligned.m8n8.x4.shared.b16 {%0,%1,%2,%3}, [%4];"
        : "=r"(r[0]), "=r"(r[1]), "=r"(r[2]), "=r"(r[3]) : "r"(addr));
}
__device__ __forceinline__ void mma16816(float* c, const unsigned* a, const unsigned* b) {
    asm volatile("mma.sync.aligned.m16n8k16.row.col.f32.bf16.bf16.f32 "
        "{%0,%1,%2,%3}, {%4,%5,%6,%7}, {%8,%9}, {%0,%1,%2,%3};"
        : "+f"(c[0]), "+f"(c[1]), "+f"(c[2]), "+f"(c[3])
        : "r"(a[0]), "r"(a[1]), "r"(a[2]), "r"(a[3]), "r"(b[0]), "r"(b[1]));
}
__device__ __forceinline__ void bf16split4(float4 v, unsigned* ph_, unsigned* pl_) {
    __nv_bfloat16 h0 = __float2bfloat16(v.x), h1 = __float2bfloat16(v.y);
    __nv_bfloat16 h2 = __float2bfloat16(v.z), h3 = __float2bfloat16(v.w);
    __nv_bfloat16 l0 = __float2bfloat16(v.x - __bfloat162float(h0));
    __nv_bfloat16 l1 = __float2bfloat16(v.y - __bfloat162float(h1));
    __nv_bfloat16 l2 = __float2bfloat16(v.z - __bfloat162float(h2));
    __nv_bfloat16 l3 = __float2bfloat16(v.w - __bfloat162float(h3));
    __nv_bfloat162 hA, hB, lA, lB;
    hA.x = h0; hA.y = h1; hB.x = h2; hB.y = h3;
    lA.x = l0; lA.y = l1; lB.x = l2; lB.y = l3;
    ph_[0] = *(unsigned*)&hA; ph_[1] = *(unsigned*)&hB;
    pl_[0] = *(unsigned*)&lA; pl_[1] = *(unsigned*)&lB;
}

// ---------------- CSR build ----------------
__global__ void zero_i_kernel(int* p, int n) {
    int t = blockIdx.x * blockDim.x + threadIdx.x;
    if (t < n) p[t] = 0;
}
__global__ void hist_kernel(const int* __restrict__ dst, int* __restrict__ cnt) {
    int e = blockIdx.x * blockDim.x + threadIdx.x;
    if (e < NE) atomicAdd(&cnt[dst[e]], 1);
}
__global__ void __launch_bounds__(256) scan_part_kernel(const int* __restrict__ cnt,
                                                        int* __restrict__ part) {
    __shared__ int sm[256];
    int base = blockIdx.x * 1024;
    int s = 0;
    for (int i = threadIdx.x; i < 1024; i += 256) {
        int idx = base + i;
        s += (idx < NN) ? cnt[idx] : 0;
    }
    sm[threadIdx.x] = s;
    __syncthreads();
    for (int d = 128; d; d >>= 1) {
        if (threadIdx.x < d) sm[threadIdx.x] += sm[threadIdx.x + d];
        __syncthreads();
    }
    if (threadIdx.x == 0) part[blockIdx.x] = sm[0];
}
__global__ void scan_mid_kernel(int* part, int npart) {
    if (threadIdx.x == 0) {
        int run = 0;
        for (int i = 0; i < npart; ++i) { int v = part[i]; part[i] = run; run += v; }
    }
}
__global__ void __launch_bounds__(256) scan_final_kernel(const int* __restrict__ cnt,
                                                         const int* __restrict__ part,
                                                         int* __restrict__ off,
                                                         int* __restrict__ pos) {
    __shared__ int wsum[8];
    int base = blockIdx.x * 1024;
    int lane = threadIdx.x & 31, wid = threadIdx.x >> 5;
    int v[4]; int s = 0;
    int i0 = base + threadIdx.x * 4;
#pragma unroll
    for (int i = 0; i < 4; ++i) {
        int idx = i0 + i;
        v[i] = (idx < NN) ? cnt[idx] : 0;
        s += v[i];
    }
    int ps = s;
#pragma unroll
    for (int o = 1; o < 32; o <<= 1) {
        int t = __shfl_up_sync(0xFFFFFFFFu, ps, o);
        if (lane >= o) ps += t;
    }
    if (lane == 31) wsum[wid] = ps;
    __syncthreads();
    if (threadIdx.x == 0) {
        int run = 0;
#pragma unroll
        for (int w = 0; w < 8; ++w) { int t = wsum[w]; wsum[w] = run; run += t; }
    }
    __syncthreads();
    int excl = ps - s + wsum[wid] + part[blockIdx.x];
#pragma unroll
    for (int i = 0; i < 4; ++i) {
        int idx = i0 + i;
        if (idx < NN) { off[idx] = excl; pos[idx] = excl; }
        excl += v[i];
    }
    if (blockIdx.x == 0 && threadIdx.x == 0) off[NN] = NE;
}
__global__ void fill_kernel(const int* __restrict__ dst, int* __restrict__ pos,
                            int* __restrict__ eid) {
    int e = blockIdx.x * blockDim.x + threadIdx.x;
    if (e < NE) {
        int idx = atomicAdd(&pos[dst[e]], 1);
        eid[idx] = e;
    }
}

// ---------------- dense GEMM JPT=1 generic (K=64 + graph-level) -----------
template <int K, int ACT>
__global__ void __launch_bounds__(128) dense_kernel(
    const float* __restrict__ A, const float* __restrict__ W,
    const float* __restrict__ bias, float* __restrict__ out,
    int n, int Jtotal, int wstride)
{
    constexpr int KP = K + 4;
    constexpr int NT = 16;
    constexpr int NPRE = NT * K / 512;
    extern __shared__ float sm[];
    float* Ws  = sm;
    float* ins = sm + 128 * KP;
    const int tid = threadIdx.x;
    const int jbase = blockIdx.y * 128;

    for (int idx = tid; idx < 128 * K; idx += 128) {
        int r = idx / K, k = idx - r * K;
        Ws[r * KP + k] = W[(size_t)(jbase + r) * wstride + k];
    }
    float b = bias ? bias[jbase + tid] : 0.0f;

    const int stride = gridDim.x * NT;
    int t0 = blockIdx.x * NT;
    float4 pre[NPRE];
    if (t0 < n) {
        int lim = min(NT, n - t0) * (K / 4);
#pragma unroll
        for (int i = 0; i < NPRE; ++i) {
            int idx = tid + i * 128;
            pre[i] = (idx < lim) ? ((const float4*)(A + (size_t)t0 * K))[idx]
                                 : make_float4(0.f, 0.f, 0.f, 0.f);
        }
    }
    __syncthreads();

    const float4* wrow = (const float4*)(Ws + (size_t)tid * KP);

    for (; t0 < n; t0 += stride) {
        int cnt = min(NT, n - t0);
#pragma unroll
        for (int i = 0; i < NPRE; ++i)
            ((float4*)ins)[tid + i * 128] = pre[i];
        __syncthreads();
        int tn = t0 + stride;
        if (tn < n) {
            int lim = min(NT, n - tn) * (K / 4);
#pragma unroll
            for (int i = 0; i < NPRE; ++i) {
                int idx = tid + i * 128;
                pre[i] = (idx < lim) ? ((const float4*)(A + (size_t)tn * K))[idx]
                                     : make_float4(0.f, 0.f, 0.f, 0.f);
            }
        }
        float acc[NT];
#pragma unroll
        for (int q = 0; q < NT; ++q) acc[q] = 0.f;

        const float4* ins4 = (const float4*)ins;
#pragma unroll 4
        for (int k4 = 0; k4 < K / 4; ++k4) {
            float4 w = wrow[k4];
#pragma unroll
            for (int q = 0; q < NT; ++q) {
                float4 v = ins4[q * (K / 4) + k4];
                acc[q] += w.x * v.x + w.y * v.y + w.z * v.z + w.w * v.w;
            }
        }
        for (int q = 0; q < cnt; ++q) {
            float r = acc[q] + b;
            if (ACT == 1) r = (r >= 0.f) ? r : 0.01f * r;
            else if (ACT == 2) r = fmaxf(r, 0.f);
            else if (ACT == 3) r = (r > 0.f) ? r : expm1f(r);
            out[(size_t)(t0 + q) * Jtotal + jbase + tid] = r;
        }
        __syncthreads();
    }
}

// ---------------- dense1m: J=128 GEMM on tensor cores (split-bf16) ---------
// out[n,128] = act(A[n,128] @ W^T + b). W row stride = wstride floats.
// 512 thr, persistent; warp w: wm=w>>3 node-half, wg=w&7 cols {wg*16..+15}
template <int ACT>
__global__ void __launch_bounds__(512, 2) dense1m_kernel(
    const float* __restrict__ A, const float* __restrict__ W,
    const float* __restrict__ bias, float* __restrict__ out,
    int n, int wstride)
{
    constexpr int KP2 = 136;
    constexpr int NT = 32;
    extern __shared__ __nv_bfloat16 smb[];
    __nv_bfloat16* Wh = smb;                       // 128*KP2
    __nv_bfloat16* Wl = smb + 128 * KP2;
    __nv_bfloat16* Ah = smb + 2 * 128 * KP2;       // NT*KP2
    __nv_bfloat16* Al = Ah + NT * KP2;
    const int tid = threadIdx.x;
    const int lane = tid & 31, w = tid >> 5;
    const int wm = w >> 3, wg = w & 7;
    const int jb = wg * 16;

    for (int idx = tid; idx < 128 * 32; idx += 512) {
        int r = idx >> 5, c4 = idx & 31;
        float4 v = ((const float4*)(W + (size_t)r * wstride))[c4];
        bf16split4(v, (unsigned*)&Wh[r * KP2 + c4 * 4], (unsigned*)&Wl[r * KP2 + c4 * 4]);
    }

    const unsigned a_lane = (((lane & 15) * KP2) + (((lane >> 4) & 1) << 3)) * 2;
    const unsigned b_lane = ((((lane & 7) + (((lane >> 4) & 1) << 3)) * KP2)
                             + (((lane >> 3) & 1) << 3)) * 2;
    const unsigned sAh = (unsigned)__cvta_generic_to_shared(Ah) + a_lane + wm * 16 * KP2 * 2;
    const unsigned sAl = (unsigned)__cvta_generic_to_shared(Al) + a_lane + wm * 16 * KP2 * 2;
    const unsigned sWh = (unsigned)__cvta_generic_to_shared(Wh) + b_lane + (unsigned)jb * KP2 * 2;
    const unsigned sWl = (unsigned)__cvta_generic_to_shared(Wl) + b_lane + (unsigned)jb * KP2 * 2;

    __syncthreads();

    const int stride = gridDim.x * NT;
    for (int t0 = blockIdx.x * NT; t0 < n; t0 += stride) {
        int cnt = min(NT, n - t0);
        int lim4 = cnt * 32;
#pragma unroll
        for (int i = 0; i < 2; ++i) {
            int idx = tid + i * 512;
            float4 v = (idx < lim4) ? ((const float4*)(A + (size_t)t0 * 128))[idx]
                                    : make_float4(0.f, 0.f, 0.f, 0.f);
            int node = idx >> 5, kk = (idx & 31) << 2;
            bf16split4(v, (unsigned*)&Ah[node * KP2 + kk], (unsigned*)&Al[node * KP2 + kk]);
        }
        __syncthreads();

        float acc[2][4];
#pragma unroll
        for (int c = 0; c < 2; ++c)
#pragma unroll
            for (int e = 0; e < 4; ++e) acc[c][e] = 0.f;

#pragma unroll
        for (int ks = 0; ks < 8; ++ks) {
            const unsigned kb = ks * 32;
            unsigned ah[4], al[4], bh[4], bl[4];
            ldm4(ah, sAh + kb);
            ldm4(al, sAl + kb);
            ldm4(bh, sWh + kb);
            ldm4(bl, sWl + kb);
            mma16816(acc[0], ah, bh + 0);
            mma16816(acc[0], ah, bl + 0);
            mma16816(acc[0], al, bh + 0);
            mma16816(acc[1], ah, bh + 2);
            mma16816(acc[1], ah, bl + 2);
            mma16816(acc[1], al, bh + 2);
        }

        const int rbase = wm * 16 + (lane >> 2);
        const int colb = (lane & 3) * 2;
#pragma unroll
        for (int half = 0; half < 2; ++half) {
            int rl = rbase + half * 8;
            if (rl < cnt) {
                size_t node = (size_t)(t0 + rl);
#pragma unroll
                for (int sub = 0; sub < 2; ++sub) {
                    int j = jb + sub * 8 + colb;
                    float2 res;
#pragma unroll
                    for (int e = 0; e < 2; ++e) {
                        float r = acc[sub][half * 2 + e] + (bias ? __ldg(&bias[j + e]) : 0.f);
                        if (ACT == 1) r = (r >= 0.f) ? r : 0.01f * r;
                        else if (ACT == 2) r = fmaxf(r, 0.f);
                        else if (ACT == 3) r = (r > 0.f) ? r : expm1f(r);
                        if (e == 0) res.x = r; else res.y = r;
                    }
                    *(float2*)&out[node * 128 + j] = res;
                }
            }
        }
        __syncthreads();
    }
}

// ---------------- dense3m: GRU-gate GEMM on tensor cores (split-bf16) ------
template <int EPI>
__global__ void __launch_bounds__(512) dense3m_kernel(
    const float* __restrict__ A, const float* __restrict__ W,
    const float* __restrict__ bias, float* __restrict__ out,
    const float* __restrict__ gi, int n)
{
    constexpr int KP2 = 136;
    constexpr int NT = 32;
    extern __shared__ __nv_bfloat16 smb[];
    __nv_bfloat16* Wh = smb;                       // 384*KP2
    __nv_bfloat16* Wl = smb + 384 * KP2;
    __nv_bfloat16* Ah = smb + 2 * 384 * KP2;       // NT*KP2
    __nv_bfloat16* Al = Ah + NT * KP2;
    const int tid = threadIdx.x;
    const int lane = tid & 31, w = tid >> 5;
    const int wm = w >> 3, wg = w & 7;
    const int jb = wg * 16;

    for (int idx = tid; idx < 384 * 32; idx += 512) {
        float4 v = ((const float4*)W)[idx];
        int r = idx >> 5, kk = (idx & 31) << 2;
        bf16split4(v, (unsigned*)&Wh[r * KP2 + kk], (unsigned*)&Wl[r * KP2 + kk]);
    }

    const unsigned a_lane = (((lane & 15) * KP2) + (((lane >> 4) & 1) << 3)) * 2;
    const unsigned b_lane = ((((lane & 7) + (((lane >> 4) & 1) << 3)) * KP2)
                             + (((lane >> 3) & 1) << 3)) * 2;
    const unsigned sAh = (unsigned)__cvta_generic_to_shared(Ah) + a_lane + wm * 16 * KP2 * 2;
    const unsigned sAl = (unsigned)__cvta_generic_to_shared(Al) + a_lane + wm * 16 * KP2 * 2;
    const unsigned sWh = (unsigned)__cvta_generic_to_shared(Wh) + b_lane;
    const unsigned sWl = (unsigned)__cvta_generic_to_shared(Wl) + b_lane;

    __syncthreads();

    const int stride = gridDim.x * NT;
    for (int t0 = blockIdx.x * NT; t0 < n; t0 += stride) {
        int cnt = min(NT, n - t0);
        int lim4 = cnt * 32;
#pragma unroll
        for (int i = 0; i < 2; ++i) {
            int idx = tid + i * 512;
            float4 v = (idx < lim4) ? ((const float4*)(A + (size_t)t0 * 128))[idx]
                                    : make_float4(0.f, 0.f, 0.f, 0.f);
            int node = idx >> 5, kk = (idx & 31) << 2;
            bf16split4(v, (unsigned*)&Ah[node * KP2 + kk], (unsigned*)&Al[node * KP2 + kk]);
        }
        __syncthreads();

        float acc[6][4];
#pragma unroll
        for (int c = 0; c < 6; ++c)
#pragma unroll
            for (int e = 0; e < 4; ++e) acc[c][e] = 0.f;

#pragma unroll
        for (int ks = 0; ks < 8; ++ks) {
            const unsigned kb = ks * 32;
            unsigned ah[4], al[4];
            ldm4(ah, sAh + kb);
            ldm4(al, sAl + kb);
#pragma unroll
            for (int pb = 0; pb < 3; ++pb) {
                const unsigned nb = (unsigned)(jb + pb * 128) * KP2 * 2 + kb;
                unsigned bh[4], bl[4];
                ldm4(bh, sWh + nb);
                ldm4(bl, sWl + nb);
                mma16816(acc[pb * 2 + 0], ah, bh + 0);
                mma16816(acc[pb * 2 + 0], ah, bl + 0);
                mma16816(acc[pb * 2 + 0], al, bh + 0);
                mma16816(acc[pb * 2 + 1], ah, bh + 2);
                mma16816(acc[pb * 2 + 1], ah, bl + 2);
                mma16816(acc[pb * 2 + 1], al, bh + 2);
            }
        }

        const int rbase = wm * 16 + (lane >> 2);
        const int colb = (lane & 3) * 2;
#pragma unroll
        for (int half = 0; half < 2; ++half) {
            int rl = rbase + half * 8;
            if (rl < cnt) {
                size_t node = (size_t)(t0 + rl);
                if (EPI == 0) {
#pragma unroll
                    for (int pb = 0; pb < 3; ++pb)
#pragma unroll
                        for (int sub = 0; sub < 2; ++sub) {
                            int gate = jb + pb * 128 + sub * 8 + colb;
                            float2 v;
                            v.x = acc[pb * 2 + sub][half * 2 + 0] + __ldg(&bias[gate]);
                            v.y = acc[pb * 2 + sub][half * 2 + 1] + __ldg(&bias[gate + 1]);
                            *(float2*)&out[node * 384 + gate] = v;
                        }
                } else {
#pragma unroll
                    for (int sub = 0; sub < 2; ++sub) {
                        int j = jb + sub * 8 + colb;
                        float2 res;
#pragma unroll
                        for (int e = 0; e < 2; ++e) {
                            int je = j + e;
                            float hr = acc[sub][half * 2 + e] + __ldg(&bias[je]);
                            float hz = acc[2 + sub][half * 2 + e] + __ldg(&bias[128 + je]);
                            float hn = acc[4 + sub][half * 2 + e] + __ldg(&bias[256 + je]);
                            float r = sigm(gi[node * 384 + je] + hr);
                            float z = sigm(gi[node * 384 + 128 + je] + hz);
                            float nn = tanhf(gi[node * 384 + 256 + je] + r * hn);
                            float hv = A[node * 128 + je];
                            float o = fmaxf((1.f - z) * nn + z * hv, 0.f);
                            if (e == 0) res.x = o; else res.y = o;
                        }
                        *(float2*)&out[node * 128 + j] = res;
                    }
                }
            }
        }
        __syncthreads();
    }
}

// ---------------- nd gather (CSR, prefetched) ----------------
__global__ void __launch_bounds__(256) nd_gather_kernel(
    const float* __restrict__ p, const float* __restrict__ ea,
    const int* __restrict__ src, const int* __restrict__ off,
    const int* __restrict__ eid, const float* __restrict__ w1,
    float* __restrict__ tsum)
{
    __shared__ float W1b[16 * 128];
    const int tid = threadIdx.x;
    for (int idx = tid; idx < 16 * 128; idx += 256) {
        int k = idx >> 7, j = idx & 127;
        W1b[idx] = w1[j * 144 + 128 + k];
    }
    __syncthreads();
    int n = blockIdx.x * 8 + (tid >> 5);
    if (n >= NN) return;
    int lane = tid & 31;
    int beg = off[n], end = off[n + 1];
    float4 acc = make_float4(0.f, 0.f, 0.f, 0.f);
    const float4* W1b4 = (const float4*)W1b;
    const float4* p4 = (const float4*)p;
    if (beg < end) {
        int ed = eid[beg];
        int s = src[ed];
        for (int e = beg; e < end; ++e) {
            int s_cur = s, ed_cur = ed;
            if (e + 1 < end) {
                ed = eid[e + 1];
                s = src[ed];
            }
            float eav = (lane < 16) ? __ldg(&ea[(size_t)ed_cur * 16 + lane]) : 0.f;
            float4 t = p4[(size_t)s_cur * 32 + lane];
#pragma unroll
            for (int k = 0; k < 16; ++k) {
                float ek = __shfl_sync(0xFFFFFFFFu, eav, k);
                float4 w = W1b4[k * 32 + lane];
                t.x += ek * w.x; t.y += ek * w.y; t.z += ek * w.z; t.w += ek * w.w;
            }
            t.x = (t.x >= 0.f) ? t.x : 0.01f * t.x;
            t.y = (t.y >= 0.f) ? t.y : 0.01f * t.y;
            t.z = (t.z >= 0.f) ? t.z : 0.01f * t.z;
            t.w = (t.w >= 0.f) ? t.w : 0.01f * t.w;
            acc.x += t.x; acc.y += t.y; acc.z += t.z; acc.w += t.w;
        }
    }
    ((float4*)tsum)[(size_t)n * 32 + lane] = acc;
}

// ---------------- GAT attention dots ----------------
__global__ void attn_dots_kernel(const float* __restrict__ xp, const float* __restrict__ asrc,
                                 const float* __restrict__ adst, float* __restrict__ as_,
                                 float* __restrict__ ad_) {
    int n = (blockIdx.x * blockDim.x + threadIdx.x) >> 5;
    int lane = threadIdx.x & 31;
    if (n >= NN) return;
    float4 v = ((const float4*)xp)[(size_t)n * 32 + lane];
    float4 w1 = ((const float4*)asrc)[lane];
    float4 w2 = ((const float4*)adst)[lane];
    float sa = v.x * w1.x + v.y * w1.y + v.z * w1.z + v.w * w1.w;
    float sd = v.x * w2.x + v.y * w2.y + v.z * w2.z + v.w * w2.w;
#pragma unroll
    for (int o = 16; o; o >>= 1) {
        sa += __shfl_xor_sync(0xFFFFFFFFu, sa, o);
        sd += __shfl_xor_sync(0xFFFFFFFFu, sd, o);
    }
    if (lane == 0) { as_[n] = sa; ad_[n] = sd; }
}

// ---------------- GAT gather (CSR, online softmax, prefetched) -------------
__global__ void __launch_bounds__(256) gat_gather_kernel(
    const int* __restrict__ src, const int* __restrict__ off, const int* __restrict__ eid,
    const float* __restrict__ as_, const float* __restrict__ ad_,
    const float* __restrict__ xp, const float* __restrict__ bias,
    float* __restrict__ hout)
{
    int n = blockIdx.x * 8 + (threadIdx.x >> 5);
    if (n >= NN) return;
    int lane = threadIdx.x & 31;
    int beg = off[n], end = off[n + 1];
    float adn = ad_[n];
    float m = -INFINITY, den = 0.f;
    float4 acc = make_float4(0.f, 0.f, 0.f, 0.f);
    const float4* xp4 = (const float4*)xp;
    if (beg < end) {
        int s = src[eid[beg]];
        float av = __ldg(&as_[s]);
        for (int e = beg; e < end; ++e) {
            int s_cur = s; float a = av + adn;
            if (e + 1 < end) {
                s = src[eid[e + 1]];
                av = __ldg(&as_[s]);
            }
            float4 v = xp4[(size_t)s_cur * 32 + lane];
            a = (a >= 0.f) ? a : 0.01f * a;
            if (a > m) {
                float f = __expf(m - a);
                den *= f;
                acc.x *= f; acc.y *= f; acc.z *= f; acc.w *= f;
                m = a;
            }
            float w = __expf(a - m);
            den += w;
            acc.x += w * v.x; acc.y += w * v.y; acc.z += w * v.z; acc.w += w * v.w;
        }
    }
    float inv = (den > 0.f) ? 1.f / den : 0.f;
    float4 b = ((const float4*)bias)[lane];
    float4 r;
    r.x = acc.x * inv + b.x; r.y = acc.y * inv + b.y;
    r.z = acc.z * inv + b.z; r.w = acc.w * inv + b.w;
    r.x = (r.x > 0.f) ? r.x : expm1f(r.x);
    r.y = (r.y > 0.f) ? r.y : expm1f(r.y);
    r.z = (r.z > 0.f) ? r.z : expm1f(r.z);
    r.w = (r.w > 0.f) ? r.w : expm1f(r.w);
    ((float4*)hout)[(size_t)n * 32 + lane] = r;
}

// ---------------- readout ----------------
__global__ void __launch_bounds__(128) graph_agg_kernel(const float* __restrict__ xcur,
                                                        const int* __restrict__ batch,
                                                        float* __restrict__ agg,
                                                        float* __restrict__ outv) {
    int g = blockIdx.x;
    int lo, hi;
    {
        int l = 0, r = NN;
        while (l < r) { int m = (l + r) >> 1; if (batch[m] < g) l = m + 1; else r = m; }
        lo = l;
    }
    {
        int l = lo, r = NN;
        while (l < r) { int m = (l + r) >> 1; if (batch[m] < g + 1) l = m + 1; else r = m; }
        hi = l;
    }
    float s = 0.f;
    for (int n = lo; n < hi; ++n) s += xcur[(size_t)n * 128 + threadIdx.x];
    agg[g * 128 + threadIdx.x] = s;
    outv[g * 128 + threadIdx.x] = fmaxf(s, 0.f);
}

__global__ void add_kernel(const float* __restrict__ a, const float* __restrict__ b,
                           float* __restrict__ c, int n) {
    int t = blockIdx.x * blockDim.x + threadIdx.x;
    if (t < n) c[t] = a[t] + b[t];
}

__global__ void lstm_combine_kernel(const float* __restrict__ gi, const float* __restrict__ gh,
                                    const float* __restrict__ hc, float* __restrict__ out) {
    int t = blockIdx.x * blockDim.x + threadIdx.x;
    if (t >= NG * 128) return;
    int g = t >> 7, j = t & 127;
    size_t base = (size_t)g * 512;
    float gI = gi[base + j]       + gh[base + j];
    float gF = gi[base + 128 + j] + gh[base + 128 + j];
    float gG = gi[base + 256 + j] + gh[base + 256 + j];
    float gO = gi[base + 384 + j] + gh[base + 384 + j];
    float c = hc[t];
    float c2 = sigm(gF) * c + sigm(gI) * tanhf(gG);
    out[t] = sigm(gO) * tanhf(c2);
}

__global__ void final_kernel(const float* __restrict__ outv, const float* __restrict__ w,
                             const float* __restrict__ b, float* __restrict__ res) {
    int g = (blockIdx.x * blockDim.x + threadIdx.x) >> 5;
    int lane = threadIdx.x & 31;
    if (g >= NG) return;
    float4 v = ((const float4*)outv)[(size_t)g * 32 + lane];
    float4 ww = ((const float4*)w)[lane];
    float s = v.x * ww.x + v.y * ww.y + v.z * ww.z + v.w * ww.w;
#pragma unroll
    for (int o = 16; o; o >>= 1) s += __shfl_xor_sync(0xFFFFFFFFu, s, o);
    if (lane == 0) res[g] = s + b[0];
}

// ---------------- host ----------------
#define SM_J1K64  ((128 * 68 + 16 * 64) * 4)
#define SM_J1K128 ((128 * 132 + 16 * 128) * 4)
#define SM_M1     ((2 * 128 * 136 + 2 * 32 * 136) * 2)
#define SM_M3     ((2 * 384 * 136 + 2 * 32 * 136) * 2)

extern "C" void kernel_launch(void* const* d_in, const int* in_sizes, int n_in,
                              void* d_out, int out_size) {
    const float* x        = (const float*)d_in[0];
    const int*   ei       = (const int*)  d_in[1];
    const float* ea       = (const float*)d_in[2];
    const int*   batch    = (const int*)  d_in[3];
    const float* lin1_w   = (const float*)d_in[4];
    const float* lin1_b   = (const float*)d_in[5];
    const float* nd_lin1w = (const float*)d_in[6];
    const float* nd_lin2w = (const float*)d_in[7];
    const float* nd_bias  = (const float*)d_in[8];
    const float* gru0_wih = (const float*)d_in[9];
    const float* gru0_whh = (const float*)d_in[10];
    const float* gru0_bih = (const float*)d_in[11];
    const float* gru0_bhh = (const float*)d_in[12];
    const float* gat_w    = (const float*)d_in[13];
    const float* gat_asrc = (const float*)d_in[14];
    const float* gat_adst = (const float*)d_in[15];
    const float* gat_b    = (const float*)d_in[16];
    const float* gru_wih  = (const float*)d_in[17];
    const float* gru_whh  = (const float*)d_in[18];
    const float* gru_bih  = (const float*)d_in[19];
    const float* gru_bhh  = (const float*)d_in[20];
    const float* gin_w    = (const float*)d_in[21];
    const float* gin_b    = (const float*)d_in[22];
    const float* lstm_wih = (const float*)d_in[23];
    const float* lstm_whh = (const float*)d_in[24];
    const float* lstm_bih = (const float*)d_in[25];
    const float* lstm_bhh = (const float*)d_in[26];
    const float* lin2_w   = (const float*)d_in[27];
    const float* lin2_b   = (const float*)d_in[28];
    float* out = (float*)d_out;

    const int* src = ei;
    const int* dst = ei + NE;

    float *px1, *pp, *ph, *pxc, *pgi, *pas, *pad;
    float *pagg, *pgout, *pghh, *pgtmp, *pggi, *pggh;
    int *pcnt, *poff, *ppos, *peid, *ppart;
    cudaGetSymbolAddress((void**)&px1, f_x1);
    cudaGetSymbolAddress((void**)&pp, f_p);
    cudaGetSymbolAddress((void**)&ph, f_h);
    cudaGetSymbolAddress((void**)&pxc, f_xcur);
    cudaGetSymbolAddress((void**)&pgi, f_gi);
    cudaGetSymbolAddress((void**)&pas, f_as);
    cudaGetSymbolAddress((void**)&pad, f_ad);
    cudaGetSymbolAddress((void**)&pagg, g_agg);
    cudaGetSymbolAddress((void**)&pgout, g_out);
    cudaGetSymbolAddress((void**)&pghh, g_hh);
    cudaGetSymbolAddress((void**)&pgtmp, g_tmp);
    cudaGetSymbolAddress((void**)&pggi, g_gi);
    cudaGetSymbolAddress((void**)&pggh, g_gh);
    cudaGetSymbolAddress((void**)&pcnt, c_cnt);
    cudaGetSymbolAddress((void**)&poff, c_off);
    cudaGetSymbolAddress((void**)&ppos, c_pos);
    cudaGetSymbolAddress((void**)&peid, c_eid);
    cudaGetSymbolAddress((void**)&ppart, c_part);

    cudaFuncSetAttribute((const void*)dense_kernel<64, 1>, cudaFuncAttributeMaxDynamicSharedMemorySize, SM_J1K64);
    cudaFuncSetAttribute((const void*)dense_kernel<128, 0>, cudaFuncAttributeMaxDynamicSharedMemorySize, SM_J1K128);
    cudaFuncSetAttribute((const void*)dense_kernel<128, 3>, cudaFuncAttributeMaxDynamicSharedMemorySize, SM_J1K128);
    cudaFuncSetAttribute((const void*)dense1m_kernel<0>, cudaFuncAttributeMaxDynamicSharedMemorySize, SM_M1);
    cudaFuncSetAttribute((const void*)dense1m_kernel<3>, cudaFuncAttributeMaxDynamicSharedMemorySize, SM_M1);
    cudaFuncSetAttribute((const void*)dense3m_kernel<0>, cudaFuncAttributeMaxDynamicSharedMemorySize, SM_M3);
    cudaFuncSetAttribute((const void*)dense3m_kernel<1>, cudaFuncAttributeMaxDynamicSharedMemorySize, SM_M3);

    const int GP1b = 592;
    const int GPD1 = 296;   // dense1m: 2 CTAs/SM
    const int GP3 = 148;    // dense3m: 1 CTA/SM
    const int NPART = (NN + 1023) / 1024;
    const int tilesG = (NG + 15) / 16;
    const int ZB = 256;

    // 0) x1 = leaky(x @ lin1_w.T + b)
    dense_kernel<64, 1><<<dim3(GP1b, 1), 128, SM_J1K64>>>(x, lin1_w, lin1_b, px1, NN, 128, 64);
    // 1-2) CSR phase A
    zero_i_kernel<<<(NN + ZB - 1) / ZB, ZB>>>(pcnt, NN);
    hist_kernel<<<(NE + ZB - 1) / ZB, ZB>>>(dst, pcnt);
    // 3) p = x1 @ W1a.T   <-- PROFILED (tensor-core)
    dense1m_kernel<0><<<GPD1, 512, SM_M1>>>(px1, nd_lin1w, nullptr, pp, NN, 144);
    // 4-7) CSR phase B
    scan_part_kernel<<<NPART, 256>>>(pcnt, ppart);
    scan_mid_kernel<<<1, 32>>>(ppart, NPART);
    scan_final_kernel<<<NPART, 256>>>(pcnt, ppart, poff, ppos);
    fill_kernel<<<(NE + ZB - 1) / ZB, ZB>>>(dst, ppos, peid);
    // tsum
    nd_gather_kernel<<<(NN + 7) / 8, 256>>>(pp, ea, src, poff, peid, nd_lin1w, pgi);
    // h = elu(tsum @ W2.T + nd_bias)
    dense1m_kernel<3><<<GPD1, 512, SM_M1>>>(pgi, nd_lin2w, nd_bias, ph, NN, 128);
    // GRU0 (tensor-core split-bf16)
    dense3m_kernel<0><<<GP3, 512, SM_M3>>>(ph, gru0_wih, gru0_bih, pgi, nullptr, NN);
    dense3m_kernel<1><<<GP3, 512, SM_M3>>>(px1, gru0_whh, gru0_bhh, pxc, pgi, NN);

    // GAT layers
    for (int l = 0; l < 2; ++l) {
        dense1m_kernel<0><<<GPD1, 512, SM_M1>>>(pxc, gat_w + (size_t)l * 128 * 128, nullptr, pp, NN, 128);
        attn_dots_kernel<<<(NN * 32 + ZB - 1) / ZB, ZB>>>(pp, gat_asrc + l * 128, gat_adst + l * 128, pas, pad);
        gat_gather_kernel<<<(NN + 7) / 8, 256>>>(src, poff, peid, pas, pad, pp, gat_b + l * 128, ph);
        dense3m_kernel<0><<<GP3, 512, SM_M3>>>(ph, gru_wih + (size_t)l * 384 * 128, gru_bih + l * 384, pgi, nullptr, NN);
        dense3m_kernel<1><<<GP3, 512, SM_M3>>>(pxc, gru_whh + (size_t)l * 384 * 128, gru_bhh + l * 384, pxc, pgi, NN);
    }

    // readout
    graph_agg_kernel<<<NG, 128>>>(pxc, batch, pagg, pgout);
    for (int t = 0; t < 2; ++t) {
        add_kernel<<<(NG * 128 + ZB - 1) / ZB, ZB>>>(pgout, pagg, pgtmp, NG * 128);
        dense_kernel<128, 3><<<dim3(tilesG, 1), 128, SM_J1K128>>>(pgtmp, gin_w, gin_b, pghh, NG, 128, 128);
        dense_kernel<128, 0><<<dim3(tilesG, 4), 128, SM_J1K128>>>(pgout, lstm_wih, lstm_bih, pggi, NG, 512, 128);
        dense_kernel<128, 0><<<dim3(tilesG, 4), 128, SM_J1K128>>>(pghh, lstm_whh, lstm_bhh, pggh, NG, 512, 128);
        lstm_combine_kernel<<<(NG * 128 + ZB - 1) / ZB, ZB>>>(pggi, pggh, pghh, pgout);
    }
    final_kernel<<<(NG * 32 + 127) / 128, 128>>>(pgout, lin2_w, lin2_b, out);
}